// round 2
// baseline (speedup 1.0000x reference)
#include <cuda_runtime.h>
#include <cuda_bf16.h>

// ---------------- problem constants ----------------
#define NTOK   64          // tokens per window (8x8)
#define CDIM   256
#define HEADS  8
#define HD     32
#define PITCH  260         // smem row pitch (floats): 260*4=1040B, 16B aligned, stride%32=4 banks
#define NWIN   2048        // 8 images * 16 * 16 windows
#define CHW    4194304     // 256*128*128
#define SCALE  0.17677669529663687f   // 32^-0.5

// ---------------- precomputed device globals ----------------
__device__ float g_qT[32 * 512];           // [e][h*64+n]  (already * SCALE)
__device__ float g_biasT[HEADS * 64 * 64]; // [h][m][n]
__device__ float g_kvwT[256 * 512];        // [c][d]   (kv_w transposed)
__device__ float g_pwT[256 * 256];         // [c][d]   (proj_w transposed)

// ---------------- packed f32x2 helpers (Blackwell FFMA2) ----------------
__device__ __forceinline__ unsigned long long pk2(float x) {
    unsigned long long r;
    asm("mov.b64 %0, {%1, %1};" : "=l"(r) : "r"(__float_as_uint(x)));
    return r;
}
__device__ __forceinline__ float2 up2(unsigned long long v) {
    float2 f;
    asm("mov.b64 {%0, %1}, %2;" : "=f"(f.x), "=f"(f.y) : "l"(v));
    return f;
}
#define FMA2(d, a, b, c) \
    asm("fma.rn.f32x2 %0, %1, %2, %3;" : "=l"(d) : "l"(a), "l"(b), "l"(c))

// ---------------- setup kernel: tiny, runs once per launch ----------------
__global__ void setup_kernel(const float* __restrict__ emb,
                             const float* __restrict__ rpb,
                             const float* __restrict__ q_w,
                             const float* __restrict__ q_b,
                             const float* __restrict__ kv_w,
                             const float* __restrict__ proj_w) {
    int gid = blockIdx.x * blockDim.x + threadIdx.x;
    if (gid < 16384) {
        // q^T[e][h*64+n] = SCALE * (emb[n] . q_w[h*32+e] + q_b)
        int e  = gid >> 9;
        int hn = gid & 511;
        int h  = hn >> 6, n = hn & 63;
        int d  = h * 32 + e;
        const float* er = emb + n * 256;
        const float* wr = q_w + d * 256;
        float acc = q_b[d];
        #pragma unroll 4
        for (int c = 0; c < 256; c++) acc = fmaf(er[c], wr[c], acc);
        g_qT[gid] = acc * SCALE;
    } else if (gid < 16384 + 32768) {
        // bias^T[h][m][n] = rpb[relidx(n,m)*8 + h]
        int t = gid - 16384;
        int h = t >> 12;
        int m = (t >> 6) & 63;
        int n = t & 63;
        int r0 = (n >> 3) - (m >> 3) + 7;
        int r1 = (n & 7) - (m & 7) + 7;
        g_biasT[t] = rpb[(r0 * 15 + r1) * HEADS + h];
    } else if (gid < 16384 + 32768 + 131072) {
        int t = gid - 49152;              // c*512 + d
        int c = t >> 9, d = t & 511;
        g_kvwT[t] = kv_w[d * 256 + c];
    } else {                               // gid < 245760
        int t = gid - 180224;             // c*256 + d
        int c = t >> 8, d = t & 255;
        g_pwT[t] = proj_w[d * 256 + c];
    }
}

// ---------------- register-blocked fp32x2 GEMM pass ----------------
// C[64 x 256] = A[64 x 256](smem, PITCH) * B^T-slice(global, c-major) + bias
// 512 threads: ty=tid>>5 -> rows n0=4*ty ; tx=tid&31 -> cols {tx*4..+3, 128+tx*4..+3}
__device__ __forceinline__ void gemm_pass(
    const float* __restrict__ A,        // smem, pitch PITCH
    const float* __restrict__ Bt,       // global [c][ldB]
    int ldB, int dbase,
    const float* __restrict__ bias,     // global, 256 floats (already offset)
    float* dst, int dstPitch,           // smem (PITCH) or global (256)
    float* s_b, int tid) {

    const int ty = tid >> 5;
    const int tx = tid & 31;
    const int n0 = ty << 2;

    unsigned long long acc[4][4];
    #pragma unroll
    for (int i = 0; i < 4; i++)
        #pragma unroll
        for (int j = 0; j < 4; j++) acc[i][j] = 0ULL;   // bits(0,0) == (0.f,0.f)

    for (int kb = 0; kb < 16; kb++) {
        // stage B tile [16][256] (coalesced: rows of transposed weights)
        #pragma unroll
        for (int t = 0; t < 2; t++) {
            int li = tid + t * 512;            // float4 index over 1024
            int r  = li >> 6, c4 = li & 63;
            *(float4*)(s_b + r * 256 + c4 * 4) =
                *(const float4*)(Bt + (size_t)(kb * 16 + r) * ldB + dbase + c4 * 4);
        }
        __syncthreads();

        #pragma unroll
        for (int kk = 0; kk < 16; kk++) {
            int k = kb * 16 + kk;
            unsigned long long a0 = pk2(A[(n0 + 0) * PITCH + k]);   // broadcast LDS
            unsigned long long a1 = pk2(A[(n0 + 1) * PITCH + k]);
            unsigned long long a2 = pk2(A[(n0 + 2) * PITCH + k]);
            unsigned long long a3 = pk2(A[(n0 + 3) * PITCH + k]);
            const unsigned long long* b0 =
                (const unsigned long long*)(s_b + kk * 256 + tx * 4);
            const unsigned long long* b1 =
                (const unsigned long long*)(s_b + kk * 256 + 128 + tx * 4);
            unsigned long long bv0 = b0[0], bv1 = b0[1], bv2 = b1[0], bv3 = b1[1];
            FMA2(acc[0][0], a0, bv0, acc[0][0]);
            FMA2(acc[0][1], a0, bv1, acc[0][1]);
            FMA2(acc[0][2], a0, bv2, acc[0][2]);
            FMA2(acc[0][3], a0, bv3, acc[0][3]);
            FMA2(acc[1][0], a1, bv0, acc[1][0]);
            FMA2(acc[1][1], a1, bv1, acc[1][1]);
            FMA2(acc[1][2], a1, bv2, acc[1][2]);
            FMA2(acc[1][3], a1, bv3, acc[1][3]);
            FMA2(acc[2][0], a2, bv0, acc[2][0]);
            FMA2(acc[2][1], a2, bv1, acc[2][1]);
            FMA2(acc[2][2], a2, bv2, acc[2][2]);
            FMA2(acc[2][3], a2, bv3, acc[2][3]);
            FMA2(acc[3][0], a3, bv0, acc[3][0]);
            FMA2(acc[3][1], a3, bv1, acc[3][1]);
            FMA2(acc[3][2], a3, bv2, acc[3][2]);
            FMA2(acc[3][3], a3, bv3, acc[3][3]);
        }
        __syncthreads();
    }

    // epilogue: add bias, store two float4 per row
    float4 bA = *(const float4*)(bias + tx * 4);
    float4 bB = *(const float4*)(bias + 128 + tx * 4);
    #pragma unroll
    for (int i = 0; i < 4; i++) {
        float2 p0 = up2(acc[i][0]), p1 = up2(acc[i][1]);
        float2 p2 = up2(acc[i][2]), p3 = up2(acc[i][3]);
        float* drow = dst + (size_t)(n0 + i) * dstPitch;
        *(float4*)(drow + tx * 4) =
            make_float4(p0.x + bA.x, p0.y + bA.y, p1.x + bA.z, p1.y + bA.w);
        *(float4*)(drow + 128 + tx * 4) =
            make_float4(p2.x + bB.x, p2.y + bB.y, p3.x + bB.z, p3.y + bB.w);
    }
}

// ---------------- main fused kernel: one CTA per window ----------------
extern __shared__ float smem[];

__global__ void __launch_bounds__(512, 1)
win_attn_kernel(const float* __restrict__ x,
                const float* __restrict__ kv_b,
                const float* __restrict__ proj_b,
                float* __restrict__ out) {
    float* s_x = smem;               // 64*260 = 16640 f (also q^T stage, also s_o)
    float* s_k = smem + 16640;       // 16640 f
    float* s_v = smem + 33280;       // 16640 f
    float* s_b = smem + 49920;       // 16*256 = 4096 f
    const int tid = threadIdx.x;
    const int bw  = blockIdx.x;
    const int b   = bw >> 8;
    const int i   = (bw >> 4) & 15;
    const int j   = bw & 15;
    const float* xbase = x + (size_t)b * CHW + i * 262144 + j * 2048;

    // ---- phase A: load window [64 tok][256 ch] into smem ----
    #pragma unroll
    for (int t = 0; t < 8; t++) {
        int li = tid + t * 512;          // float4 index over 4096
        int n  = li >> 6, c4 = li & 63;
        int wi = n >> 3, wj = n & 7;
        float4 v = *(const float4*)(xbase + wi * 32768 + wj * 256 + c4 * 4);
        *(float4*)(s_x + n * PITCH + c4 * 4) = v;
    }
    __syncthreads();

    // ---- phase B: kv GEMM -> s_k, s_v ----
    gemm_pass(s_x, g_kvwT, 512, 0,   kv_b,       s_k, PITCH, s_b, tid);
    gemm_pass(s_x, g_kvwT, 512, 256, kv_b + 256, s_v, PITCH, s_b, tid);

    // ---- stage q^T over s_x (window data no longer needed) ----
    #pragma unroll
    for (int t = 0; t < 8; t++) {
        int li = tid + t * 512;          // float4 index over 4096 (16384 floats)
        *(float4*)(s_x + li * 4) = *(const float4*)(g_qT + li * 4);
    }
    __syncthreads();

    // ---- phase C: attention, one (head, token) row per thread ----
    const int h = tid >> 6;
    const int n = tid & 63;
    float s[64];
    #pragma unroll
    for (int m = 0; m < 64; m++) s[m] = 0.f;

    const float* kcol = s_k + h * 32;
    #pragma unroll 1
    for (int e = 0; e < 32; e++) {
        float qe = s_x[e * 512 + tid];           // q^T[e][h*64+n], conflict-free
        const float* kp = kcol + e;
        #pragma unroll
        for (int m = 0; m < 64; m++)
            s[m] = fmaf(qe, kp[m * PITCH], s[m]); // broadcast LDS
    }

    const float* bp = g_biasT + h * 4096 + n;    // [h][m][n], coalesced over n
    float mx = -1e30f;
    #pragma unroll
    for (int m = 0; m < 64; m++) { s[m] += bp[m * 64]; mx = fmaxf(mx, s[m]); }
    float sum = 0.f;
    #pragma unroll
    for (int m = 0; m < 64; m++) { s[m] = __expf(s[m] - mx); sum += s[m]; }
    float inv = 1.f / sum;
    #pragma unroll
    for (int m = 0; m < 64; m++) s[m] *= inv;

    __syncthreads();   // all q^T reads done -> s_x region becomes s_o

    #pragma unroll 1
    for (int eb = 0; eb < 2; eb++) {
        float o[16];
        #pragma unroll
        for (int e2 = 0; e2 < 16; e2++) o[e2] = 0.f;
        const float* vbase = s_v + h * 32 + eb * 16;
        #pragma unroll
        for (int m = 0; m < 64; m++) {
            float pv = s[m];
            const float* vp = vbase + m * PITCH;
            #pragma unroll
            for (int e2 = 0; e2 < 16; e2++)
                o[e2] = fmaf(pv, vp[e2], o[e2]);  // broadcast LDS
        }
        #pragma unroll
        for (int e2 = 0; e2 < 16; e2 += 4)
            *(float4*)(s_x + n * PITCH + h * 32 + eb * 16 + e2) =
                make_float4(o[e2], o[e2 + 1], o[e2 + 2], o[e2 + 3]);
    }
    __syncthreads();

    // ---- phase D: proj GEMM -> global out ----
    gemm_pass(s_x, g_pwT, 256, 0, proj_b,
              out + (size_t)bw * (NTOK * CDIM), 256, s_b, tid);
}

// ---------------- launcher ----------------
extern "C" void kernel_launch(void* const* d_in, const int* in_sizes, int n_in,
                              void* d_out, int out_size) {
    const float* x      = (const float*)d_in[0];
    const float* emb    = (const float*)d_in[1];
    const float* rpb    = (const float*)d_in[2];
    const float* q_w    = (const float*)d_in[3];
    const float* q_b    = (const float*)d_in[4];
    const float* kv_w   = (const float*)d_in[5];
    const float* kv_b   = (const float*)d_in[6];
    const float* proj_w = (const float*)d_in[7];
    const float* proj_b = (const float*)d_in[8];
    float* out = (float*)d_out;

    (void)in_sizes; (void)n_in; (void)out_size;

    cudaFuncSetAttribute(win_attn_kernel,
                         cudaFuncAttributeMaxDynamicSharedMemorySize, 216064);

    setup_kernel<<<480, 512>>>(emb, rpb, q_w, q_b, kv_w, proj_w);
    win_attn_kernel<<<NWIN, 512, 216064>>>(x, kv_b, proj_b, out);
}

// round 3
// speedup vs baseline: 1.6084x; 1.6084x over previous
#include <cuda_runtime.h>
#include <cuda_bf16.h>

// ---------------- problem constants ----------------
#define NTOK   64          // tokens per window (8x8)
#define CDIM   256
#define HEADS  8
#define HD     32
#define PITCH  260         // smem row pitch (floats): 260*4=1040B, 16B aligned, stride%32=4 banks
#define NWIN   2048        // 8 images * 16 * 16 windows
#define CHW    4194304     // 256*128*128
#define SCALE  0.17677669529663687f   // 32^-0.5

// ---------------- precomputed device globals ----------------
__device__ float g_qT[32 * 512];           // [e][h*64+n]  (already * SCALE)
__device__ float g_biasT[HEADS * 64 * 64]; // [h][m][n]
__device__ float g_kvwT[256 * 512];        // [c][d]   (kv_w transposed)
__device__ float g_pwT[256 * 256];         // [c][d]   (proj_w transposed)

// ---------------- packed f32x2 helpers (Blackwell FFMA2) ----------------
__device__ __forceinline__ unsigned long long pk2(float x) {
    unsigned long long r;
    asm("mov.b64 %0, {%1, %1};" : "=l"(r) : "r"(__float_as_uint(x)));
    return r;
}
__device__ __forceinline__ float2 up2(unsigned long long v) {
    float2 f;
    asm("mov.b64 {%0, %1}, %2;" : "=f"(f.x), "=f"(f.y) : "l"(v));
    return f;
}
#define FMA2(d, a, b, c) \
    asm("fma.rn.f32x2 %0, %1, %2, %3;" : "=l"(d) : "l"(a), "l"(b), "l"(c))

// ---------------- setup kernel: tiny, runs once per launch ----------------
__global__ void setup_kernel(const float* __restrict__ emb,
                             const float* __restrict__ rpb,
                             const float* __restrict__ q_w,
                             const float* __restrict__ q_b,
                             const float* __restrict__ kv_w,
                             const float* __restrict__ proj_w) {
    int gid = blockIdx.x * blockDim.x + threadIdx.x;
    if (gid < 16384) {
        // q^T[e][h*64+n] = SCALE * (emb[n] . q_w[h*32+e] + q_b)
        int e  = gid >> 9;
        int hn = gid & 511;
        int h  = hn >> 6, n = hn & 63;
        int d  = h * 32 + e;
        const float* er = emb + n * 256;
        const float* wr = q_w + d * 256;
        float acc = q_b[d];
        #pragma unroll 4
        for (int c = 0; c < 256; c++) acc = fmaf(er[c], wr[c], acc);
        g_qT[gid] = acc * SCALE;
    } else if (gid < 16384 + 32768) {
        // bias^T[h][m][n] = rpb[relidx(n,m)*8 + h]
        int t = gid - 16384;
        int h = t >> 12;
        int m = (t >> 6) & 63;
        int n = t & 63;
        int r0 = (n >> 3) - (m >> 3) + 7;
        int r1 = (n & 7) - (m & 7) + 7;
        g_biasT[t] = rpb[(r0 * 15 + r1) * HEADS + h];
    } else if (gid < 16384 + 32768 + 131072) {
        int t = gid - 49152;              // c*512 + d
        int c = t >> 9, d = t & 511;
        g_kvwT[t] = kv_w[d * 256 + c];
    } else {                               // gid < 245760
        int t = gid - 180224;             // c*256 + d
        int c = t >> 8, d = t & 255;
        g_pwT[t] = proj_w[d * 256 + c];
    }
}

// ---------------- register-blocked fp32x2 GEMM pass ----------------
// C[64 x 256] = A[64 x 256](smem, PITCH) * B^T-slice(global, c-major) + bias
// 512 threads: ty=tid>>5 -> rows n0=4*ty ; tx=tid&31 -> cols {tx*4..+3, 128+tx*4..+3}
__device__ __forceinline__ void gemm_pass(
    const float* __restrict__ A,        // smem, pitch PITCH
    const float* __restrict__ Bt,       // global [c][ldB]
    int ldB, int dbase,
    const float* __restrict__ bias,     // global, 256 floats (already offset)
    float* dst, int dstPitch,           // smem (PITCH) or global (256)
    float* s_b, int tid) {

    const int ty = tid >> 5;
    const int tx = tid & 31;
    const int n0 = ty << 2;

    unsigned long long acc[4][4];
    #pragma unroll
    for (int i = 0; i < 4; i++)
        #pragma unroll
        for (int j = 0; j < 4; j++) acc[i][j] = 0ULL;   // bits(0,0) == (0.f,0.f)

    for (int kb = 0; kb < 16; kb++) {
        // stage B tile [16][256] (coalesced: rows of transposed weights)
        #pragma unroll
        for (int t = 0; t < 2; t++) {
            int li = tid + t * 512;            // float4 index over 1024
            int r  = li >> 6, c4 = li & 63;
            *(float4*)(s_b + r * 256 + c4 * 4) =
                *(const float4*)(Bt + (size_t)(kb * 16 + r) * ldB + dbase + c4 * 4);
        }
        __syncthreads();

        #pragma unroll
        for (int kk = 0; kk < 16; kk++) {
            int k = kb * 16 + kk;
            unsigned long long a0 = pk2(A[(n0 + 0) * PITCH + k]);   // broadcast LDS
            unsigned long long a1 = pk2(A[(n0 + 1) * PITCH + k]);
            unsigned long long a2 = pk2(A[(n0 + 2) * PITCH + k]);
            unsigned long long a3 = pk2(A[(n0 + 3) * PITCH + k]);
            const unsigned long long* b0 =
                (const unsigned long long*)(s_b + kk * 256 + tx * 4);
            const unsigned long long* b1 =
                (const unsigned long long*)(s_b + kk * 256 + 128 + tx * 4);
            unsigned long long bv0 = b0[0], bv1 = b0[1], bv2 = b1[0], bv3 = b1[1];
            FMA2(acc[0][0], a0, bv0, acc[0][0]);
            FMA2(acc[0][1], a0, bv1, acc[0][1]);
            FMA2(acc[0][2], a0, bv2, acc[0][2]);
            FMA2(acc[0][3], a0, bv3, acc[0][3]);
            FMA2(acc[1][0], a1, bv0, acc[1][0]);
            FMA2(acc[1][1], a1, bv1, acc[1][1]);
            FMA2(acc[1][2], a1, bv2, acc[1][2]);
            FMA2(acc[1][3], a1, bv3, acc[1][3]);
            FMA2(acc[2][0], a2, bv0, acc[2][0]);
            FMA2(acc[2][1], a2, bv1, acc[2][1]);
            FMA2(acc[2][2], a2, bv2, acc[2][2]);
            FMA2(acc[2][3], a2, bv3, acc[2][3]);
            FMA2(acc[3][0], a3, bv0, acc[3][0]);
            FMA2(acc[3][1], a3, bv1, acc[3][1]);
            FMA2(acc[3][2], a3, bv2, acc[3][2]);
            FMA2(acc[3][3], a3, bv3, acc[3][3]);
        }
        __syncthreads();
    }

    // epilogue: add bias, store two float4 per row
    float4 bA = *(const float4*)(bias + tx * 4);
    float4 bB = *(const float4*)(bias + 128 + tx * 4);
    #pragma unroll
    for (int i = 0; i < 4; i++) {
        float2 p0 = up2(acc[i][0]), p1 = up2(acc[i][1]);
        float2 p2 = up2(acc[i][2]), p3 = up2(acc[i][3]);
        float* drow = dst + (size_t)(n0 + i) * dstPitch;
        *(float4*)(drow + tx * 4) =
            make_float4(p0.x + bA.x, p0.y + bA.y, p1.x + bA.z, p1.y + bA.w);
        *(float4*)(drow + 128 + tx * 4) =
            make_float4(p2.x + bB.x, p2.y + bB.y, p3.x + bB.z, p3.y + bB.w);
    }
}

// ---------------- main fused kernel: one CTA per window ----------------
extern __shared__ float smem[];

__global__ void __launch_bounds__(512, 1)
win_attn_kernel(const float* __restrict__ x,
                const float* __restrict__ kv_b,
                const float* __restrict__ proj_b,
                float* __restrict__ out) {
    float* s_x = smem;               // 64*260 = 16640 f (also q^T stage, also s_o)
    float* s_k = smem + 16640;       // 16640 f
    float* s_v = smem + 33280;       // 16640 f
    float* s_b = smem + 49920;       // 16*256 = 4096 f
    const int tid = threadIdx.x;
    const int bw  = blockIdx.x;
    const int b   = bw >> 8;
    const int i   = (bw >> 4) & 15;
    const int j   = bw & 15;
    const float* xbase = x + (size_t)b * CHW + i * 262144 + j * 2048;

    // ---- phase A: load window [64 tok][256 ch] into smem ----
    #pragma unroll
    for (int t = 0; t < 8; t++) {
        int li = tid + t * 512;          // float4 index over 4096
        int n  = li >> 6, c4 = li & 63;
        int wi = n >> 3, wj = n & 7;
        float4 v = *(const float4*)(xbase + wi * 32768 + wj * 256 + c4 * 4);
        *(float4*)(s_x + n * PITCH + c4 * 4) = v;
    }
    __syncthreads();

    // ---- phase B: kv GEMM -> s_k, s_v ----
    gemm_pass(s_x, g_kvwT, 512, 0,   kv_b,       s_k, PITCH, s_b, tid);
    gemm_pass(s_x, g_kvwT, 512, 256, kv_b + 256, s_v, PITCH, s_b, tid);

    // ---- stage q^T over s_x (window data no longer needed) ----
    #pragma unroll
    for (int t = 0; t < 8; t++) {
        int li = tid + t * 512;          // float4 index over 4096 (16384 floats)
        *(float4*)(s_x + li * 4) = *(const float4*)(g_qT + li * 4);
    }
    __syncthreads();

    // ---- phase C: attention, one (head, token) row per thread ----
    const int h = tid >> 6;
    const int n = tid & 63;
    float s[64];
    #pragma unroll
    for (int m = 0; m < 64; m++) s[m] = 0.f;

    const float* kcol = s_k + h * 32;
    #pragma unroll 1
    for (int e = 0; e < 32; e++) {
        float qe = s_x[e * 512 + tid];           // q^T[e][h*64+n], conflict-free
        const float* kp = kcol + e;
        #pragma unroll
        for (int m = 0; m < 64; m++)
            s[m] = fmaf(qe, kp[m * PITCH], s[m]); // broadcast LDS
    }

    const float* bp = g_biasT + h * 4096 + n;    // [h][m][n], coalesced over n
    float mx = -1e30f;
    #pragma unroll
    for (int m = 0; m < 64; m++) { s[m] += bp[m * 64]; mx = fmaxf(mx, s[m]); }
    float sum = 0.f;
    #pragma unroll
    for (int m = 0; m < 64; m++) { s[m] = __expf(s[m] - mx); sum += s[m]; }
    float inv = 1.f / sum;
    #pragma unroll
    for (int m = 0; m < 64; m++) s[m] *= inv;

    __syncthreads();   // all q^T reads done -> s_x region becomes s_o

    #pragma unroll 1
    for (int eb = 0; eb < 2; eb++) {
        float o[16];
        #pragma unroll
        for (int e2 = 0; e2 < 16; e2++) o[e2] = 0.f;
        const float* vbase = s_v + h * 32 + eb * 16;
        #pragma unroll
        for (int m = 0; m < 64; m++) {
            float pv = s[m];
            const float* vp = vbase + m * PITCH;
            #pragma unroll
            for (int e2 = 0; e2 < 16; e2++)
                o[e2] = fmaf(pv, vp[e2], o[e2]);  // broadcast LDS
        }
        #pragma unroll
        for (int e2 = 0; e2 < 16; e2 += 4)
            *(float4*)(s_x + n * PITCH + h * 32 + eb * 16 + e2) =
                make_float4(o[e2], o[e2 + 1], o[e2 + 2], o[e2 + 3]);
    }
    __syncthreads();

    // ---- phase D: proj GEMM -> global out ----
    gemm_pass(s_x, g_pwT, 256, 0, proj_b,
              out + (size_t)bw * (NTOK * CDIM), 256, s_b, tid);
}

// ---------------- launcher ----------------
extern "C" void kernel_launch(void* const* d_in, const int* in_sizes, int n_in,
                              void* d_out, int out_size) {
    const float* x      = (const float*)d_in[0];
    const float* emb    = (const float*)d_in[1];
    const float* rpb    = (const float*)d_in[2];
    const float* q_w    = (const float*)d_in[3];
    const float* q_b    = (const float*)d_in[4];
    const float* kv_w   = (const float*)d_in[5];
    const float* kv_b   = (const float*)d_in[6];
    const float* proj_w = (const float*)d_in[7];
    const float* proj_b = (const float*)d_in[8];
    float* out = (float*)d_out;

    (void)in_sizes; (void)n_in; (void)out_size;

    cudaFuncSetAttribute(win_attn_kernel,
                         cudaFuncAttributeMaxDynamicSharedMemorySize, 216064);

    setup_kernel<<<480, 512>>>(emb, rpb, q_w, q_b, kv_w, proj_w);
    win_attn_kernel<<<NWIN, 512, 216064>>>(x, kv_b, proj_b, out);
}

// round 5
// speedup vs baseline: 1.6393x; 1.0192x over previous
#include <cuda_runtime.h>
#include <cuda_bf16.h>
#include <cstdint>

typedef unsigned long long ull;

#define SCALE 0.17677669529663687f   // 32^-0.5

// ---------------- device scratch ----------------
__device__ __align__(128) float g_KV[131072ULL * 512];   // [gtok][512] (k:0..255, v:256..511)
__device__ __align__(128) float g_O [131072ULL * 256];   // [gtok][256]
__device__ __align__(128) float g_q   [8 * 64 * 32];     // [(h*64+n)*32+e], already * SCALE
__device__ __align__(128) float g_biasT[8 * 64 * 64];    // [h][m][n]
__device__ __align__(128) __nv_bfloat16 g_kvw_blk[262144]; // 8 chunks x 64KB blocked SW128 (hi|lo)
__device__ __align__(128) __nv_bfloat16 g_pw_blk [131072]; // 4 chunks x 64KB

// ---------------- helpers ----------------
__device__ __forceinline__ uint32_t smem_u32(const void* p) {
    uint32_t a;
    asm("{ .reg .u64 t; cvta.to.shared.u64 t, %1; cvt.u32.u64 %0, t; }" : "=r"(a) : "l"(p));
    return a;
}
__device__ __forceinline__ ull pk2(float x) {
    ull r; asm("mov.b64 %0, {%1, %1};" : "=l"(r) : "r"(__float_as_uint(x))); return r;
}
__device__ __forceinline__ float2 up2(ull v) {
    float2 f; asm("mov.b64 {%0, %1}, %2;" : "=f"(f.x), "=f"(f.y) : "l"(v)); return f;
}
#define FMA2(d, a, b, c) \
    asm("fma.rn.f32x2 %0, %1, %2, %3;" : "=l"(d) : "l"(a), "l"(b), "l"(c))

// blocked SW128 layouts: atom = 8 rows x 64 bf16 (1024B); atoms: (rows/8) per k-col-block
__device__ __forceinline__ uint32_t a_sw_off(int m, int kk) {   // A: 128 rows
    uint32_t off = ((uint32_t)(kk >> 6) * 16 + (m >> 3)) * 1024 + (m & 7) * 128 + (kk & 63) * 2;
    return off ^ ((off >> 3) & 0x70);
}
__device__ __forceinline__ uint32_t b_sw_off(int nn, int kk) {  // B: 64 rows
    uint32_t off = ((uint32_t)(kk >> 6) * 8 + (nn >> 3)) * 1024 + (nn & 7) * 128 + (kk & 63) * 2;
    return off ^ ((off >> 3) & 0x70);
}

__device__ __forceinline__ void ldsm_x4(uint32_t* r, uint32_t addr) {
    asm volatile("ldmatrix.sync.aligned.m8n8.x4.shared.b16 {%0,%1,%2,%3}, [%4];"
        : "=r"(r[0]), "=r"(r[1]), "=r"(r[2]), "=r"(r[3]) : "r"(addr));
}
__device__ __forceinline__ void mma16816(float* c, const uint32_t* a, const uint32_t* b) {
    asm volatile(
        "mma.sync.aligned.m16n8k16.row.col.f32.bf16.bf16.f32 "
        "{%0,%1,%2,%3}, {%4,%5,%6,%7}, {%8,%9}, {%0,%1,%2,%3};"
        : "+f"(c[0]), "+f"(c[1]), "+f"(c[2]), "+f"(c[3])
        : "r"(a[0]), "r"(a[1]), "r"(a[2]), "r"(a[3]), "r"(b[0]), "r"(b[1]));
}

// ---------------- setup: q, bias, weight conversion (runs once per launch) ----------------
__global__ void setup_kernel(const float* __restrict__ emb,
                             const float* __restrict__ rpb,
                             const float* __restrict__ q_w,
                             const float* __restrict__ q_b,
                             const float* __restrict__ kv_w,
                             const float* __restrict__ proj_w) {
    int gid = blockIdx.x * blockDim.x + threadIdx.x;
    if (gid < 16384) {
        // g_q[(h*64+n)*32+e] = SCALE * (emb[n] . q_w[h*32+e] + q_b)
        int e = gid & 31; int hn = gid >> 5;
        int h = hn >> 6, n = hn & 63;
        int d = h * 32 + e;
        const float* er = emb + n * 256;
        const float* wr = q_w + d * 256;
        float acc = q_b[d];
        #pragma unroll 4
        for (int c = 0; c < 256; c++) acc = fmaf(er[c], wr[c], acc);
        g_q[gid] = acc * SCALE;
    } else if (gid < 49152) {
        int t = gid - 16384;
        int h = t >> 12, m = (t >> 6) & 63, n = t & 63;
        int r0 = (n >> 3) - (m >> 3) + 7;
        int r1 = (n & 7) - (m & 7) + 7;
        g_biasT[t] = rpb[(r0 * 15 + r1) * 8 + h];
    } else if (gid < 311296) {
        // kv_w [512][256] -> hi|lo bf16 blocked swizzled, chunk = d>>6
        int t = gid - 49152;             // n*512 + kk
        int n = t >> 9, kk = t & 511;
        float w = kv_w[n * 256 + (kk & 255)];
        __nv_bfloat16 hb = __float2bfloat16(w);
        __nv_bfloat16 val = (kk < 256) ? hb : __float2bfloat16(w - __bfloat162float(hb));
        g_kvw_blk[(((uint32_t)(n >> 6)) * 65536 + b_sw_off(n & 63, kk)) >> 1] = val;
    } else {
        int t = gid - 311296;            // n*512 + kk, n < 256
        int n = t >> 9, kk = t & 511;
        float w = proj_w[n * 256 + (kk & 255)];
        __nv_bfloat16 hb = __float2bfloat16(w);
        __nv_bfloat16 val = (kk < 256) ? hb : __float2bfloat16(w - __bfloat162float(hb));
        g_pw_blk[(((uint32_t)(n >> 6)) * 65536 + b_sw_off(n & 63, kk)) >> 1] = val;
    }
}

// ---------------- mma.sync split-bf16 GEMM: C[128 x NC*64] = A[128x256] @ W^T + bias --------
// A in smem as bf16 hi (k 0..255) | lo (k 256..511), blocked SW128 (128KB).
// B streamed per 64-col chunk from precomputed blocked global (64KB), register-prefetched.
template<int NC, bool GATHER>
__global__ void __launch_bounds__(512, 1)
gemm_kernel(const float* __restrict__ xsrc,
            const float* __restrict__ bias,
            float* __restrict__ coutp) {
    extern __shared__ char gsm[];
    const uint32_t sraw = smem_u32(gsm);
    const uint32_t sA = (sraw + 1023) & ~1023u;
    const uint32_t sB = sA + 131072;
    char* Ab = gsm + (sA - sraw);
    char* Bb = gsm + (sB - sraw);

    const int tid = threadIdx.x;
    const int wid = tid >> 5;
    const int lid = tid & 31;
    const int r0  = blockIdx.x * 128;

    const __nv_bfloat16* wblk = GATHER ? g_kvw_blk : g_pw_blk;
    float* C = GATHER ? g_KV : coutp;
    const int ldc = NC * 64;

    // prefetch B chunk 0 into registers (overlaps with A build)
    uint4 pre[8];
    {
        const uint4* srcb = (const uint4*)wblk;
        #pragma unroll
        for (int t = 0; t < 8; t++) pre[t] = srcb[tid + t * 512];
    }

    // ---- build A tile: fp32 -> bf16 hi (k 0..255) | lo (k 256..511), blocked SW128 ----
    #pragma unroll 4
    for (int it = 0; it < 32; it++) {
        int idx = tid + it * 512;            // 0..16383 (float2 units)
        int m = idx >> 7, p = idx & 127, c = p * 2;
        const float* rowp;
        if constexpr (GATHER) {
            int r = r0 + m;                  // r = bw*64 + n
            int b = r >> 14, i = (r >> 10) & 15, j = (r >> 6) & 15, n = r & 63;
            rowp = xsrc + ((size_t)b << 22) + ((size_t)i << 18)
                 + ((size_t)(n >> 3) << 15) + ((size_t)j << 11) + ((size_t)(n & 7) << 8);
        } else {
            rowp = g_O + (size_t)(r0 + m) * 256;
        }
        float2 f = *(const float2*)(rowp + c);
        __nv_bfloat162 h2 = __floats2bfloat162_rn(f.x, f.y);
        float lx = f.x - __bfloat162float(h2.x);
        float ly = f.y - __bfloat162float(h2.y);
        __nv_bfloat162 l2 = __floats2bfloat162_rn(lx, ly);
        *(uint32_t*)(Ab + a_sw_off(m, c))       = *(uint32_t*)&h2;
        *(uint32_t*)(Ab + a_sw_off(m, c + 256)) = *(uint32_t*)&l2;
    }

    // ---- per-warp / per-lane geometry for ldmatrix ----
    const int m0w = (wid >> 2) * 32;         // warp tile 32 rows x 16 cols; grid 4x4
    const int n0w = (wid & 3) * 16;
    const int lrow = lid & 7;
    const int quad = lid >> 3;
    // A x4 matrices order: (m0,k0),(m0+8,k0),(m0,k0+8),(m0+8,k0+8)
    const int mA0 = m0w + lrow + (quad & 1) * 8;
    const int mA1 = mA0 + 16;
    const uint32_t aoff0 = ((uint32_t)(mA0 >> 3) << 10) + ((uint32_t)(mA0 & 7) << 7);
    const uint32_t aoff1 = ((uint32_t)(mA1 >> 3) << 10) + ((uint32_t)(mA1 & 7) << 7);
    const uint32_t xorA  = (uint32_t)(mA0 & 7) << 4;     // same for mA1
    const int kqa = (quad >> 1) * 8;
    // B x4 matrices order: (n0,k0),(n0,k0+8),(n0+8,k0),(n0+8,k0+8)
    const int nB = n0w + lrow + (quad >> 1) * 8;
    const uint32_t boff = ((uint32_t)(nB >> 3) << 10) + ((uint32_t)(nB & 7) << 7);
    const uint32_t xorB = (uint32_t)(nB & 7) << 4;
    const int kqb = (quad & 1) * 8;

    __syncthreads();

    for (int ch = 0; ch < NC; ch++) {
        // store prefetched B chunk to smem
        uint4* dstb = (uint4*)Bb;
        #pragma unroll
        for (int t = 0; t < 8; t++) dstb[tid + t * 512] = pre[t];
        __syncthreads();
        // kick off next chunk's global loads (hidden under MMA)
        if (ch + 1 < NC) {
            const uint4* srcb = (const uint4*)((const char*)wblk + (size_t)(ch + 1) * 65536);
            #pragma unroll
            for (int t = 0; t < 8; t++) pre[t] = srcb[tid + t * 512];
        }

        float c[2][2][4];
        #pragma unroll
        for (int mt = 0; mt < 2; mt++)
            #pragma unroll
            for (int nt = 0; nt < 2; nt++)
                #pragma unroll
                for (int i = 0; i < 4; i++) c[mt][nt][i] = 0.f;

        // 3 split terms: hi*hi + lo*hi + hi*lo, each K=256 (16 k16-steps)
        #pragma unroll
        for (int term = 0; term < 3; term++) {
            const int ab = (term == 1) ? 256 : 0;
            const int bb = (term == 2) ? 256 : 0;
            #pragma unroll
            for (int s = 0; s < 16; s++) {
                const int ak = ab + s * 16 + kqa;
                const int bk = bb + s * 16 + kqb;
                const uint32_t kpA = (((uint32_t)(ak >> 6)) << 14) | (((uint32_t)(ak & 63)) << 1);
                const uint32_t kpB = (((uint32_t)(bk >> 6)) << 13) | (((uint32_t)(bk & 63)) << 1);
                uint32_t a0[4], a1[4], b[4];
                ldsm_x4(a0, sA + aoff0 + (kpA ^ xorA));
                ldsm_x4(a1, sA + aoff1 + (kpA ^ xorA));
                ldsm_x4(b,  sB + boff  + (kpB ^ xorB));
                mma16816(c[0][0], a0, b);
                mma16816(c[0][1], a0, b + 2);
                mma16816(c[1][0], a1, b);
                mma16816(c[1][1], a1, b + 2);
            }
        }

        // epilogue: bias add + direct STG.64 (thread t: rows m0+t/4 (+8), cols n0+2*(t&3))
        const int colb = ch * 64 + n0w;
        #pragma unroll
        for (int nt = 0; nt < 2; nt++) {
            const int col = colb + nt * 8 + 2 * (lid & 3);
            const float2 bv = *(const float2*)(bias + col);
            #pragma unroll
            for (int mt = 0; mt < 2; mt++) {
                const int rlo = r0 + m0w + mt * 16 + (lid >> 2);
                *(float2*)(C + (size_t)rlo * ldc + col) =
                    make_float2(c[mt][nt][0] + bv.x, c[mt][nt][1] + bv.y);
                *(float2*)(C + (size_t)(rlo + 8) * ldc + col) =
                    make_float2(c[mt][nt][2] + bv.x, c[mt][nt][3] + bv.y);
            }
        }
        __syncthreads();   // before overwriting B smem
    }
}

// ---------------- attention: 1 CTA per window, fp32 + packed FMA2 ----------------
#define KVP 264   // smem pitch (floats)

__global__ void __launch_bounds__(512, 1)
attn_kernel() {
    extern __shared__ float asm_[];
    float* s_k = asm_;                // 64 x KVP
    float* s_v = asm_ + 64 * KVP;     // 64 x KVP
    const int tid = threadIdx.x;
    const int bw  = blockIdx.x;
    const int h = tid >> 6, n = tid & 63;

    const float* kvbase = g_KV + (size_t)bw * 64 * 512;
    #pragma unroll
    for (int t = 0; t < 16; t++) {
        int idx = tid + t * 512;          // 8192 float4
        int m = idx >> 7, c4 = idx & 127;
        float4 v = *(const float4*)(kvbase + (size_t)m * 512 + c4 * 4);
        if (c4 < 64) *(float4*)(s_k + m * KVP + c4 * 4) = v;
        else         *(float4*)(s_v + m * KVP + (c4 - 64) * 4) = v;
    }

    // q[h][n][0..31] into packed regs
    ull qr[16];
    const float4* qp = (const float4*)(g_q + tid * 32);
    #pragma unroll
    for (int i = 0; i < 8; i++) {
        float4 q4 = qp[i];
        asm("mov.b64 %0, {%1, %2};" : "=l"(qr[2*i])   : "f"(q4.x), "f"(q4.y));
        asm("mov.b64 %0, {%1, %2};" : "=l"(qr[2*i+1]) : "f"(q4.z), "f"(q4.w));
    }
    __syncthreads();

    // ---- QK^T : s[m] = q . k[m] ----
    float s[64];
    const char* kb = (const char*)(s_k + h * 32);
    #pragma unroll 2
    for (int m = 0; m < 64; m++) {
        ull a0 = 0, a1 = 0;
        const char* kr = kb + m * (KVP * 4);
        #pragma unroll
        for (int i = 0; i < 8; i++) {
            ulonglong2 kv2 = *(const ulonglong2*)(kr + i * 16);   // broadcast LDS128
            FMA2(a0, qr[2*i],   kv2.x, a0);
            FMA2(a1, qr[2*i+1], kv2.y, a1);
        }
        float2 f0 = up2(a0), f1 = up2(a1);
        s[m] = (f0.x + f0.y) + (f1.x + f1.y);
    }

    // ---- bias + softmax ----
    const float* bp = g_biasT + h * 4096 + n;
    float mx = -1e30f;
    #pragma unroll
    for (int m = 0; m < 64; m++) { s[m] += bp[m * 64]; mx = fmaxf(mx, s[m]); }
    float sum = 0.f;
    #pragma unroll
    for (int m = 0; m < 64; m++) { s[m] = __expf(s[m] - mx); sum += s[m]; }
    float inv = 1.f / sum;
    #pragma unroll
    for (int m = 0; m < 64; m++) s[m] *= inv;

    // ---- AV : o[e] = sum_m p[m] * v[m][e], packed accumulators ----
    ull o[16];
    #pragma unroll
    for (int i = 0; i < 16; i++) o[i] = 0ULL;
    const char* vb = (const char*)(s_v + h * 32);
    #pragma unroll 2
    for (int m = 0; m < 64; m++) {
        ull pv = pk2(s[m]);
        const char* vr = vb + m * (KVP * 4);
        #pragma unroll
        for (int i = 0; i < 8; i++) {
            ulonglong2 vv = *(const ulonglong2*)(vr + i * 16);
            FMA2(o[2*i],   pv, vv.x, o[2*i]);
            FMA2(o[2*i+1], pv, vv.y, o[2*i+1]);
        }
    }
    __syncthreads();    // everyone done reading s_k -> reuse as output stage

    float* so = s_k;    // stage [n][KVP], 256 cols used
    #pragma unroll
    for (int i = 0; i < 16; i += 2) {
        float2 fa = up2(o[i]), fb = up2(o[i+1]);
        *(float4*)(so + n * KVP + h * 32 + i * 2) = make_float4(fa.x, fa.y, fb.x, fb.y);
    }
    __syncthreads();

    float* ob = g_O + (size_t)bw * 64 * 256;
    #pragma unroll
    for (int t = 0; t < 8; t++) {
        int idx = tid + t * 512;          // 4096 float4
        int m = idx >> 6, c4 = idx & 63;
        *(float4*)(ob + m * 256 + c4 * 4) = *(const float4*)(so + m * KVP + c4 * 4);
    }
}

// ---------------- launcher ----------------
extern "C" void kernel_launch(void* const* d_in, const int* in_sizes, int n_in,
                              void* d_out, int out_size) {
    const float* x      = (const float*)d_in[0];
    const float* emb    = (const float*)d_in[1];
    const float* rpb    = (const float*)d_in[2];
    const float* q_w    = (const float*)d_in[3];
    const float* q_b    = (const float*)d_in[4];
    const float* kv_w   = (const float*)d_in[5];
    const float* kv_b   = (const float*)d_in[6];
    const float* proj_w = (const float*)d_in[7];
    const float* proj_b = (const float*)d_in[8];
    float* out = (float*)d_out;
    (void)in_sizes; (void)n_in; (void)out_size;

    const int GSM = 1024 + 131072 + 65536;   // 197632
    const int ASM = 2 * 64 * KVP * 4;        // 135168

    cudaFuncSetAttribute(gemm_kernel<8, true>,
                         cudaFuncAttributeMaxDynamicSharedMemorySize, GSM);
    cudaFuncSetAttribute(gemm_kernel<4, false>,
                         cudaFuncAttributeMaxDynamicSharedMemorySize, GSM);
    cudaFuncSetAttribute(attn_kernel,
                         cudaFuncAttributeMaxDynamicSharedMemorySize, ASM);

    setup_kernel<<<864, 512>>>(emb, rpb, q_w, q_b, kv_w, proj_w);
    gemm_kernel<8, true ><<<1024, 512, GSM>>>(x, kv_b, nullptr);
    attn_kernel<<<2048, 512, ASM>>>();
    gemm_kernel<4, false><<<1024, 512, GSM>>>(nullptr, proj_b, out);
}

// round 6
// speedup vs baseline: 2.6314x; 1.6052x over previous
#include <cuda_runtime.h>
#include <cuda_bf16.h>
#include <cstdint>

typedef unsigned long long ull;

#define SCALE 0.17677669529663687f   // 32^-0.5

// ---------------- device scratch ----------------
__device__ __align__(128) float g_KV[131072ULL * 512];   // [gtok][512] (k:0..255, v:256..511)
__device__ __align__(128) float g_O [131072ULL * 256];   // [gtok][256]
__device__ __align__(128) float g_q   [8 * 64 * 32];     // [(h*64+n)*32+e], already * SCALE
__device__ __align__(128) float g_biasT[8 * 64 * 64];    // [h][m][n]
__device__ __align__(128) __nv_bfloat16 g_kvw_blk[262144]; // 8 chunks x 64KB blocked SW128 (hi|lo)
__device__ __align__(128) __nv_bfloat16 g_pw_blk [131072]; // 4 chunks x 64KB

// ---------------- helpers ----------------
__device__ __forceinline__ uint32_t smem_u32(const void* p) {
    uint32_t a;
    asm("{ .reg .u64 t; cvta.to.shared.u64 t, %1; cvt.u32.u64 %0, t; }" : "=r"(a) : "l"(p));
    return a;
}
__device__ __forceinline__ ull pk2(float x) {
    ull r; asm("mov.b64 %0, {%1, %1};" : "=l"(r) : "r"(__float_as_uint(x))); return r;
}
__device__ __forceinline__ float2 up2(ull v) {
    float2 f; asm("mov.b64 {%0, %1}, %2;" : "=f"(f.x), "=f"(f.y) : "l"(v)); return f;
}
#define FMA2(d, a, b, c) \
    asm("fma.rn.f32x2 %0, %1, %2, %3;" : "=l"(d) : "l"(a), "l"(b), "l"(c))

// blocked SW128 layouts: atom = 8 rows x 64 bf16 (1024B); atoms: (rows/8) per k-col-block
__device__ __forceinline__ uint32_t a_sw_off(int m, int kk) {   // A: 128 rows
    uint32_t off = ((uint32_t)(kk >> 6) * 16 + (m >> 3)) * 1024 + (m & 7) * 128 + (kk & 63) * 2;
    return off ^ ((off >> 3) & 0x70);
}
__device__ __forceinline__ uint32_t b_sw_off(int nn, int kk) {  // B: 64 rows
    uint32_t off = ((uint32_t)(kk >> 6) * 8 + (nn >> 3)) * 1024 + (nn & 7) * 128 + (kk & 63) * 2;
    return off ^ ((off >> 3) & 0x70);
}

__device__ __forceinline__ void ldsm_x4(uint32_t* r, uint32_t addr) {
    asm volatile("ldmatrix.sync.aligned.m8n8.x4.shared.b16 {%0,%1,%2,%3}, [%4];"
        : "=r"(r[0]), "=r"(r[1]), "=r"(r[2]), "=r"(r[3]) : "r"(addr));
}
__device__ __forceinline__ void mma16816(float* c, const uint32_t* a, const uint32_t* b) {
    asm volatile(
        "mma.sync.aligned.m16n8k16.row.col.f32.bf16.bf16.f32 "
        "{%0,%1,%2,%3}, {%4,%5,%6,%7}, {%8,%9}, {%0,%1,%2,%3};"
        : "+f"(c[0]), "+f"(c[1]), "+f"(c[2]), "+f"(c[3])
        : "r"(a[0]), "r"(a[1]), "r"(a[2]), "r"(a[3]), "r"(b[0]), "r"(b[1]));
}

// ---------------- setup: q, bias, weight conversion (runs once per launch) ----------------
__global__ void setup_kernel(const float* __restrict__ emb,
                             const float* __restrict__ rpb,
                             const float* __restrict__ q_w,
                             const float* __restrict__ q_b,
                             const float* __restrict__ kv_w,
                             const float* __restrict__ proj_w) {
    int gid = blockIdx.x * blockDim.x + threadIdx.x;
    if (gid < 16384) {
        // g_q[(h*64+n)*32+e] = SCALE * (emb[n] . q_w[h*32+e] + q_b)
        int e = gid & 31; int hn = gid >> 5;
        int h = hn >> 6, n = hn & 63;
        int d = h * 32 + e;
        const float* er = emb + n * 256;
        const float* wr = q_w + d * 256;
        float acc = q_b[d];
        #pragma unroll 4
        for (int c = 0; c < 256; c++) acc = fmaf(er[c], wr[c], acc);
        g_q[gid] = acc * SCALE;
    } else if (gid < 49152) {
        int t = gid - 16384;
        int h = t >> 12, m = (t >> 6) & 63, n = t & 63;
        int r0 = (n >> 3) - (m >> 3) + 7;
        int r1 = (n & 7) - (m & 7) + 7;
        g_biasT[t] = rpb[(r0 * 15 + r1) * 8 + h];
    } else if (gid < 311296) {
        // kv_w [512][256] -> hi|lo bf16 blocked swizzled, chunk = d>>6
        int t = gid - 49152;             // n*512 + kk
        int n = t >> 9, kk = t & 511;
        float w = kv_w[n * 256 + (kk & 255)];
        __nv_bfloat16 hb = __float2bfloat16(w);
        __nv_bfloat16 val = (kk < 256) ? hb : __float2bfloat16(w - __bfloat162float(hb));
        g_kvw_blk[(((uint32_t)(n >> 6)) * 65536 + b_sw_off(n & 63, kk)) >> 1] = val;
    } else {
        int t = gid - 311296;            // n*512 + kk, n < 256
        int n = t >> 9, kk = t & 511;
        float w = proj_w[n * 256 + (kk & 255)];
        __nv_bfloat16 hb = __float2bfloat16(w);
        __nv_bfloat16 val = (kk < 256) ? hb : __float2bfloat16(w - __bfloat162float(hb));
        g_pw_blk[(((uint32_t)(n >> 6)) * 65536 + b_sw_off(n & 63, kk)) >> 1] = val;
    }
}

// ---------------- mma.sync split-bf16 GEMM: C[128 x NC*64] = A[128x256] @ W^T + bias --------
// A in smem as bf16 hi (k 0..255) | lo (k 256..511), blocked SW128 (128KB).
// B streamed as 16KB sub-chunks (64 cols x 128 k) through a 6-slot cp.async ring (3 in flight).
template<int NC, bool GATHER>
__global__ void __launch_bounds__(512, 1)
gemm_kernel(const float* __restrict__ xsrc,
            const float* __restrict__ bias,
            float* __restrict__ coutp) {
    extern __shared__ char gsm[];
    const uint32_t sraw = smem_u32(gsm);
    const uint32_t sA = (sraw + 1023) & ~1023u;
    const uint32_t sB = sA + 131072;          // 6 x 16KB ring
    char* Ab = gsm + (sA - sraw);

    const int tid = threadIdx.x;
    const int wid = tid >> 5;
    const int lid = tid & 31;
    const int r0  = blockIdx.x * 128;
    const int NSUB = 4 * NC;

    const __nv_bfloat16* wblk = GATHER ? g_kvw_blk : g_pw_blk;
    float* C = GATHER ? g_KV : coutp;
    const int ldc = NC * 64;

    // issue sub-chunk copy j into ring slot j%6 (1 commit group = 16KB)
    auto issue_copy = [&](int j) {
        uint32_t dst = sB + (uint32_t)(j % 6) * 16384 + (uint32_t)tid * 16;
        const char* src = (const char*)wblk + (size_t)j * 16384 + (size_t)tid * 16;
        asm volatile("cp.async.cg.shared.global [%0], [%1], 16;" :: "r"(dst), "l"(src));
        asm volatile("cp.async.cg.shared.global [%0], [%1], 16;" :: "r"(dst + 8192), "l"(src + 8192));
        asm volatile("cp.async.commit_group;" ::: "memory");
    };

    // prologue: 3 sub-chunks in flight before A build
    issue_copy(0); issue_copy(1); issue_copy(2);

    // ---- build A tile: fp32 -> bf16 hi (k 0..255) | lo (k 256..511), blocked SW128 ----
    #pragma unroll 4
    for (int it = 0; it < 32; it++) {
        int idx = tid + it * 512;            // 0..16383 (float2 units)
        int m = idx >> 7, p = idx & 127, c = p * 2;
        const float* rowp;
        if constexpr (GATHER) {
            int r = r0 + m;                  // r = bw*64 + n
            int b = r >> 14, i = (r >> 10) & 15, j = (r >> 6) & 15, n = r & 63;
            rowp = xsrc + ((size_t)b << 22) + ((size_t)i << 18)
                 + ((size_t)(n >> 3) << 15) + ((size_t)j << 11) + ((size_t)(n & 7) << 8);
        } else {
            rowp = g_O + (size_t)(r0 + m) * 256;
        }
        float2 f = *(const float2*)(rowp + c);
        __nv_bfloat162 h2 = __floats2bfloat162_rn(f.x, f.y);
        float lx = f.x - __bfloat162float(h2.x);
        float ly = f.y - __bfloat162float(h2.y);
        __nv_bfloat162 l2 = __floats2bfloat162_rn(lx, ly);
        *(uint32_t*)(Ab + a_sw_off(m, c))       = *(uint32_t*)&h2;
        *(uint32_t*)(Ab + a_sw_off(m, c + 256)) = *(uint32_t*)&l2;
    }

    // ---- per-warp / per-lane geometry for ldmatrix ----
    const int m0w = (wid >> 2) * 32;         // warp tile 32 rows x 16 cols; grid 4x4
    const int n0w = (wid & 3) * 16;
    const int lrow = lid & 7;
    const int quad = lid >> 3;
    const int mA0 = m0w + lrow + (quad & 1) * 8;
    const int mA1 = mA0 + 16;
    const uint32_t aoff0 = ((uint32_t)(mA0 >> 3) << 10) + ((uint32_t)(mA0 & 7) << 7);
    const uint32_t aoff1 = ((uint32_t)(mA1 >> 3) << 10) + ((uint32_t)(mA1 & 7) << 7);
    const uint32_t xorA  = (uint32_t)(mA0 & 7) << 4;     // same for mA1
    const int kqa = (quad >> 1) * 8;
    const int nB = n0w + lrow + (quad >> 1) * 8;
    const uint32_t boff = ((uint32_t)(nB >> 3) << 10) + ((uint32_t)(nB & 7) << 7);
    const uint32_t xorB = (uint32_t)(nB & 7) << 4;
    const int kqb = (quad & 1) * 8;

    auto ldA = [&](int ak, uint32_t* d0, uint32_t* d1) {
        uint32_t kp = (((uint32_t)(ak >> 6)) << 14) | (((uint32_t)(ak & 63)) << 1);
        ldsm_x4(d0, sA + aoff0 + (kp ^ xorA));
        ldsm_x4(d1, sA + aoff1 + (kp ^ xorA));
    };
    auto ldB = [&](uint32_t slot, int kl, uint32_t* d) {
        uint32_t kp = (((uint32_t)(kl >> 6)) << 13) | (((uint32_t)(kl & 63)) << 1);
        ldsm_x4(d, slot + boff + (kp ^ xorB));
    };

    float c[2][2][4];
    #pragma unroll
    for (int mt = 0; mt < 2; mt++)
        #pragma unroll
        for (int nt = 0; nt < 2; nt++)
            #pragma unroll
            for (int i = 0; i < 4; i++) c[mt][nt][i] = 0.f;

    uint32_t fh0[2][4], fh1[2][4], fl0[2][4], fl1[2][4], fb[2][4];

    // ---- sub-chunk loop: sub 0,1 = B-hi (2 A-terms), sub 2,3 = B-lo (1 A-term) ----
    for (int i = 0; i < NSUB; i++) {
        if (i + 3 < NSUB) issue_copy(i + 3);
        asm volatile("cp.async.wait_group 3;" ::: "memory");
        __syncthreads();

        const uint32_t slot = sB + (uint32_t)(i % 6) * 16384;
        const int sub = i & 3;

        if (sub < 2) {
            const int kb = sub * 128;
            ldA(kb + kqa,       fh0[0], fh1[0]);
            ldA(kb + 256 + kqa, fl0[0], fl1[0]);
            ldB(slot, kqb, fb[0]);
            #pragma unroll
            for (int st = 0; st < 8; st++) {
                const int cb = st & 1, nb = cb ^ 1;
                if (st < 7) {
                    ldA(kb + (st + 1) * 16 + kqa,       fh0[nb], fh1[nb]);
                    ldA(kb + 256 + (st + 1) * 16 + kqa, fl0[nb], fl1[nb]);
                    ldB(slot, (st + 1) * 16 + kqb, fb[nb]);
                }
                mma16816(c[0][0], fh0[cb], fb[cb]);
                mma16816(c[0][1], fh0[cb], fb[cb] + 2);
                mma16816(c[1][0], fh1[cb], fb[cb]);
                mma16816(c[1][1], fh1[cb], fb[cb] + 2);
                mma16816(c[0][0], fl0[cb], fb[cb]);
                mma16816(c[0][1], fl0[cb], fb[cb] + 2);
                mma16816(c[1][0], fl1[cb], fb[cb]);
                mma16816(c[1][1], fl1[cb], fb[cb] + 2);
            }
        } else {
            const int kb = (sub - 2) * 128;
            ldA(kb + kqa, fh0[0], fh1[0]);
            ldB(slot, kqb, fb[0]);
            #pragma unroll
            for (int st = 0; st < 8; st++) {
                const int cb = st & 1, nb = cb ^ 1;
                if (st < 7) {
                    ldA(kb + (st + 1) * 16 + kqa, fh0[nb], fh1[nb]);
                    ldB(slot, (st + 1) * 16 + kqb, fb[nb]);
                }
                mma16816(c[0][0], fh0[cb], fb[cb]);
                mma16816(c[0][1], fh0[cb], fb[cb] + 2);
                mma16816(c[1][0], fh1[cb], fb[cb]);
                mma16816(c[1][1], fh1[cb], fb[cb] + 2);
            }
        }

        if (sub == 3) {
            // epilogue for chunk ch = i>>2: bias add + direct STG.64
            const int ch = i >> 2;
            const int colb = ch * 64 + n0w;
            #pragma unroll
            for (int nt = 0; nt < 2; nt++) {
                const int col = colb + nt * 8 + 2 * (lid & 3);
                const float2 bv = *(const float2*)(bias + col);
                #pragma unroll
                for (int mt = 0; mt < 2; mt++) {
                    const int rlo = r0 + m0w + mt * 16 + (lid >> 2);
                    *(float2*)(C + (size_t)rlo * ldc + col) =
                        make_float2(c[mt][nt][0] + bv.x, c[mt][nt][1] + bv.y);
                    *(float2*)(C + (size_t)(rlo + 8) * ldc + col) =
                        make_float2(c[mt][nt][2] + bv.x, c[mt][nt][3] + bv.y);
                }
            }
            #pragma unroll
            for (int mt = 0; mt < 2; mt++)
                #pragma unroll
                for (int nt = 0; nt < 2; nt++)
                    #pragma unroll
                    for (int k2 = 0; k2 < 4; k2++) c[mt][nt][k2] = 0.f;
        }
    }
}

// ---------------- attention: 1 CTA per window, fp32 + packed FMA2 ----------------
#define KVP 264   // smem pitch (floats)

__global__ void __launch_bounds__(512, 1)
attn_kernel() {
    extern __shared__ float asm_[];
    float* s_k = asm_;                // 64 x KVP
    float* s_v = asm_ + 64 * KVP;     // 64 x KVP
    const int tid = threadIdx.x;
    const int bw  = blockIdx.x;
    const int h = tid >> 6, n = tid & 63;

    const float* kvbase = g_KV + (size_t)bw * 64 * 512;
    #pragma unroll
    for (int t = 0; t < 16; t++) {
        int idx = tid + t * 512;          // 8192 float4
        int m = idx >> 7, c4 = idx & 127;
        float4 v = *(const float4*)(kvbase + (size_t)m * 512 + c4 * 4);
        if (c4 < 64) *(float4*)(s_k + m * KVP + c4 * 4) = v;
        else         *(float4*)(s_v + m * KVP + (c4 - 64) * 4) = v;
    }

    // q[h][n][0..31] into packed regs
    ull qr[16];
    const float4* qp = (const float4*)(g_q + tid * 32);
    #pragma unroll
    for (int i = 0; i < 8; i++) {
        float4 q4 = qp[i];
        asm("mov.b64 %0, {%1, %2};" : "=l"(qr[2*i])   : "f"(q4.x), "f"(q4.y));
        asm("mov.b64 %0, {%1, %2};" : "=l"(qr[2*i+1]) : "f"(q4.z), "f"(q4.w));
    }
    __syncthreads();

    // ---- QK^T : s[m] = q . k[m] ----
    float s[64];
    const char* kb = (const char*)(s_k + h * 32);
    #pragma unroll 2
    for (int m = 0; m < 64; m++) {
        ull a0 = 0, a1 = 0;
        const char* kr = kb + m * (KVP * 4);
        #pragma unroll
        for (int i = 0; i < 8; i++) {
            ulonglong2 kv2 = *(const ulonglong2*)(kr + i * 16);   // broadcast LDS128
            FMA2(a0, qr[2*i],   kv2.x, a0);
            FMA2(a1, qr[2*i+1], kv2.y, a1);
        }
        float2 f0 = up2(a0), f1 = up2(a1);
        s[m] = (f0.x + f0.y) + (f1.x + f1.y);
    }

    // ---- bias + softmax ----
    const float* bp = g_biasT + h * 4096 + n;
    float mx = -1e30f;
    #pragma unroll
    for (int m = 0; m < 64; m++) { s[m] += bp[m * 64]; mx = fmaxf(mx, s[m]); }
    float sum = 0.f;
    #pragma unroll
    for (int m = 0; m < 64; m++) { s[m] = __expf(s[m] - mx); sum += s[m]; }
    float inv = 1.f / sum;
    #pragma unroll
    for (int m = 0; m < 64; m++) s[m] *= inv;

    // ---- AV : o[e] = sum_m p[m] * v[m][e], packed accumulators ----
    ull o[16];
    #pragma unroll
    for (int i = 0; i < 16; i++) o[i] = 0ULL;
    const char* vb = (const char*)(s_v + h * 32);
    #pragma unroll 2
    for (int m = 0; m < 64; m++) {
        ull pv = pk2(s[m]);
        const char* vr = vb + m * (KVP * 4);
        #pragma unroll
        for (int i = 0; i < 8; i++) {
            ulonglong2 vv = *(const ulonglong2*)(vr + i * 16);
            FMA2(o[2*i],   pv, vv.x, o[2*i]);
            FMA2(o[2*i+1], pv, vv.y, o[2*i+1]);
        }
    }
    __syncthreads();    // everyone done reading s_k -> reuse as output stage

    float* so = s_k;    // stage [n][KVP], 256 cols used
    #pragma unroll
    for (int i = 0; i < 16; i += 2) {
        float2 fa = up2(o[i]), fb2 = up2(o[i+1]);
        *(float4*)(so + n * KVP + h * 32 + i * 2) = make_float4(fa.x, fa.y, fb2.x, fb2.y);
    }
    __syncthreads();

    float* ob = g_O + (size_t)bw * 64 * 256;
    #pragma unroll
    for (int t = 0; t < 8; t++) {
        int idx = tid + t * 512;          // 4096 float4
        int m = idx >> 6, c4 = idx & 63;
        *(float4*)(ob + m * 256 + c4 * 4) = *(const float4*)(so + m * KVP + c4 * 4);
    }
}

// ---------------- launcher ----------------
extern "C" void kernel_launch(void* const* d_in, const int* in_sizes, int n_in,
                              void* d_out, int out_size) {
    const float* x      = (const float*)d_in[0];
    const float* emb    = (const float*)d_in[1];
    const float* rpb    = (const float*)d_in[2];
    const float* q_w    = (const float*)d_in[3];
    const float* q_b    = (const float*)d_in[4];
    const float* kv_w   = (const float*)d_in[5];
    const float* kv_b   = (const float*)d_in[6];
    const float* proj_w = (const float*)d_in[7];
    const float* proj_b = (const float*)d_in[8];
    float* out = (float*)d_out;
    (void)in_sizes; (void)n_in; (void)out_size;

    const int GSM = 1024 + 131072 + 98304;   // 230400: pad + A + 6x16KB ring
    const int ASM = 2 * 64 * KVP * 4;        // 135168

    cudaFuncSetAttribute(gemm_kernel<8, true>,
                         cudaFuncAttributeMaxDynamicSharedMemorySize, GSM);
    cudaFuncSetAttribute(gemm_kernel<4, false>,
                         cudaFuncAttributeMaxDynamicSharedMemorySize, GSM);
    cudaFuncSetAttribute(attn_kernel,
                         cudaFuncAttributeMaxDynamicSharedMemorySize, ASM);

    setup_kernel<<<864, 512>>>(emb, rpb, q_w, q_b, kv_w, proj_w);
    gemm_kernel<8, true ><<<1024, 512, GSM>>>(x, kv_b, nullptr);
    attn_kernel<<<2048, 512, ASM>>>();
    gemm_kernel<4, false><<<1024, 512, GSM>>>(nullptr, proj_b, out);
}

// round 7
// speedup vs baseline: 2.7342x; 1.0391x over previous
#include <cuda_runtime.h>
#include <cuda_bf16.h>
#include <cstdint>

typedef unsigned long long ull;

#define SCALE 0.17677669529663687f   // 32^-0.5

// ---------------- device scratch ----------------
__device__ __align__(128) float g_KV[131072ULL * 512];   // [gtok][512] (k:0..255, v:256..511)
__device__ __align__(128) float g_O [131072ULL * 256];   // [gtok][256]
__device__ __align__(128) float g_q   [8 * 64 * 32];     // [(h*64+n)*32+e], already * SCALE
__device__ __align__(128) float g_biasT[8 * 64 * 64];    // [h][m][n]
// B stages: 32KB each = 128 cols x 128 k (SW128 atoms). kv: 16 stages, proj: 8 stages.
__device__ __align__(128) __nv_bfloat16 g_kvw_blk[262144];
__device__ __align__(128) __nv_bfloat16 g_pw_blk [131072];

// ---------------- helpers ----------------
__device__ __forceinline__ uint32_t smem_u32(const void* p) {
    uint32_t a;
    asm("{ .reg .u64 t; cvta.to.shared.u64 t, %1; cvt.u32.u64 %0, t; }" : "=r"(a) : "l"(p));
    return a;
}
__device__ __forceinline__ ull pk2(float x) {
    ull r; asm("mov.b64 %0, {%1, %1};" : "=l"(r) : "r"(__float_as_uint(x))); return r;
}
__device__ __forceinline__ float2 up2(ull v) {
    float2 f; asm("mov.b64 {%0, %1}, %2;" : "=f"(f.x), "=f"(f.y) : "l"(v)); return f;
}
#define FMA2(d, a, b, c) \
    asm("fma.rn.f32x2 %0, %1, %2, %3;" : "=l"(d) : "l"(a), "l"(b), "l"(c))

// 128-row blocked SW128: atom = 8 rows x 64 bf16 (1024B), 16 atoms per 64-k block
__device__ __forceinline__ uint32_t a_sw_off(int m, int kk) {
    uint32_t off = ((uint32_t)(kk >> 6) * 16 + (m >> 3)) * 1024 + (m & 7) * 128 + (kk & 63) * 2;
    return off ^ ((off >> 3) & 0x70);
}

__device__ __forceinline__ void ldsm_x4(uint32_t* r, uint32_t addr) {
    asm volatile("ldmatrix.sync.aligned.m8n8.x4.shared.b16 {%0,%1,%2,%3}, [%4];"
        : "=r"(r[0]), "=r"(r[1]), "=r"(r[2]), "=r"(r[3]) : "r"(addr));
}
__device__ __forceinline__ void mma16816(float* c, const uint32_t* a, const uint32_t* b) {
    asm volatile(
        "mma.sync.aligned.m16n8k16.row.col.f32.bf16.bf16.f32 "
        "{%0,%1,%2,%3}, {%4,%5,%6,%7}, {%8,%9}, {%0,%1,%2,%3};"
        : "+f"(c[0]), "+f"(c[1]), "+f"(c[2]), "+f"(c[3])
        : "r"(a[0]), "r"(a[1]), "r"(a[2]), "r"(a[3]), "r"(b[0]), "r"(b[1]));
}

// ---------------- setup: q, bias, weight conversion (runs once per launch) ----------------
__global__ void setup_kernel(const float* __restrict__ emb,
                             const float* __restrict__ rpb,
                             const float* __restrict__ q_w,
                             const float* __restrict__ q_b,
                             const float* __restrict__ kv_w,
                             const float* __restrict__ proj_w) {
    int gid = blockIdx.x * blockDim.x + threadIdx.x;
    if (gid < 16384) {
        int e = gid & 31; int hn = gid >> 5;
        int h = hn >> 6, n = hn & 63;
        int d = h * 32 + e;
        const float* er = emb + n * 256;
        const float* wr = q_w + d * 256;
        float acc = q_b[d];
        #pragma unroll 4
        for (int c = 0; c < 256; c++) acc = fmaf(er[c], wr[c], acc);
        g_q[gid] = acc * SCALE;
    } else if (gid < 49152) {
        int t = gid - 16384;
        int h = t >> 12, m = (t >> 6) & 63, n = t & 63;
        int r0 = (n >> 3) - (m >> 3) + 7;
        int r1 = (n & 7) - (m & 7) + 7;
        g_biasT[t] = rpb[(r0 * 15 + r1) * 8 + h];
    } else if (gid < 311296) {
        // kv_w: extended-k layout (hi 0..255 | lo 256..511), stage = 32KB (128 cols x 128 k)
        int t = gid - 49152;             // n*512 + kk,  n < 512
        int n = t >> 9, kk = t & 511;
        float w = kv_w[n * 256 + (kk & 255)];
        __nv_bfloat16 hb = __float2bfloat16(w);
        __nv_bfloat16 val = (kk < 256) ? hb : __float2bfloat16(w - __bfloat162float(hb));
        int cp = n >> 7, nn = n & 127, j = kk >> 7, kkl = kk & 127;
        g_kvw_blk[(((uint32_t)(cp * 4 + j)) * 32768 + a_sw_off(nn, kkl)) >> 1] = val;
    } else {
        int t = gid - 311296;            // n*512 + kk,  n < 256
        int n = t >> 9, kk = t & 511;
        float w = proj_w[n * 256 + (kk & 255)];
        __nv_bfloat16 hb = __float2bfloat16(w);
        __nv_bfloat16 val = (kk < 256) ? hb : __float2bfloat16(w - __bfloat162float(hb));
        int cp = n >> 7, nn = n & 127, j = kk >> 7, kkl = kk & 127;
        g_pw_blk[(((uint32_t)(cp * 4 + j)) * 32768 + a_sw_off(nn, kkl)) >> 1] = val;
    }
}

// ---------------- mma.sync split-bf16 GEMM: C[128 x NC*64] = A[128x256] @ W^T + bias --------
// A in smem as bf16 hi|lo blocked SW128 (128KB). B streamed as 32KB stages
// (128 cols x 128 k) through a 3-slot cp.async ring. Warp tile 32x32, grid 4x4.
template<int NC, bool GATHER>
__global__ void __launch_bounds__(512, 1)
gemm_kernel(const float* __restrict__ xsrc,
            const float* __restrict__ bias,
            float* __restrict__ coutp) {
    extern __shared__ char gsm[];
    const uint32_t sraw = smem_u32(gsm);
    const uint32_t sA = (sraw + 1023) & ~1023u;
    const uint32_t sB = sA + 131072;          // 3 x 32KB ring

    const int tid = threadIdx.x;
    const int wid = tid >> 5;
    const int lid = tid & 31;
    const int r0  = blockIdx.x * 128;
    const int NST = 2 * NC;                    // stages (4 per 128-col pair)

    const __nv_bfloat16* wblk = GATHER ? g_kvw_blk : g_pw_blk;
    float* C = GATHER ? g_KV : coutp;
    const int ldc = NC * 64;
    char* Ab = gsm + (sA - sraw);

    // issue stage j into ring slot j%3 (one commit group = 32KB; 64B/thread)
    auto issue_copy = [&](int j) {
        uint32_t dst = sB + (uint32_t)(j % 3) * 32768 + (uint32_t)tid * 64;
        const char* src = (const char*)wblk + (size_t)j * 32768 + (size_t)tid * 64;
        #pragma unroll
        for (int q = 0; q < 4; q++)
            asm volatile("cp.async.cg.shared.global [%0], [%1], 16;"
                         :: "r"(dst + q * 16), "l"(src + q * 16));
        asm volatile("cp.async.commit_group;" ::: "memory");
    };

    issue_copy(0); issue_copy(1); issue_copy(2);

    // ---- build A tile: fp32 -> bf16 hi (k 0..255) | lo (k 256..511), blocked SW128 ----
    #pragma unroll 4
    for (int it = 0; it < 32; it++) {
        int idx = tid + it * 512;            // 0..16383 (float2 units)
        int m = idx >> 7, p = idx & 127, c = p * 2;
        const float* rowp;
        if constexpr (GATHER) {
            int r = r0 + m;                  // r = bw*64 + n
            int b = r >> 14, i = (r >> 10) & 15, j = (r >> 6) & 15, n = r & 63;
            rowp = xsrc + ((size_t)b << 22) + ((size_t)i << 18)
                 + ((size_t)(n >> 3) << 15) + ((size_t)j << 11) + ((size_t)(n & 7) << 8);
        } else {
            rowp = g_O + (size_t)(r0 + m) * 256;
        }
        float2 f = *(const float2*)(rowp + c);
        __nv_bfloat162 h2 = __floats2bfloat162_rn(f.x, f.y);
        float lx = f.x - __bfloat162float(h2.x);
        float ly = f.y - __bfloat162float(h2.y);
        __nv_bfloat162 l2 = __floats2bfloat162_rn(lx, ly);
        *(uint32_t*)(Ab + a_sw_off(m, c))       = *(uint32_t*)&h2;
        *(uint32_t*)(Ab + a_sw_off(m, c + 256)) = *(uint32_t*)&l2;
    }

    // ---- per-warp / per-lane geometry ----
    const int m0w = (wid >> 2) * 32;          // warp tile 32 rows x 32 cols; grid 4x4
    const int n0w = (wid & 3) * 32;
    const int lrow = lid & 7;
    const int quad = lid >> 3;
    const int mA0 = m0w + lrow + (quad & 1) * 8;
    const int mA1 = mA0 + 16;
    const uint32_t aoff0 = ((uint32_t)(mA0 >> 3) << 10) + ((uint32_t)(mA0 & 7) << 7);
    const uint32_t aoff1 = ((uint32_t)(mA1 >> 3) << 10) + ((uint32_t)(mA1 & 7) << 7);
    const uint32_t xorA  = (uint32_t)(mA0 & 7) << 4;
    const int kqa = (quad >> 1) * 8;
    const int nB0 = n0w + lrow + (quad >> 1) * 8;      // B frag 0: cols n0w..+15
    const uint32_t boff0 = ((uint32_t)(nB0 >> 3) << 10) + ((uint32_t)(nB0 & 7) << 7);
    const uint32_t boff1 = boff0 + 2048;               // B frag 1: cols n0w+16..+31
    const uint32_t xorB  = (uint32_t)(nB0 & 7) << 4;
    const int kqb = (quad & 1) * 8;

    auto ldA = [&](int ak, uint32_t* d0, uint32_t* d1) {
        uint32_t kp = (((uint32_t)(ak >> 6)) << 14) | (((uint32_t)(ak & 63)) << 1);
        ldsm_x4(d0, sA + aoff0 + (kp ^ xorA));
        ldsm_x4(d1, sA + aoff1 + (kp ^ xorA));
    };
    auto ldB2 = [&](uint32_t slot, int kl, uint32_t* d0, uint32_t* d1) {
        uint32_t kp = (((uint32_t)(kl >> 6)) << 14) | (((uint32_t)(kl & 63)) << 1);
        ldsm_x4(d0, slot + boff0 + (kp ^ xorB));
        ldsm_x4(d1, slot + boff1 + (kp ^ xorB));
    };

    float c[2][4][4];
    #pragma unroll
    for (int mt = 0; mt < 2; mt++)
        #pragma unroll
        for (int nt = 0; nt < 4; nt++)
            #pragma unroll
            for (int i = 0; i < 4; i++) c[mt][nt][i] = 0.f;

    uint32_t fh0[2][4], fh1[2][4], fl0[2][4], fl1[2][4], fb0[2][4], fb1[2][4];

    // 8 MMAs across 8 independent accumulator groups, with A frags (a0,a1)
    auto mma8 = [&](uint32_t* a0, uint32_t* a1, uint32_t* b0, uint32_t* b1) {
        mma16816(c[0][0], a0, b0);
        mma16816(c[0][1], a0, b0 + 2);
        mma16816(c[0][2], a0, b1);
        mma16816(c[0][3], a0, b1 + 2);
        mma16816(c[1][0], a1, b0);
        mma16816(c[1][1], a1, b0 + 2);
        mma16816(c[1][2], a1, b1);
        mma16816(c[1][3], a1, b1 + 2);
    };

    // ---- stage loop: per pair, j 0,1 = B-hi (A hi+lo), j 2,3 = B-lo (A hi) ----
    for (int i = 0; i < NST; i++) {
        asm volatile("cp.async.wait_group 2;" ::: "memory");
        __syncthreads();

        const uint32_t slot = sB + (uint32_t)(i % 3) * 32768;
        const int j = i & 3;

        if (j < 2) {
            const int kb = j * 128;
            ldA(kb + kqa,       fh0[0], fh1[0]);
            ldA(kb + 256 + kqa, fl0[0], fl1[0]);
            ldB2(slot, kqb, fb0[0], fb1[0]);
            #pragma unroll
            for (int st = 0; st < 8; st++) {
                const int cb = st & 1, nb = cb ^ 1;
                if (st < 7) {
                    ldA(kb + (st + 1) * 16 + kqa,       fh0[nb], fh1[nb]);
                    ldA(kb + 256 + (st + 1) * 16 + kqa, fl0[nb], fl1[nb]);
                    ldB2(slot, (st + 1) * 16 + kqb, fb0[nb], fb1[nb]);
                }
                mma8(fh0[cb], fh1[cb], fb0[cb], fb1[cb]);
                mma8(fl0[cb], fl1[cb], fb0[cb], fb1[cb]);
            }
        } else {
            const int kb = (j - 2) * 128;
            ldA(kb + kqa, fh0[0], fh1[0]);
            ldB2(slot, kqb, fb0[0], fb1[0]);
            #pragma unroll
            for (int st = 0; st < 8; st++) {
                const int cb = st & 1, nb = cb ^ 1;
                if (st < 7) {
                    ldA(kb + (st + 1) * 16 + kqa, fh0[nb], fh1[nb]);
                    ldB2(slot, (st + 1) * 16 + kqb, fb0[nb], fb1[nb]);
                }
                mma8(fh0[cb], fh1[cb], fb0[cb], fb1[cb]);
            }
        }

        if (j == 3) {
            // epilogue for 128-col pair cp = i>>2: bias add + direct STG.64
            const int colb = (i >> 2) * 128 + n0w;
            #pragma unroll
            for (int nt = 0; nt < 4; nt++) {
                const int col = colb + nt * 8 + 2 * (lid & 3);
                const float2 bv = *(const float2*)(bias + col);
                #pragma unroll
                for (int mt = 0; mt < 2; mt++) {
                    const int rlo = r0 + m0w + mt * 16 + (lid >> 2);
                    *(float2*)(C + (size_t)rlo * ldc + col) =
                        make_float2(c[mt][nt][0] + bv.x, c[mt][nt][1] + bv.y);
                    *(float2*)(C + (size_t)(rlo + 8) * ldc + col) =
                        make_float2(c[mt][nt][2] + bv.x, c[mt][nt][3] + bv.y);
                }
            }
            #pragma unroll
            for (int mt = 0; mt < 2; mt++)
                #pragma unroll
                for (int nt = 0; nt < 4; nt++)
                    #pragma unroll
                    for (int k2 = 0; k2 < 4; k2++) c[mt][nt][k2] = 0.f;
        }
        __syncthreads();
        if (i + 3 < NST) issue_copy(i + 3);
    }
}

// ---------------- attention: 1 CTA per window, fp32 + packed FMA2 ----------------
#define KVP 264   // smem pitch (floats)

__global__ void __launch_bounds__(512, 1)
attn_kernel() {
    extern __shared__ float asm_[];
    float* s_k = asm_;                // 64 x KVP
    float* s_v = asm_ + 64 * KVP;     // 64 x KVP
    const int tid = threadIdx.x;
    const int bw  = blockIdx.x;
    const int h = tid >> 6, n = tid & 63;

    const float* kvbase = g_KV + (size_t)bw * 64 * 512;
    #pragma unroll
    for (int t = 0; t < 16; t++) {
        int idx = tid + t * 512;          // 8192 float4
        int m = idx >> 7, c4 = idx & 127;
        float4 v = *(const float4*)(kvbase + (size_t)m * 512 + c4 * 4);
        if (c4 < 64) *(float4*)(s_k + m * KVP + c4 * 4) = v;
        else         *(float4*)(s_v + m * KVP + (c4 - 64) * 4) = v;
    }

    ull qr[16];
    const float4* qp = (const float4*)(g_q + tid * 32);
    #pragma unroll
    for (int i = 0; i < 8; i++) {
        float4 q4 = qp[i];
        asm("mov.b64 %0, {%1, %2};" : "=l"(qr[2*i])   : "f"(q4.x), "f"(q4.y));
        asm("mov.b64 %0, {%1, %2};" : "=l"(qr[2*i+1]) : "f"(q4.z), "f"(q4.w));
    }
    __syncthreads();

    float s[64];
    const char* kb = (const char*)(s_k + h * 32);
    #pragma unroll 2
    for (int m = 0; m < 64; m++) {
        ull a0 = 0, a1 = 0;
        const char* kr = kb + m * (KVP * 4);
        #pragma unroll
        for (int i = 0; i < 8; i++) {
            ulonglong2 kv2 = *(const ulonglong2*)(kr + i * 16);
            FMA2(a0, qr[2*i],   kv2.x, a0);
            FMA2(a1, qr[2*i+1], kv2.y, a1);
        }
        float2 f0 = up2(a0), f1 = up2(a1);
        s[m] = (f0.x + f0.y) + (f1.x + f1.y);
    }

    const float* bp = g_biasT + h * 4096 + n;
    float mx = -1e30f;
    #pragma unroll
    for (int m = 0; m < 64; m++) { s[m] += bp[m * 64]; mx = fmaxf(mx, s[m]); }
    float sum = 0.f;
    #pragma unroll
    for (int m = 0; m < 64; m++) { s[m] = __expf(s[m] - mx); sum += s[m]; }
    float inv = 1.f / sum;
    #pragma unroll
    for (int m = 0; m < 64; m++) s[m] *= inv;

    ull o[16];
    #pragma unroll
    for (int i = 0; i < 16; i++) o[i] = 0ULL;
    const char* vb = (const char*)(s_v + h * 32);
    #pragma unroll 2
    for (int m = 0; m < 64; m++) {
        ull pv = pk2(s[m]);
        const char* vr = vb + m * (KVP * 4);
        #pragma unroll
        for (int i = 0; i < 8; i++) {
            ulonglong2 vv = *(const ulonglong2*)(vr + i * 16);
            FMA2(o[2*i],   pv, vv.x, o[2*i]);
            FMA2(o[2*i+1], pv, vv.y, o[2*i+1]);
        }
    }
    __syncthreads();

    float* so = s_k;
    #pragma unroll
    for (int i = 0; i < 16; i += 2) {
        float2 fa = up2(o[i]), fb2 = up2(o[i+1]);
        *(float4*)(so + n * KVP + h * 32 + i * 2) = make_float4(fa.x, fa.y, fb2.x, fb2.y);
    }
    __syncthreads();

    float* ob = g_O + (size_t)bw * 64 * 256;
    #pragma unroll
    for (int t = 0; t < 8; t++) {
        int idx = tid + t * 512;
        int m = idx >> 6, c4 = idx & 63;
        *(float4*)(ob + m * 256 + c4 * 4) = *(const float4*)(so + m * KVP + c4 * 4);
    }
}

// ---------------- launcher ----------------
extern "C" void kernel_launch(void* const* d_in, const int* in_sizes, int n_in,
                              void* d_out, int out_size) {
    const float* x      = (const float*)d_in[0];
    const float* emb    = (const float*)d_in[1];
    const float* rpb    = (const float*)d_in[2];
    const float* q_w    = (const float*)d_in[3];
    const float* q_b    = (const float*)d_in[4];
    const float* kv_w   = (const float*)d_in[5];
    const float* kv_b   = (const float*)d_in[6];
    const float* proj_w = (const float*)d_in[7];
    const float* proj_b = (const float*)d_in[8];
    float* out = (float*)d_out;
    (void)in_sizes; (void)n_in; (void)out_size;

    const int GSM = 1024 + 131072 + 98304;   // 230400: pad + A + 3x32KB ring
    const int ASM = 2 * 64 * KVP * 4;        // 135168

    cudaFuncSetAttribute(gemm_kernel<8, true>,
                         cudaFuncAttributeMaxDynamicSharedMemorySize, GSM);
    cudaFuncSetAttribute(gemm_kernel<4, false>,
                         cudaFuncAttributeMaxDynamicSharedMemorySize, GSM);
    cudaFuncSetAttribute(attn_kernel,
                         cudaFuncAttributeMaxDynamicSharedMemorySize, ASM);

    setup_kernel<<<864, 512>>>(emb, rpb, q_w, q_b, kv_w, proj_w);
    gemm_kernel<8, true ><<<1024, 512, GSM>>>(x, kv_b, nullptr);
    attn_kernel<<<2048, 512, ASM>>>();
    gemm_kernel<4, false><<<1024, 512, GSM>>>(nullptr, proj_b, out);
}

// round 8
// speedup vs baseline: 2.8612x; 1.0465x over previous
#include <cuda_runtime.h>
#include <cuda_bf16.h>
#include <cstdint>

typedef unsigned long long ull;

#define SCALE 0.17677669529663687f   // 32^-0.5

// ---------------- device scratch ----------------
__device__ __align__(128) float g_KV[131072ULL * 512];   // [gtok][512] (k:0..255, v:256..511)
__device__ __align__(128) float g_O [131072ULL * 256];   // [gtok][256]
__device__ __align__(128) float g_q   [8 * 64 * 32];     // [(h*64+n)*32+e], already * SCALE
__device__ __align__(128) float g_biasT[8 * 64 * 64];    // [h][m][n]
// B stages: 32KB each = 128 cols x 128 k (SW128 atoms). kv: 16 stages, proj: 8 stages.
__device__ __align__(128) __nv_bfloat16 g_kvw_blk[262144];
__device__ __align__(128) __nv_bfloat16 g_pw_blk [131072];

// ---------------- helpers ----------------
__device__ __forceinline__ uint32_t smem_u32(const void* p) {
    uint32_t a;
    asm("{ .reg .u64 t; cvta.to.shared.u64 t, %1; cvt.u32.u64 %0, t; }" : "=r"(a) : "l"(p));
    return a;
}
__device__ __forceinline__ ull pk2(float x) {
    ull r; asm("mov.b64 %0, {%1, %1};" : "=l"(r) : "r"(__float_as_uint(x))); return r;
}
__device__ __forceinline__ float2 up2(ull v) {
    float2 f; asm("mov.b64 {%0, %1}, %2;" : "=f"(f.x), "=f"(f.y) : "l"(v)); return f;
}
#define FMA2(d, a, b, c) \
    asm("fma.rn.f32x2 %0, %1, %2, %3;" : "=l"(d) : "l"(a), "l"(b), "l"(c))
#define MUL2(d, a, b) \
    asm("mul.rn.f32x2 %0, %1, %2;" : "=l"(d) : "l"(a), "l"(b))

// 128-row blocked SW128: atom = 8 rows x 64 bf16 (1024B), 16 atoms per 64-k block
__device__ __forceinline__ uint32_t a_sw_off(int m, int kk) {
    uint32_t off = ((uint32_t)(kk >> 6) * 16 + (m >> 3)) * 1024 + (m & 7) * 128 + (kk & 63) * 2;
    return off ^ ((off >> 3) & 0x70);
}

__device__ __forceinline__ void ldsm_x4(uint32_t* r, uint32_t addr) {
    asm volatile("ldmatrix.sync.aligned.m8n8.x4.shared.b16 {%0,%1,%2,%3}, [%4];"
        : "=r"(r[0]), "=r"(r[1]), "=r"(r[2]), "=r"(r[3]) : "r"(addr));
}
__device__ __forceinline__ void mma16816(float* c, const uint32_t* a, const uint32_t* b) {
    asm volatile(
        "mma.sync.aligned.m16n8k16.row.col.f32.bf16.bf16.f32 "
        "{%0,%1,%2,%3}, {%4,%5,%6,%7}, {%8,%9}, {%0,%1,%2,%3};"
        : "+f"(c[0]), "+f"(c[1]), "+f"(c[2]), "+f"(c[3])
        : "r"(a[0]), "r"(a[1]), "r"(a[2]), "r"(a[3]), "r"(b[0]), "r"(b[1]));
}

// ---------------- setup: q, bias, weight conversion (runs once per launch) ----------------
__global__ void setup_kernel(const float* __restrict__ emb,
                             const float* __restrict__ rpb,
                             const float* __restrict__ q_w,
                             const float* __restrict__ q_b,
                             const float* __restrict__ kv_w,
                             const float* __restrict__ proj_w) {
    int gid = blockIdx.x * blockDim.x + threadIdx.x;
    if (gid < 16384) {
        int e = gid & 31; int hn = gid >> 5;
        int h = hn >> 6, n = hn & 63;
        int d = h * 32 + e;
        const float* er = emb + n * 256;
        const float* wr = q_w + d * 256;
        float acc = q_b[d];
        #pragma unroll 4
        for (int c = 0; c < 256; c++) acc = fmaf(er[c], wr[c], acc);
        g_q[gid] = acc * SCALE;
    } else if (gid < 49152) {
        int t = gid - 16384;
        int h = t >> 12, m = (t >> 6) & 63, n = t & 63;
        int r0 = (n >> 3) - (m >> 3) + 7;
        int r1 = (n & 7) - (m & 7) + 7;
        g_biasT[t] = rpb[(r0 * 15 + r1) * 8 + h];
    } else if (gid < 311296) {
        // kv_w: extended-k layout (hi 0..255 | lo 256..511), stage = 32KB (128 cols x 128 k)
        int t = gid - 49152;             // n*512 + kk,  n < 512
        int n = t >> 9, kk = t & 511;
        float w = kv_w[n * 256 + (kk & 255)];
        __nv_bfloat16 hb = __float2bfloat16(w);
        __nv_bfloat16 val = (kk < 256) ? hb : __float2bfloat16(w - __bfloat162float(hb));
        int cp = n >> 7, nn = n & 127, j = kk >> 7, kkl = kk & 127;
        g_kvw_blk[(((uint32_t)(cp * 4 + j)) * 32768 + a_sw_off(nn, kkl)) >> 1] = val;
    } else {
        int t = gid - 311296;            // n*512 + kk,  n < 256
        int n = t >> 9, kk = t & 511;
        float w = proj_w[n * 256 + (kk & 255)];
        __nv_bfloat16 hb = __float2bfloat16(w);
        __nv_bfloat16 val = (kk < 256) ? hb : __float2bfloat16(w - __bfloat162float(hb));
        int cp = n >> 7, nn = n & 127, j = kk >> 7, kkl = kk & 127;
        g_pw_blk[(((uint32_t)(cp * 4 + j)) * 32768 + a_sw_off(nn, kkl)) >> 1] = val;
    }
}

// ---------------- mma.sync split-bf16 GEMM: C[128 x NC*64] = A[128x256] @ W^T + bias --------
// A in smem as bf16 hi|lo blocked SW128 (128KB). B streamed as 32KB stages
// (128 cols x 128 k) through a 3-slot cp.async ring, ONE barrier per stage.
template<int NC, bool GATHER>
__global__ void __launch_bounds__(512, 1)
gemm_kernel(const float* __restrict__ xsrc,
            const float* __restrict__ bias,
            float* __restrict__ coutp) {
    extern __shared__ char gsm[];
    const uint32_t sraw = smem_u32(gsm);
    const uint32_t sA = (sraw + 1023) & ~1023u;
    const uint32_t sB = sA + 131072;          // 3 x 32KB ring

    const int tid = threadIdx.x;
    const int wid = tid >> 5;
    const int lid = tid & 31;
    const int r0  = blockIdx.x * 128;
    const int NST = 2 * NC;                    // stages (4 per 128-col pair)

    const __nv_bfloat16* wblk = GATHER ? g_kvw_blk : g_pw_blk;
    float* C = GATHER ? g_KV : coutp;
    const int ldc = NC * 64;
    char* Ab = gsm + (sA - sraw);

    // issue stage j into ring slot j%3 (one commit group = 32KB; 64B/thread)
    auto issue_copy = [&](int j) {
        uint32_t dst = sB + (uint32_t)(j % 3) * 32768 + (uint32_t)tid * 64;
        const char* src = (const char*)wblk + (size_t)j * 32768 + (size_t)tid * 64;
        #pragma unroll
        for (int q = 0; q < 4; q++)
            asm volatile("cp.async.cg.shared.global [%0], [%1], 16;"
                         :: "r"(dst + q * 16), "l"(src + q * 16));
        asm volatile("cp.async.commit_group;" ::: "memory");
    };

    issue_copy(0); issue_copy(1);

    // ---- build A tile: fp32 -> bf16 hi (k 0..255) | lo (k 256..511), blocked SW128 ----
    #pragma unroll 4
    for (int it = 0; it < 32; it++) {
        int idx = tid + it * 512;            // 0..16383 (float2 units)
        int m = idx >> 7, p = idx & 127, c = p * 2;
        const float* rowp;
        if constexpr (GATHER) {
            int r = r0 + m;                  // r = bw*64 + n
            int b = r >> 14, i = (r >> 10) & 15, j = (r >> 6) & 15, n = r & 63;
            rowp = xsrc + ((size_t)b << 22) + ((size_t)i << 18)
                 + ((size_t)(n >> 3) << 15) + ((size_t)j << 11) + ((size_t)(n & 7) << 8);
        } else {
            rowp = g_O + (size_t)(r0 + m) * 256;
        }
        float2 f = *(const float2*)(rowp + c);
        __nv_bfloat162 h2 = __floats2bfloat162_rn(f.x, f.y);
        float lx = f.x - __bfloat162float(h2.x);
        float ly = f.y - __bfloat162float(h2.y);
        __nv_bfloat162 l2 = __floats2bfloat162_rn(lx, ly);
        *(uint32_t*)(Ab + a_sw_off(m, c))       = *(uint32_t*)&h2;
        *(uint32_t*)(Ab + a_sw_off(m, c + 256)) = *(uint32_t*)&l2;
    }

    // ---- per-warp / per-lane geometry ----
    const int m0w = (wid >> 2) * 32;          // warp tile 32 rows x 32 cols; grid 4x4
    const int n0w = (wid & 3) * 32;
    const int lrow = lid & 7;
    const int quad = lid >> 3;
    const int mA0 = m0w + lrow + (quad & 1) * 8;
    const int mA1 = mA0 + 16;
    const uint32_t aoff0 = ((uint32_t)(mA0 >> 3) << 10) + ((uint32_t)(mA0 & 7) << 7);
    const uint32_t aoff1 = ((uint32_t)(mA1 >> 3) << 10) + ((uint32_t)(mA1 & 7) << 7);
    const uint32_t xorA  = (uint32_t)(mA0 & 7) << 4;
    const int kqa = (quad >> 1) * 8;
    const int nB0 = n0w + lrow + (quad >> 1) * 8;      // B frag 0: cols n0w..+15
    const uint32_t boff0 = ((uint32_t)(nB0 >> 3) << 10) + ((uint32_t)(nB0 & 7) << 7);
    const uint32_t boff1 = boff0 + 2048;               // B frag 1: cols n0w+16..+31
    const uint32_t xorB  = (uint32_t)(nB0 & 7) << 4;
    const int kqb = (quad & 1) * 8;

    auto ldA = [&](int ak, uint32_t* d0, uint32_t* d1) {
        uint32_t kp = (((uint32_t)(ak >> 6)) << 14) | (((uint32_t)(ak & 63)) << 1);
        ldsm_x4(d0, sA + aoff0 + (kp ^ xorA));
        ldsm_x4(d1, sA + aoff1 + (kp ^ xorA));
    };
    auto ldB2 = [&](uint32_t slot, int kl, uint32_t* d0, uint32_t* d1) {
        uint32_t kp = (((uint32_t)(kl >> 6)) << 14) | (((uint32_t)(kl & 63)) << 1);
        ldsm_x4(d0, slot + boff0 + (kp ^ xorB));
        ldsm_x4(d1, slot + boff1 + (kp ^ xorB));
    };

    float c[2][4][4];
    #pragma unroll
    for (int mt = 0; mt < 2; mt++)
        #pragma unroll
        for (int nt = 0; nt < 4; nt++)
            #pragma unroll
            for (int i = 0; i < 4; i++) c[mt][nt][i] = 0.f;

    uint32_t fh0[2][4], fh1[2][4], fl0[2][4], fl1[2][4], fb0[2][4], fb1[2][4];

    auto mma8 = [&](uint32_t* a0, uint32_t* a1, uint32_t* b0, uint32_t* b1) {
        mma16816(c[0][0], a0, b0);
        mma16816(c[0][1], a0, b0 + 2);
        mma16816(c[0][2], a0, b1);
        mma16816(c[0][3], a0, b1 + 2);
        mma16816(c[1][0], a1, b0);
        mma16816(c[1][1], a1, b0 + 2);
        mma16816(c[1][2], a1, b1);
        mma16816(c[1][3], a1, b1 + 2);
    };

    // ---- stage loop: ONE sync per stage; issue i+2 into slot (i-1)%3 (safe post-sync) ----
    for (int i = 0; i < NST; i++) {
        asm volatile("cp.async.wait_group 1;" ::: "memory");
        __syncthreads();
        if (i + 2 < NST) issue_copy(i + 2);

        const uint32_t slot = sB + (uint32_t)(i % 3) * 32768;
        const int j = i & 3;

        if (j < 2) {
            const int kb = j * 128;
            ldA(kb + kqa,       fh0[0], fh1[0]);
            ldA(kb + 256 + kqa, fl0[0], fl1[0]);
            ldB2(slot, kqb, fb0[0], fb1[0]);
            #pragma unroll
            for (int st = 0; st < 8; st++) {
                const int cb = st & 1, nb = cb ^ 1;
                if (st < 7) {
                    ldA(kb + (st + 1) * 16 + kqa,       fh0[nb], fh1[nb]);
                    ldA(kb + 256 + (st + 1) * 16 + kqa, fl0[nb], fl1[nb]);
                    ldB2(slot, (st + 1) * 16 + kqb, fb0[nb], fb1[nb]);
                }
                mma8(fh0[cb], fh1[cb], fb0[cb], fb1[cb]);
                mma8(fl0[cb], fl1[cb], fb0[cb], fb1[cb]);
            }
        } else {
            const int kb = (j - 2) * 128;
            ldA(kb + kqa, fh0[0], fh1[0]);
            ldB2(slot, kqb, fb0[0], fb1[0]);
            #pragma unroll
            for (int st = 0; st < 8; st++) {
                const int cb = st & 1, nb = cb ^ 1;
                if (st < 7) {
                    ldA(kb + (st + 1) * 16 + kqa, fh0[nb], fh1[nb]);
                    ldB2(slot, (st + 1) * 16 + kqb, fb0[nb], fb1[nb]);
                }
                mma8(fh0[cb], fh1[cb], fb0[cb], fb1[cb]);
            }
        }

        if (j == 3) {
            // epilogue for 128-col pair cp = i>>2: bias add + direct STG.64
            const int colb = (i >> 2) * 128 + n0w;
            #pragma unroll
            for (int nt = 0; nt < 4; nt++) {
                const int col = colb + nt * 8 + 2 * (lid & 3);
                const float2 bv = *(const float2*)(bias + col);
                #pragma unroll
                for (int mt = 0; mt < 2; mt++) {
                    const int rlo = r0 + m0w + mt * 16 + (lid >> 2);
                    *(float2*)(C + (size_t)rlo * ldc + col) =
                        make_float2(c[mt][nt][0] + bv.x, c[mt][nt][1] + bv.y);
                    *(float2*)(C + (size_t)(rlo + 8) * ldc + col) =
                        make_float2(c[mt][nt][2] + bv.x, c[mt][nt][3] + bv.y);
                }
            }
            #pragma unroll
            for (int mt = 0; mt < 2; mt++)
                #pragma unroll
                for (int nt = 0; nt < 4; nt++)
                    #pragma unroll
                    for (int k2 = 0; k2 < 4; k2++) c[mt][nt][k2] = 0.f;
        }
    }
}

// ---------------- attention: 1 CTA per window, flash-chunked fp32 + packed FMA2 ----------------
#define KVP 264   // smem pitch (floats)

__global__ void __launch_bounds__(512, 1)
attn_kernel() {
    extern __shared__ float asm_[];
    float* s_k = asm_;                // 64 x KVP
    float* s_v = asm_ + 64 * KVP;     // 64 x KVP
    const int tid = threadIdx.x;
    const int bw  = blockIdx.x;
    const int h = tid >> 6, n = tid & 63;

    const float* kvbase = g_KV + (size_t)bw * 64 * 512;
    #pragma unroll
    for (int t = 0; t < 16; t++) {
        int idx = tid + t * 512;          // 8192 float4
        int m = idx >> 7, c4 = idx & 127;
        float4 v = *(const float4*)(kvbase + (size_t)m * 512 + c4 * 4);
        if (c4 < 64) *(float4*)(s_k + m * KVP + c4 * 4) = v;
        else         *(float4*)(s_v + m * KVP + (c4 - 64) * 4) = v;
    }

    ull qr[16];
    const float4* qp = (const float4*)(g_q + tid * 32);
    #pragma unroll
    for (int i = 0; i < 8; i++) {
        float4 q4 = qp[i];
        asm("mov.b64 %0, {%1, %2};" : "=l"(qr[2*i])   : "f"(q4.x), "f"(q4.y));
        asm("mov.b64 %0, {%1, %2};" : "=l"(qr[2*i+1]) : "f"(q4.z), "f"(q4.w));
    }
    __syncthreads();

    const char* kb = (const char*)(s_k + h * 32);
    const char* vb = (const char*)(s_v + h * 32);
    const float* bp = g_biasT + h * 4096 + n;

    float m_run = -1e30f, lsum = 0.f;
    ull o[16];
    #pragma unroll
    for (int i = 0; i < 16; i++) o[i] = 0ULL;

    // ---- online-softmax over 4 chunks of 16 keys ----
    #pragma unroll 1
    for (int cnk = 0; cnk < 4; cnk++) {
        float sc[16];
        #pragma unroll
        for (int mm = 0; mm < 16; mm++) {
            const int m = cnk * 16 + mm;
            ull a0 = 0, a1 = 0;
            const char* kr = kb + m * (KVP * 4);
            #pragma unroll
            for (int i = 0; i < 8; i++) {
                ulonglong2 kv2 = *(const ulonglong2*)(kr + i * 16);  // broadcast LDS128
                FMA2(a0, qr[2*i],   kv2.x, a0);
                FMA2(a1, qr[2*i+1], kv2.y, a1);
            }
            float2 f0 = up2(a0), f1 = up2(a1);
            sc[mm] = (f0.x + f0.y) + (f1.x + f1.y) + bp[m * 64];
        }
        float cm = sc[0];
        #pragma unroll
        for (int mm = 1; mm < 16; mm++) cm = fmaxf(cm, sc[mm]);
        const float nm = fmaxf(m_run, cm);
        const float scl = __expf(m_run - nm);
        m_run = nm;
        lsum *= scl;
        const ull s2 = pk2(scl);
        #pragma unroll
        for (int i = 0; i < 16; i++) MUL2(o[i], o[i], s2);

        #pragma unroll
        for (int mm = 0; mm < 16; mm++) {
            const int m = cnk * 16 + mm;
            const float p = __expf(sc[mm] - nm);
            lsum += p;
            const ull pv = pk2(p);
            const char* vr = vb + m * (KVP * 4);
            #pragma unroll
            for (int i = 0; i < 8; i++) {
                ulonglong2 vv = *(const ulonglong2*)(vr + i * 16);
                FMA2(o[2*i],   pv, vv.x, o[2*i]);
                FMA2(o[2*i+1], pv, vv.y, o[2*i+1]);
            }
        }
    }

    const ull iv = pk2(1.f / lsum);
    #pragma unroll
    for (int i = 0; i < 16; i++) MUL2(o[i], o[i], iv);

    __syncthreads();    // everyone done reading s_k -> reuse as output stage

    float* so = s_k;
    #pragma unroll
    for (int i = 0; i < 16; i += 2) {
        float2 fa = up2(o[i]), fb2 = up2(o[i+1]);
        *(float4*)(so + n * KVP + h * 32 + i * 2) = make_float4(fa.x, fa.y, fb2.x, fb2.y);
    }
    __syncthreads();

    float* ob = g_O + (size_t)bw * 64 * 256;
    #pragma unroll
    for (int t = 0; t < 8; t++) {
        int idx = tid + t * 512;
        int m = idx >> 6, c4 = idx & 63;
        *(float4*)(ob + m * 256 + c4 * 4) = *(const float4*)(so + m * KVP + c4 * 4);
    }
}

// ---------------- launcher ----------------
extern "C" void kernel_launch(void* const* d_in, const int* in_sizes, int n_in,
                              void* d_out, int out_size) {
    const float* x      = (const float*)d_in[0];
    const float* emb    = (const float*)d_in[1];
    const float* rpb    = (const float*)d_in[2];
    const float* q_w    = (const float*)d_in[3];
    const float* q_b    = (const float*)d_in[4];
    const float* kv_w   = (const float*)d_in[5];
    const float* kv_b   = (const float*)d_in[6];
    const float* proj_w = (const float*)d_in[7];
    const float* proj_b = (const float*)d_in[8];
    float* out = (float*)d_out;
    (void)in_sizes; (void)n_in; (void)out_size;

    const int GSM = 1024 + 131072 + 98304;   // 230400: pad + A + 3x32KB ring
    const int ASM = 2 * 64 * KVP * 4;        // 135168

    cudaFuncSetAttribute(gemm_kernel<8, true>,
                         cudaFuncAttributeMaxDynamicSharedMemorySize, GSM);
    cudaFuncSetAttribute(gemm_kernel<4, false>,
                         cudaFuncAttributeMaxDynamicSharedMemorySize, GSM);
    cudaFuncSetAttribute(attn_kernel,
                         cudaFuncAttributeMaxDynamicSharedMemorySize, ASM);

    setup_kernel<<<864, 512>>>(emb, rpb, q_w, q_b, kv_w, proj_w);
    gemm_kernel<8, true ><<<1024, 512, GSM>>>(x, kv_b, nullptr);
    attn_kernel<<<2048, 512, ASM>>>();
    gemm_kernel<4, false><<<1024, 512, GSM>>>(nullptr, proj_b, out);
}

// round 10
// speedup vs baseline: 3.4991x; 1.2229x over previous
#include <cuda_runtime.h>
#include <cuda_bf16.h>
#include <cstdint>

typedef unsigned long long ull;

#define SCALE 0.17677669529663687f   // 32^-0.5

// ---------------- device scratch ----------------
// g_KV: per window (2048) 131072 B: K-hi 32KB | K-lo 32KB | V-hi 32KB | V-lo 32KB
// each 32KB block: [64 rows m][256 dims d] bf16, blocked SW128 (atom 8x64, 8 atoms per d-block)
__device__ __align__(128) uint8_t g_KV[2048ULL * 131072];
__device__ __align__(128) float g_O [131072ULL * 256];   // [gtok][256]
__device__ __align__(128) float g_q [8 * 64 * 32];       // [(h*64+n)*32+e], * SCALE
__device__ __align__(128) float g_biasF[32768];          // C-frag-ordered bias
__device__ __align__(128) uint4 g_qfrag[128 * 32];       // A-frag-ordered q (hi/lo), 128 slots
// B stages: 32KB each = 128 cols x 128 k (SW128 atoms). kv: 16 stages, proj: 8 stages.
__device__ __align__(128) __nv_bfloat16 g_kvw_blk[262144];
__device__ __align__(128) __nv_bfloat16 g_pw_blk [131072];

// ---------------- helpers ----------------
__device__ __forceinline__ uint32_t smem_u32(const void* p) {
    uint32_t a;
    asm("{ .reg .u64 t; cvta.to.shared.u64 t, %1; cvt.u32.u64 %0, t; }" : "=r"(a) : "l"(p));
    return a;
}

// 128-row blocked SW128 (GEMM A/B stages)
__device__ __forceinline__ uint32_t a_sw_off(int m, int kk) {
    uint32_t off = ((uint32_t)(kk >> 6) * 16 + (m >> 3)) * 1024 + (m & 7) * 128 + (kk & 63) * 2;
    return off ^ ((off >> 3) & 0x70);
}
// 64-row blocked SW128 (per-window K/V blocks)
__device__ __forceinline__ uint32_t kv_off(int m, int d) {
    uint32_t off = ((uint32_t)(d >> 6) * 8 + (m >> 3)) * 1024 + (m & 7) * 128 + (d & 63) * 2;
    return off ^ ((off >> 3) & 0x70);
}

// split fp32 pair -> bf16x2 hi (returned) + bf16x2 lo
__device__ __forceinline__ uint32_t split2(float a, float b, uint32_t& lo) {
    __nv_bfloat162 h = __floats2bfloat162_rn(a, b);
    float ra = a - __bfloat162float(h.x);
    float rb = b - __bfloat162float(h.y);
    __nv_bfloat162 l = __floats2bfloat162_rn(ra, rb);
    lo = *(uint32_t*)&l;
    return *(uint32_t*)&h;
}

__device__ __forceinline__ void ldsm_x4(uint32_t* r, uint32_t addr) {
    asm volatile("ldmatrix.sync.aligned.m8n8.x4.shared.b16 {%0,%1,%2,%3}, [%4];"
        : "=r"(r[0]), "=r"(r[1]), "=r"(r[2]), "=r"(r[3]) : "r"(addr));
}
__device__ __forceinline__ void ldsm_x4_t(uint32_t* r, uint32_t addr) {
    asm volatile("ldmatrix.sync.aligned.m8n8.x4.trans.shared.b16 {%0,%1,%2,%3}, [%4];"
        : "=r"(r[0]), "=r"(r[1]), "=r"(r[2]), "=r"(r[3]) : "r"(addr));
}
__device__ __forceinline__ void mma16816(float* c, const uint32_t* a, const uint32_t* b) {
    asm volatile(
        "mma.sync.aligned.m16n8k16.row.col.f32.bf16.bf16.f32 "
        "{%0,%1,%2,%3}, {%4,%5,%6,%7}, {%8,%9}, {%0,%1,%2,%3};"
        : "+f"(c[0]), "+f"(c[1]), "+f"(c[2]), "+f"(c[3])
        : "r"(a[0]), "r"(a[1]), "r"(a[2]), "r"(a[3]), "r"(b[0]), "r"(b[1]));
}

// ---------------- setup 1: q, bias(frag order), weight blocks ----------------
__global__ void setup_kernel(const float* __restrict__ emb,
                             const float* __restrict__ rpb,
                             const float* __restrict__ q_w,
                             const float* __restrict__ q_b,
                             const float* __restrict__ kv_w,
                             const float* __restrict__ proj_w) {
    int gid = blockIdx.x * blockDim.x + threadIdx.x;
    if (gid < 16384) {
        int e = gid & 31; int hn = gid >> 5;
        int h = hn >> 6, n = hn & 63;
        int d = h * 32 + e;
        const float* er = emb + n * 256;
        const float* wr = q_w + d * 256;
        float acc = q_b[d];
        #pragma unroll 4
        for (int c = 0; c < 256; c++) acc = fmaf(er[c], wr[c], acc);
        g_q[gid] = acc * SCALE;
    } else if (gid < 49152) {
        // bias in C-fragment order: t = ((((h*2+s)*2+mt)*8+nt)*32+lane)*4 + r
        int t = gid - 16384;
        int r = t & 3, lane = (t >> 2) & 31, nt = (t >> 7) & 7;
        int mt = (t >> 10) & 1, s = (t >> 11) & 1, h = t >> 12;
        int n = s * 32 + mt * 16 + (lane >> 2) + ((r >> 1) << 3);
        int m = nt * 8 + ((lane & 3) << 1) + (r & 1);
        int r0 = (n >> 3) - (m >> 3) + 7;
        int r1 = (n & 7) - (m & 7) + 7;
        g_biasF[t] = rpb[(r0 * 15 + r1) * 8 + h];
    } else if (gid < 311296) {
        int t = gid - 49152;             // n*512 + kk,  n < 512
        int n = t >> 9, kk = t & 511;
        float w = kv_w[n * 256 + (kk & 255)];
        __nv_bfloat16 hb = __float2bfloat16(w);
        __nv_bfloat16 val = (kk < 256) ? hb : __float2bfloat16(w - __bfloat162float(hb));
        int cp = n >> 7, nn = n & 127, j = kk >> 7, kkl = kk & 127;
        g_kvw_blk[(((uint32_t)(cp * 4 + j)) * 32768 + a_sw_off(nn, kkl)) >> 1] = val;
    } else {
        int t = gid - 311296;            // n*512 + kk,  n < 256
        int n = t >> 9, kk = t & 511;
        float w = proj_w[n * 256 + (kk & 255)];
        __nv_bfloat16 hb = __float2bfloat16(w);
        __nv_bfloat16 val = (kk < 256) ? hb : __float2bfloat16(w - __bfloat162float(hb));
        int cp = n >> 7, nn = n & 127, j = kk >> 7, kkl = kk & 127;
        g_pw_blk[(((uint32_t)(cp * 4 + j)) * 32768 + a_sw_off(nn, kkl)) >> 1] = val;
    }
}

// ---------------- setup 2: q A-fragments (128 slots: h,s,mt,kt,prec) ----------------
__global__ void setup2_kernel() {
    int t = blockIdx.x * blockDim.x + threadIdx.x;   // 4096
    int lane = t & 31, slot = t >> 5;                // slot 0..127
    int prec = slot & 1, kt = (slot >> 1) & 1, mt = (slot >> 2) & 1;
    int s = (slot >> 3) & 1, h = slot >> 4;          // h 0..7
    uint32_t rr[4];
    #pragma unroll
    for (int r = 0; r < 4; r++) {
        int n = s * 32 + mt * 16 + (lane >> 2) + ((r & 1) << 3);
        int k = kt * 16 + ((lane & 3) << 1) + ((r >> 1) << 3);
        float q0 = g_q[(h * 64 + n) * 32 + k];
        float q1 = g_q[(h * 64 + n) * 32 + k + 1];
        uint32_t lo;
        uint32_t hi = split2(q0, q1, lo);
        rr[r] = prec ? lo : hi;
    }
    g_qfrag[slot * 32 + lane] = make_uint4(rr[0], rr[1], rr[2], rr[3]);
}

// ---------------- kv epilogue store: fp32 pair -> hi/lo bf16 into window blocks ----------------
__device__ __forceinline__ void store2_kv(int r, int col, float a, float b) {
    const int w = r >> 6, m = r & 63;
    const int isV = col >= 256;
    const int d = col - (isV ? 256 : 0);
    uint8_t* base = g_KV + (size_t)w * 131072 + (isV ? 65536 : 0);
    const uint32_t off = kv_off(m, d);
    uint32_t lo;
    uint32_t hi = split2(a, b, lo);
    *(uint32_t*)(base + off) = hi;
    *(uint32_t*)(base + off + 32768) = lo;
}

// ---------------- mma.sync split-bf16 GEMM ----------------
template<int NC, bool GATHER>
__global__ void __launch_bounds__(512, 1)
gemm_kernel(const float* __restrict__ xsrc,
            const float* __restrict__ bias,
            float* __restrict__ coutp) {
    extern __shared__ char gsm[];
    const uint32_t sraw = smem_u32(gsm);
    const uint32_t sA = (sraw + 1023) & ~1023u;
    const uint32_t sB = sA + 131072;          // 3 x 32KB ring

    const int tid = threadIdx.x;
    const int wid = tid >> 5;
    const int lid = tid & 31;
    const int r0  = blockIdx.x * 128;
    const int NST = 2 * NC;

    const __nv_bfloat16* wblk = GATHER ? g_kvw_blk : g_pw_blk;
    const int ldc = NC * 64;
    char* Ab = gsm + (sA - sraw);

    auto issue_copy = [&](int j) {
        uint32_t dst = sB + (uint32_t)(j % 3) * 32768 + (uint32_t)tid * 64;
        const char* src = (const char*)wblk + (size_t)j * 32768 + (size_t)tid * 64;
        #pragma unroll
        for (int q = 0; q < 4; q++)
            asm volatile("cp.async.cg.shared.global [%0], [%1], 16;"
                         :: "r"(dst + q * 16), "l"(src + q * 16));
        asm volatile("cp.async.commit_group;" ::: "memory");
    };

    issue_copy(0); issue_copy(1);

    // ---- build A tile: fp32 -> bf16 hi|lo, blocked SW128 ----
    #pragma unroll 4
    for (int it = 0; it < 32; it++) {
        int idx = tid + it * 512;
        int m = idx >> 7, p = idx & 127, c = p * 2;
        const float* rowp;
        if constexpr (GATHER) {
            int r = r0 + m;
            int b = r >> 14, i = (r >> 10) & 15, j = (r >> 6) & 15, n = r & 63;
            rowp = xsrc + ((size_t)b << 22) + ((size_t)i << 18)
                 + ((size_t)(n >> 3) << 15) + ((size_t)j << 11) + ((size_t)(n & 7) << 8);
        } else {
            rowp = g_O + (size_t)(r0 + m) * 256;
        }
        float2 f = *(const float2*)(rowp + c);
        uint32_t lo;
        uint32_t hi = split2(f.x, f.y, lo);
        *(uint32_t*)(Ab + a_sw_off(m, c))       = hi;
        *(uint32_t*)(Ab + a_sw_off(m, c + 256)) = lo;
    }

    const int m0w = (wid >> 2) * 32;
    const int n0w = (wid & 3) * 32;
    const int lrow = lid & 7;
    const int quad = lid >> 3;
    const int mA0 = m0w + lrow + (quad & 1) * 8;
    const int mA1 = mA0 + 16;
    const uint32_t aoff0 = ((uint32_t)(mA0 >> 3) << 10) + ((uint32_t)(mA0 & 7) << 7);
    const uint32_t aoff1 = ((uint32_t)(mA1 >> 3) << 10) + ((uint32_t)(mA1 & 7) << 7);
    const uint32_t xorA  = (uint32_t)(mA0 & 7) << 4;
    const int kqa = (quad >> 1) * 8;
    const int nB0 = n0w + lrow + (quad >> 1) * 8;
    const uint32_t boff0 = ((uint32_t)(nB0 >> 3) << 10) + ((uint32_t)(nB0 & 7) << 7);
    const uint32_t boff1 = boff0 + 2048;
    const uint32_t xorB  = (uint32_t)(nB0 & 7) << 4;
    const int kqb = (quad & 1) * 8;

    auto ldA = [&](int ak, uint32_t* d0, uint32_t* d1) {
        uint32_t kp = (((uint32_t)(ak >> 6)) << 14) | (((uint32_t)(ak & 63)) << 1);
        ldsm_x4(d0, sA + aoff0 + (kp ^ xorA));
        ldsm_x4(d1, sA + aoff1 + (kp ^ xorA));
    };
    auto ldB2 = [&](uint32_t slot, int kl, uint32_t* d0, uint32_t* d1) {
        uint32_t kp = (((uint32_t)(kl >> 6)) << 14) | (((uint32_t)(kl & 63)) << 1);
        ldsm_x4(d0, slot + boff0 + (kp ^ xorB));
        ldsm_x4(d1, slot + boff1 + (kp ^ xorB));
    };

    float c[2][4][4];
    #pragma unroll
    for (int mt = 0; mt < 2; mt++)
        #pragma unroll
        for (int nt = 0; nt < 4; nt++)
            #pragma unroll
            for (int i = 0; i < 4; i++) c[mt][nt][i] = 0.f;

    uint32_t fh0[2][4], fh1[2][4], fl0[2][4], fl1[2][4], fb0[2][4], fb1[2][4];

    auto mma8 = [&](uint32_t* a0, uint32_t* a1, uint32_t* b0, uint32_t* b1) {
        mma16816(c[0][0], a0, b0);
        mma16816(c[0][1], a0, b0 + 2);
        mma16816(c[0][2], a0, b1);
        mma16816(c[0][3], a0, b1 + 2);
        mma16816(c[1][0], a1, b0);
        mma16816(c[1][1], a1, b0 + 2);
        mma16816(c[1][2], a1, b1);
        mma16816(c[1][3], a1, b1 + 2);
    };

    for (int i = 0; i < NST; i++) {
        asm volatile("cp.async.wait_group 1;" ::: "memory");
        __syncthreads();
        if (i + 2 < NST) issue_copy(i + 2);

        const uint32_t slot = sB + (uint32_t)(i % 3) * 32768;
        const int j = i & 3;

        if (j < 2) {
            const int kb = j * 128;
            ldA(kb + kqa,       fh0[0], fh1[0]);
            ldA(kb + 256 + kqa, fl0[0], fl1[0]);
            ldB2(slot, kqb, fb0[0], fb1[0]);
            #pragma unroll
            for (int st = 0; st < 8; st++) {
                const int cb = st & 1, nb = cb ^ 1;
                if (st < 7) {
                    ldA(kb + (st + 1) * 16 + kqa,       fh0[nb], fh1[nb]);
                    ldA(kb + 256 + (st + 1) * 16 + kqa, fl0[nb], fl1[nb]);
                    ldB2(slot, (st + 1) * 16 + kqb, fb0[nb], fb1[nb]);
                }
                mma8(fh0[cb], fh1[cb], fb0[cb], fb1[cb]);
                mma8(fl0[cb], fl1[cb], fb0[cb], fb1[cb]);
            }
        } else {
            const int kb = (j - 2) * 128;
            ldA(kb + kqa, fh0[0], fh1[0]);
            ldB2(slot, kqb, fb0[0], fb1[0]);
            #pragma unroll
            for (int st = 0; st < 8; st++) {
                const int cb = st & 1, nb = cb ^ 1;
                if (st < 7) {
                    ldA(kb + (st + 1) * 16 + kqa, fh0[nb], fh1[nb]);
                    ldB2(slot, (st + 1) * 16 + kqb, fb0[nb], fb1[nb]);
                }
                mma8(fh0[cb], fh1[cb], fb0[cb], fb1[cb]);
            }
        }

        if (j == 3) {
            const int colb = (i >> 2) * 128 + n0w;
            #pragma unroll
            for (int nt = 0; nt < 4; nt++) {
                const int col = colb + nt * 8 + 2 * (lid & 3);
                const float2 bv = *(const float2*)(bias + col);
                #pragma unroll
                for (int mt = 0; mt < 2; mt++) {
                    const int rlo = r0 + m0w + mt * 16 + (lid >> 2);
                    if constexpr (GATHER) {
                        store2_kv(rlo,     col, c[mt][nt][0] + bv.x, c[mt][nt][1] + bv.y);
                        store2_kv(rlo + 8, col, c[mt][nt][2] + bv.x, c[mt][nt][3] + bv.y);
                    } else {
                        *(float2*)(coutp + (size_t)rlo * ldc + col) =
                            make_float2(c[mt][nt][0] + bv.x, c[mt][nt][1] + bv.y);
                        *(float2*)(coutp + (size_t)(rlo + 8) * ldc + col) =
                            make_float2(c[mt][nt][2] + bv.x, c[mt][nt][3] + bv.y);
                    }
                }
            }
            #pragma unroll
            for (int mt = 0; mt < 2; mt++)
                #pragma unroll
                for (int nt = 0; nt < 4; nt++)
                    #pragma unroll
                    for (int k2 = 0; k2 < 4; k2++) c[mt][nt][k2] = 0.f;
        }
    }
}

// ---------------- tensor-core attention: 1 CTA per window, 2 warps per head --------------
__global__ void __launch_bounds__(512, 1)
attn_kernel() {
    extern __shared__ char asmem[];
    const uint32_t sraw = smem_u32(asmem);
    const uint32_t sKV = (sraw + 1023) & ~1023u;
    const int tid = threadIdx.x;
    const uint8_t* src = g_KV + (size_t)blockIdx.x * 131072;

    // K blocks (64KB) first, then V blocks (64KB): two commit groups
    #pragma unroll
    for (int t = 0; t < 8; t++) {
        uint32_t o = (uint32_t)(tid + t * 512) * 16;
        asm volatile("cp.async.cg.shared.global [%0], [%1], 16;"
                     :: "r"(sKV + o), "l"(src + o));
    }
    asm volatile("cp.async.commit_group;" ::: "memory");
    #pragma unroll
    for (int t = 8; t < 16; t++) {
        uint32_t o = (uint32_t)(tid + t * 512) * 16;
        asm volatile("cp.async.cg.shared.global [%0], [%1], 16;"
                     :: "r"(sKV + o), "l"(src + o));
    }
    asm volatile("cp.async.commit_group;" ::: "memory");

    const int wid = tid >> 5, lid = tid & 31;
    const int h = wid >> 1, s = wid & 1;
    const int lrow = lid & 7, grp = lid >> 3;

    // bias -> accumulators (C-frag order), q fragments (A-frag order)
    float sa[2][8][4];
    const float4* bf = (const float4*)g_biasF;
    #pragma unroll
    for (int mt = 0; mt < 2; mt++)
        #pragma unroll
        for (int nt = 0; nt < 8; nt++) {
            float4 b = bf[((((h * 2 + s) * 2 + mt) * 8) + nt) * 32 + lid];
            sa[mt][nt][0] = b.x; sa[mt][nt][1] = b.y;
            sa[mt][nt][2] = b.z; sa[mt][nt][3] = b.w;
        }
    uint4 qh[2][2], ql[2][2];
    #pragma unroll
    for (int mt = 0; mt < 2; mt++)
        #pragma unroll
        for (int kt = 0; kt < 2; kt++) {
            int sb = (((h * 2 + s) * 2 + mt) * 2 + kt) * 2;
            qh[mt][kt] = g_qfrag[sb * 32 + lid];
            ql[mt][kt] = g_qfrag[(sb + 1) * 32 + lid];
        }

    asm volatile("cp.async.wait_group 1;" ::: "memory");
    __syncthreads();

    // ---- S = Qh@Kh + Ql@Kh + Qh@Kl  (bias already in accumulators) ----
    #pragma unroll
    for (int kt = 0; kt < 2; kt++) {
        const int dcol = h * 32 + kt * 16 + (grp & 1) * 8;
        #pragma unroll
        for (int ntp = 0; ntp < 4; ntp++) {
            const int mrow = ntp * 16 + lrow + (grp >> 1) * 8;
            uint32_t a = sKV + kv_off(mrow, dcol);
            uint32_t bh[4], bl[4];
            ldsm_x4(bh, a);
            ldsm_x4(bl, a + 32768);
            mma16816(sa[0][2*ntp],   (const uint32_t*)&qh[0][kt], bh);
            mma16816(sa[0][2*ntp+1], (const uint32_t*)&qh[0][kt], bh + 2);
            mma16816(sa[1][2*ntp],   (const uint32_t*)&qh[1][kt], bh);
            mma16816(sa[1][2*ntp+1], (const uint32_t*)&qh[1][kt], bh + 2);
            mma16816(sa[0][2*ntp],   (const uint32_t*)&ql[0][kt], bh);
            mma16816(sa[0][2*ntp+1], (const uint32_t*)&ql[0][kt], bh + 2);
            mma16816(sa[1][2*ntp],   (const uint32_t*)&ql[1][kt], bh);
            mma16816(sa[1][2*ntp+1], (const uint32_t*)&ql[1][kt], bh + 2);
            mma16816(sa[0][2*ntp],   (const uint32_t*)&qh[0][kt], bl);
            mma16816(sa[0][2*ntp+1], (const uint32_t*)&qh[0][kt], bl + 2);
            mma16816(sa[1][2*ntp],   (const uint32_t*)&qh[1][kt], bl);
            mma16816(sa[1][2*ntp+1], (const uint32_t*)&qh[1][kt], bl + 2);
        }
    }

    // ---- softmax (rows split over 4 lanes; 2 bfly shuffles) ----
    float rinv[2][2];
    #pragma unroll
    for (int mt = 0; mt < 2; mt++)
        #pragma unroll
        for (int rh = 0; rh < 2; rh++) {
            float mx = -1e30f;
            #pragma unroll
            for (int nt = 0; nt < 8; nt++)
                mx = fmaxf(mx, fmaxf(sa[mt][nt][rh*2], sa[mt][nt][rh*2+1]));
            mx = fmaxf(mx, __shfl_xor_sync(0xffffffffu, mx, 1));
            mx = fmaxf(mx, __shfl_xor_sync(0xffffffffu, mx, 2));
            float ls = 0.f;
            #pragma unroll
            for (int nt = 0; nt < 8; nt++) {
                float p0 = __expf(sa[mt][nt][rh*2]   - mx);
                float p1 = __expf(sa[mt][nt][rh*2+1] - mx);
                sa[mt][nt][rh*2] = p0; sa[mt][nt][rh*2+1] = p1;
                ls += p0 + p1;
            }
            ls += __shfl_xor_sync(0xffffffffu, ls, 1);
            ls += __shfl_xor_sync(0xffffffffu, ls, 2);
            rinv[mt][rh] = 1.f / ls;
        }

    asm volatile("cp.async.wait_group 0;" ::: "memory");
    __syncthreads();

    // ---- O = Ph@Vh + Pl@Vh + Ph@Vl  (P via C->A fragment identity) ----
    float oa[2][4][4];
    #pragma unroll
    for (int mt = 0; mt < 2; mt++)
        #pragma unroll
        for (int nt = 0; nt < 4; nt++)
            #pragma unroll
            for (int i = 0; i < 4; i++) oa[mt][nt][i] = 0.f;

    #pragma unroll
    for (int j = 0; j < 4; j++) {
        uint32_t Ph[2][4], Pl[2][4];
        #pragma unroll
        for (int mt = 0; mt < 2; mt++) {
            Ph[mt][0] = split2(sa[mt][2*j][0],   sa[mt][2*j][1],   Pl[mt][0]);
            Ph[mt][1] = split2(sa[mt][2*j][2],   sa[mt][2*j][3],   Pl[mt][1]);
            Ph[mt][2] = split2(sa[mt][2*j+1][0], sa[mt][2*j+1][1], Pl[mt][2]);
            Ph[mt][3] = split2(sa[mt][2*j+1][2], sa[mt][2*j+1][3], Pl[mt][3]);
        }
        #pragma unroll
        for (int ep = 0; ep < 2; ep++) {
            const int mrow = j * 16 + lrow + (grp & 1) * 8;
            const int ecol = h * 32 + ep * 16 + (grp >> 1) * 8;
            uint32_t va = sKV + 65536 + kv_off(mrow, ecol);
            uint32_t vh[4], vl[4];
            ldsm_x4_t(vh, va);
            ldsm_x4_t(vl, va + 32768);
            #pragma unroll
            for (int mt = 0; mt < 2; mt++) {
                mma16816(oa[mt][2*ep],   Ph[mt], vh);
                mma16816(oa[mt][2*ep+1], Ph[mt], vh + 2);
                mma16816(oa[mt][2*ep],   Pl[mt], vh);
                mma16816(oa[mt][2*ep+1], Pl[mt], vh + 2);
                mma16816(oa[mt][2*ep],   Ph[mt], vl);
                mma16816(oa[mt][2*ep+1], Ph[mt], vl + 2);
            }
        }
    }

    // ---- scale by 1/l, write O fp32 ----
    const int q2 = (lid & 3) * 2, r4 = lid >> 2;
    #pragma unroll
    for (int mt = 0; mt < 2; mt++)
        #pragma unroll
        for (int rh = 0; rh < 2; rh++) {
            const int n = s * 32 + mt * 16 + r4 + rh * 8;
            float* orow = g_O + (size_t)(blockIdx.x * 64 + n) * 256 + h * 32;
            const float sc = rinv[mt][rh];
            #pragma unroll
            for (int nt = 0; nt < 4; nt++)
                *(float2*)(orow + nt * 8 + q2) =
                    make_float2(oa[mt][nt][rh*2] * sc, oa[mt][nt][rh*2+1] * sc);
        }
}

// ---------------- launcher ----------------
extern "C" void kernel_launch(void* const* d_in, const int* in_sizes, int n_in,
                              void* d_out, int out_size) {
    const float* x      = (const float*)d_in[0];
    const float* emb    = (const float*)d_in[1];
    const float* rpb    = (const float*)d_in[2];
    const float* q_w    = (const float*)d_in[3];
    const float* q_b    = (const float*)d_in[4];
    const float* kv_w   = (const float*)d_in[5];
    const float* kv_b   = (const float*)d_in[6];
    const float* proj_w = (const float*)d_in[7];
    const float* proj_b = (const float*)d_in[8];
    float* out = (float*)d_out;
    (void)in_sizes; (void)n_in; (void)out_size;

    const int GSM = 1024 + 131072 + 98304;   // 230400
    const int ASM = 1024 + 131072;           // 132096

    cudaFuncSetAttribute(gemm_kernel<8, true>,
                         cudaFuncAttributeMaxDynamicSharedMemorySize, GSM);
    cudaFuncSetAttribute(gemm_kernel<4, false>,
                         cudaFuncAttributeMaxDynamicSharedMemorySize, GSM);
    cudaFuncSetAttribute(attn_kernel,
                         cudaFuncAttributeMaxDynamicSharedMemorySize, ASM);

    setup_kernel<<<864, 512>>>(emb, rpb, q_w, q_b, kv_w, proj_w);
    setup2_kernel<<<8, 512>>>();
    gemm_kernel<8, true ><<<1024, 512, GSM>>>(x, kv_b, nullptr);
    attn_kernel<<<2048, 512, ASM>>>();
    gemm_kernel<4, false><<<1024, 512, GSM>>>(nullptr, proj_b, out);
}

// round 11
// speedup vs baseline: 4.4643x; 1.2759x over previous
#include <cuda_runtime.h>
#include <cuda_bf16.h>
#include <cuda_fp16.h>
#include <cstdint>

typedef unsigned long long ull;

#define SCALE 0.17677669529663687f   // 32^-0.5

// ---------------- device scratch ----------------
// g_KV: per window (2048) 131072 B: K-hi 32KB | K-lo 32KB | V-hi 32KB | V-lo 32KB (fp16)
// each 32KB block: [64 rows m][256 dims d], blocked SW128 (atom 8x64, 8 atoms per d-block)
__device__ __align__(128) uint8_t g_KV[2048ULL * 131072];
__device__ __align__(128) float g_O [131072ULL * 256];   // [gtok][256]
__device__ __align__(128) float g_q [8 * 64 * 32];       // [(h*64+n)*32+e], * SCALE
__device__ __align__(128) float g_biasF[32768];          // C-frag-ordered bias
__device__ __align__(128) uint4 g_qfrag[128 * 32];       // A-frag-ordered q (hi/lo fp16)
// Weight stages: fp16 HI ONLY. 32KB stage = 128 cols x 128 k. kv: 8 stages, proj: 4.
__device__ __align__(128) __half g_kvw_blk[131072];
__device__ __align__(128) __half g_pw_blk [65536];

// ---------------- helpers ----------------
__device__ __forceinline__ uint32_t smem_u32(const void* p) {
    uint32_t a;
    asm("{ .reg .u64 t; cvta.to.shared.u64 t, %1; cvt.u32.u64 %0, t; }" : "=r"(a) : "l"(p));
    return a;
}

// 128-row blocked SW128 (GEMM A tile + weight stages)
__device__ __forceinline__ uint32_t a_sw_off(int m, int kk) {
    uint32_t off = ((uint32_t)(kk >> 6) * 16 + (m >> 3)) * 1024 + (m & 7) * 128 + (kk & 63) * 2;
    return off ^ ((off >> 3) & 0x70);
}
// 64-row blocked SW128 (per-window K/V blocks)
__device__ __forceinline__ uint32_t kv_off(int m, int d) {
    uint32_t off = ((uint32_t)(d >> 6) * 8 + (m >> 3)) * 1024 + (m & 7) * 128 + (d & 63) * 2;
    return off ^ ((off >> 3) & 0x70);
}

// split fp32 pair -> fp16x2 hi (returned) + fp16x2 lo
__device__ __forceinline__ uint32_t split2h(float a, float b, uint32_t& lo) {
    __half2 h = __floats2half2_rn(a, b);
    float2 hf = __half22float2(h);
    __half2 l = __floats2half2_rn(a - hf.x, b - hf.y);
    lo = *(uint32_t*)&l;
    return *(uint32_t*)&h;
}

__device__ __forceinline__ void ldsm_x4(uint32_t* r, uint32_t addr) {
    asm volatile("ldmatrix.sync.aligned.m8n8.x4.shared.b16 {%0,%1,%2,%3}, [%4];"
        : "=r"(r[0]), "=r"(r[1]), "=r"(r[2]), "=r"(r[3]) : "r"(addr));
}
__device__ __forceinline__ void ldsm_x4_t(uint32_t* r, uint32_t addr) {
    asm volatile("ldmatrix.sync.aligned.m8n8.x4.trans.shared.b16 {%0,%1,%2,%3}, [%4];"
        : "=r"(r[0]), "=r"(r[1]), "=r"(r[2]), "=r"(r[3]) : "r"(addr));
}
__device__ __forceinline__ void mma16816(float* c, const uint32_t* a, const uint32_t* b) {
    asm volatile(
        "mma.sync.aligned.m16n8k16.row.col.f32.f16.f16.f32 "
        "{%0,%1,%2,%3}, {%4,%5,%6,%7}, {%8,%9}, {%0,%1,%2,%3};"
        : "+f"(c[0]), "+f"(c[1]), "+f"(c[2]), "+f"(c[3])
        : "r"(a[0]), "r"(a[1]), "r"(a[2]), "r"(a[3]), "r"(b[0]), "r"(b[1]));
}

// ---------------- setup 1: q, bias(frag order), weight stages (fp16 hi) ----------------
__global__ void setup_kernel(const float* __restrict__ emb,
                             const float* __restrict__ rpb,
                             const float* __restrict__ q_w,
                             const float* __restrict__ q_b,
                             const float* __restrict__ kv_w,
                             const float* __restrict__ proj_w) {
    int gid = blockIdx.x * blockDim.x + threadIdx.x;   // < 245760
    if (gid < 16384) {
        int e = gid & 31; int hn = gid >> 5;
        int h = hn >> 6, n = hn & 63;
        int d = h * 32 + e;
        const float* er = emb + n * 256;
        const float* wr = q_w + d * 256;
        float acc = q_b[d];
        #pragma unroll 4
        for (int c = 0; c < 256; c++) acc = fmaf(er[c], wr[c], acc);
        g_q[gid] = acc * SCALE;
    } else if (gid < 49152) {
        // bias in C-fragment order
        int t = gid - 16384;
        int r = t & 3, lane = (t >> 2) & 31, nt = (t >> 7) & 7;
        int mt = (t >> 10) & 1, s = (t >> 11) & 1, h = t >> 12;
        int n = s * 32 + mt * 16 + (lane >> 2) + ((r >> 1) << 3);
        int m = nt * 8 + ((lane & 3) << 1) + (r & 1);
        int r0 = (n >> 3) - (m >> 3) + 7;
        int r1 = (n & 7) - (m & 7) + 7;
        g_biasF[t] = rpb[(r0 * 15 + r1) * 8 + h];
    } else if (gid < 180224) {
        // kv_w fp16 hi: 512 rows x 256 k -> 8 stages of 32KB
        int t = gid - 49152;             // n*256 + kk, n < 512
        int n = t >> 8, kk = t & 255;
        int stage = (n >> 7) * 2 + (kk >> 7);
        uint32_t off = (uint32_t)stage * 32768 + a_sw_off(n & 127, kk & 127);
        g_kvw_blk[off >> 1] = __float2half(kv_w[n * 256 + kk]);
    } else {
        // proj_w fp16 hi: 256 rows x 256 k -> 4 stages
        int t = gid - 180224;            // n*256 + kk, n < 256
        int n = t >> 8, kk = t & 255;
        int stage = (n >> 7) * 2 + (kk >> 7);
        uint32_t off = (uint32_t)stage * 32768 + a_sw_off(n & 127, kk & 127);
        g_pw_blk[off >> 1] = __float2half(proj_w[n * 256 + kk]);
    }
}

// ---------------- setup 2: q A-fragments (128 slots: h,s,mt,kt,prec) ----------------
__global__ void setup2_kernel() {
    int t = blockIdx.x * blockDim.x + threadIdx.x;   // 4096
    int lane = t & 31, slot = t >> 5;                // slot 0..127
    int prec = slot & 1, kt = (slot >> 1) & 1, mt = (slot >> 2) & 1;
    int s = (slot >> 3) & 1, h = slot >> 4;
    uint32_t rr[4];
    #pragma unroll
    for (int r = 0; r < 4; r++) {
        int n = s * 32 + mt * 16 + (lane >> 2) + ((r & 1) << 3);
        int k = kt * 16 + ((lane & 3) << 1) + ((r >> 1) << 3);
        float q0 = g_q[(h * 64 + n) * 32 + k];
        float q1 = g_q[(h * 64 + n) * 32 + k + 1];
        uint32_t lo;
        uint32_t hi = split2h(q0, q1, lo);
        rr[r] = prec ? lo : hi;
    }
    g_qfrag[slot * 32 + lane] = make_uint4(rr[0], rr[1], rr[2], rr[3]);
}

// ---------------- kv epilogue store: fp32 pair -> hi/lo fp16 into window blocks ----------------
__device__ __forceinline__ void store2_kv(int r, int col, float a, float b) {
    const int w = r >> 6, m = r & 63;
    const int isV = col >= 256;
    const int d = col - (isV ? 256 : 0);
    uint8_t* base = g_KV + (size_t)w * 131072 + (isV ? 65536 : 0);
    const uint32_t off = kv_off(m, d);
    uint32_t lo;
    uint32_t hi = split2h(a, b, lo);
    *(uint32_t*)(base + off) = hi;
    *(uint32_t*)(base + off + 32768) = lo;
}

// ---------------- mma.sync split-fp16 GEMM: C = (Ah+Al) @ Wh^T + bias ----------------
// A in smem as fp16 hi (k 0..255) | lo (k 256..511), blocked SW128 (128KB).
// W fp16-hi streamed as 32KB stages (128 cols x 128 k) via 3-slot cp.async ring.
template<int NC, bool GATHER>
__global__ void __launch_bounds__(512, 1)
gemm_kernel(const float* __restrict__ xsrc,
            const float* __restrict__ bias,
            float* __restrict__ coutp) {
    extern __shared__ char gsm[];
    const uint32_t sraw = smem_u32(gsm);
    const uint32_t sA = (sraw + 1023) & ~1023u;
    const uint32_t sB = sA + 131072;          // 3 x 32KB ring

    const int tid = threadIdx.x;
    const int wid = tid >> 5;
    const int lid = tid & 31;
    const int r0  = blockIdx.x * 128;
    const int NST = NC;                        // 2 stages per 128-col pair

    const __half* wblk = GATHER ? g_kvw_blk : g_pw_blk;
    const int ldc = NC * 64;
    char* Ab = gsm + (sA - sraw);

    auto issue_copy = [&](int j) {
        uint32_t dst = sB + (uint32_t)(j % 3) * 32768 + (uint32_t)tid * 64;
        const char* src = (const char*)wblk + (size_t)j * 32768 + (size_t)tid * 64;
        #pragma unroll
        for (int q = 0; q < 4; q++)
            asm volatile("cp.async.cg.shared.global [%0], [%1], 16;"
                         :: "r"(dst + q * 16), "l"(src + q * 16));
        asm volatile("cp.async.commit_group;" ::: "memory");
    };

    issue_copy(0); issue_copy(1);

    // ---- build A tile: fp32 -> fp16 hi (k 0..255) | lo (k 256..511) ----
    #pragma unroll 4
    for (int it = 0; it < 32; it++) {
        int idx = tid + it * 512;
        int m = idx >> 7, p = idx & 127, c = p * 2;
        const float* rowp;
        if constexpr (GATHER) {
            int r = r0 + m;
            int b = r >> 14, i = (r >> 10) & 15, j = (r >> 6) & 15, n = r & 63;
            rowp = xsrc + ((size_t)b << 22) + ((size_t)i << 18)
                 + ((size_t)(n >> 3) << 15) + ((size_t)j << 11) + ((size_t)(n & 7) << 8);
        } else {
            rowp = g_O + (size_t)(r0 + m) * 256;
        }
        float2 f = *(const float2*)(rowp + c);
        uint32_t lo;
        uint32_t hi = split2h(f.x, f.y, lo);
        *(uint32_t*)(Ab + a_sw_off(m, c))       = hi;
        *(uint32_t*)(Ab + a_sw_off(m, c + 256)) = lo;
    }

    const int m0w = (wid >> 2) * 32;
    const int n0w = (wid & 3) * 32;
    const int lrow = lid & 7;
    const int quad = lid >> 3;
    const int mA0 = m0w + lrow + (quad & 1) * 8;
    const int mA1 = mA0 + 16;
    const uint32_t aoff0 = ((uint32_t)(mA0 >> 3) << 10) + ((uint32_t)(mA0 & 7) << 7);
    const uint32_t aoff1 = ((uint32_t)(mA1 >> 3) << 10) + ((uint32_t)(mA1 & 7) << 7);
    const uint32_t xorA  = (uint32_t)(mA0 & 7) << 4;
    const int kqa = (quad >> 1) * 8;
    const int nB0 = n0w + lrow + (quad >> 1) * 8;
    const uint32_t boff0 = ((uint32_t)(nB0 >> 3) << 10) + ((uint32_t)(nB0 & 7) << 7);
    const uint32_t boff1 = boff0 + 2048;
    const uint32_t xorB  = (uint32_t)(nB0 & 7) << 4;
    const int kqb = (quad & 1) * 8;

    auto ldA = [&](int ak, uint32_t* d0, uint32_t* d1) {
        uint32_t kp = (((uint32_t)(ak >> 6)) << 14) | (((uint32_t)(ak & 63)) << 1);
        ldsm_x4(d0, sA + aoff0 + (kp ^ xorA));
        ldsm_x4(d1, sA + aoff1 + (kp ^ xorA));
    };
    auto ldB2 = [&](uint32_t slot, int kl, uint32_t* d0, uint32_t* d1) {
        uint32_t kp = (((uint32_t)(kl >> 6)) << 14) | (((uint32_t)(kl & 63)) << 1);
        ldsm_x4(d0, slot + boff0 + (kp ^ xorB));
        ldsm_x4(d1, slot + boff1 + (kp ^ xorB));
    };

    float c[2][4][4];
    #pragma unroll
    for (int mt = 0; mt < 2; mt++)
        #pragma unroll
        for (int nt = 0; nt < 4; nt++)
            #pragma unroll
            for (int i = 0; i < 4; i++) c[mt][nt][i] = 0.f;

    uint32_t fh0[2][4], fh1[2][4], fl0[2][4], fl1[2][4], fb0[2][4], fb1[2][4];

    auto mma8 = [&](uint32_t* a0, uint32_t* a1, uint32_t* b0, uint32_t* b1) {
        mma16816(c[0][0], a0, b0);
        mma16816(c[0][1], a0, b0 + 2);
        mma16816(c[0][2], a0, b1);
        mma16816(c[0][3], a0, b1 + 2);
        mma16816(c[1][0], a1, b0);
        mma16816(c[1][1], a1, b0 + 2);
        mma16816(c[1][2], a1, b1);
        mma16816(c[1][3], a1, b1 + 2);
    };

    // ---- stage loop: stage i covers k-slice (i&1)*128, 128-col pair i>>1 ----
    for (int i = 0; i < NST; i++) {
        asm volatile("cp.async.wait_group 1;" ::: "memory");
        __syncthreads();
        if (i + 2 < NST) issue_copy(i + 2);

        const uint32_t slot = sB + (uint32_t)(i % 3) * 32768;
        const int kb = (i & 1) * 128;

        ldA(kb + kqa,       fh0[0], fh1[0]);
        ldA(kb + 256 + kqa, fl0[0], fl1[0]);
        ldB2(slot, kqb, fb0[0], fb1[0]);
        #pragma unroll
        for (int st = 0; st < 8; st++) {
            const int cb = st & 1, nb = cb ^ 1;
            if (st < 7) {
                ldA(kb + (st + 1) * 16 + kqa,       fh0[nb], fh1[nb]);
                ldA(kb + 256 + (st + 1) * 16 + kqa, fl0[nb], fl1[nb]);
                ldB2(slot, (st + 1) * 16 + kqb, fb0[nb], fb1[nb]);
            }
            mma8(fh0[cb], fh1[cb], fb0[cb], fb1[cb]);
            mma8(fl0[cb], fl1[cb], fb0[cb], fb1[cb]);
        }

        if (i & 1) {
            // epilogue for 128-col pair (i>>1): bias add + store
            const int colb = (i >> 1) * 128 + n0w;
            #pragma unroll
            for (int nt = 0; nt < 4; nt++) {
                const int col = colb + nt * 8 + 2 * (lid & 3);
                const float2 bv = *(const float2*)(bias + col);
                #pragma unroll
                for (int mt = 0; mt < 2; mt++) {
                    const int rlo = r0 + m0w + mt * 16 + (lid >> 2);
                    if constexpr (GATHER) {
                        store2_kv(rlo,     col, c[mt][nt][0] + bv.x, c[mt][nt][1] + bv.y);
                        store2_kv(rlo + 8, col, c[mt][nt][2] + bv.x, c[mt][nt][3] + bv.y);
                    } else {
                        *(float2*)(coutp + (size_t)rlo * ldc + col) =
                            make_float2(c[mt][nt][0] + bv.x, c[mt][nt][1] + bv.y);
                        *(float2*)(coutp + (size_t)(rlo + 8) * ldc + col) =
                            make_float2(c[mt][nt][2] + bv.x, c[mt][nt][3] + bv.y);
                    }
                }
            }
            #pragma unroll
            for (int mt = 0; mt < 2; mt++)
                #pragma unroll
                for (int nt = 0; nt < 4; nt++)
                    #pragma unroll
                    for (int k2 = 0; k2 < 4; k2++) c[mt][nt][k2] = 0.f;
        }
    }
}

// ---------------- tensor-core attention: 1 CTA per window, 2 warps per head --------------
__global__ void __launch_bounds__(512, 1)
attn_kernel() {
    extern __shared__ char asmem[];
    const uint32_t sraw = smem_u32(asmem);
    const uint32_t sKV = (sraw + 1023) & ~1023u;
    const int tid = threadIdx.x;
    const uint8_t* src = g_KV + (size_t)blockIdx.x * 131072;

    // K blocks (64KB) first, then V blocks (64KB): two commit groups
    #pragma unroll
    for (int t = 0; t < 8; t++) {
        uint32_t o = (uint32_t)(tid + t * 512) * 16;
        asm volatile("cp.async.cg.shared.global [%0], [%1], 16;"
                     :: "r"(sKV + o), "l"(src + o));
    }
    asm volatile("cp.async.commit_group;" ::: "memory");
    #pragma unroll
    for (int t = 8; t < 16; t++) {
        uint32_t o = (uint32_t)(tid + t * 512) * 16;
        asm volatile("cp.async.cg.shared.global [%0], [%1], 16;"
                     :: "r"(sKV + o), "l"(src + o));
    }
    asm volatile("cp.async.commit_group;" ::: "memory");

    const int wid = tid >> 5, lid = tid & 31;
    const int h = wid >> 1, s = wid & 1;
    const int lrow = lid & 7, grp = lid >> 3;

    // bias -> accumulators (C-frag order), q fragments (A-frag order)
    float sa[2][8][4];
    const float4* bf = (const float4*)g_biasF;
    #pragma unroll
    for (int mt = 0; mt < 2; mt++)
        #pragma unroll
        for (int nt = 0; nt < 8; nt++) {
            float4 b = bf[((((h * 2 + s) * 2 + mt) * 8) + nt) * 32 + lid];
            sa[mt][nt][0] = b.x; sa[mt][nt][1] = b.y;
            sa[mt][nt][2] = b.z; sa[mt][nt][3] = b.w;
        }
    uint4 qh[2][2], ql[2][2];
    #pragma unroll
    for (int mt = 0; mt < 2; mt++)
        #pragma unroll
        for (int kt = 0; kt < 2; kt++) {
            int sb = (((h * 2 + s) * 2 + mt) * 2 + kt) * 2;
            qh[mt][kt] = g_qfrag[sb * 32 + lid];
            ql[mt][kt] = g_qfrag[(sb + 1) * 32 + lid];
        }

    asm volatile("cp.async.wait_group 1;" ::: "memory");
    __syncthreads();

    // ---- S = Qh@Kh + Ql@Kh + Qh@Kl  (bias already in accumulators) ----
    #pragma unroll
    for (int kt = 0; kt < 2; kt++) {
        const int dcol = h * 32 + kt * 16 + (grp & 1) * 8;
        #pragma unroll
        for (int ntp = 0; ntp < 4; ntp++) {
            const int mrow = ntp * 16 + lrow + (grp >> 1) * 8;
            uint32_t a = sKV + kv_off(mrow, dcol);
            uint32_t bh[4], bl[4];
            ldsm_x4(bh, a);
            ldsm_x4(bl, a + 32768);
            mma16816(sa[0][2*ntp],   (const uint32_t*)&qh[0][kt], bh);
            mma16816(sa[0][2*ntp+1], (const uint32_t*)&qh[0][kt], bh + 2);
            mma16816(sa[1][2*ntp],   (const uint32_t*)&qh[1][kt], bh);
            mma16816(sa[1][2*ntp+1], (const uint32_t*)&qh[1][kt], bh + 2);
            mma16816(sa[0][2*ntp],   (const uint32_t*)&ql[0][kt], bh);
            mma16816(sa[0][2*ntp+1], (const uint32_t*)&ql[0][kt], bh + 2);
            mma16816(sa[1][2*ntp],   (const uint32_t*)&ql[1][kt], bh);
            mma16816(sa[1][2*ntp+1], (const uint32_t*)&ql[1][kt], bh + 2);
            mma16816(sa[0][2*ntp],   (const uint32_t*)&qh[0][kt], bl);
            mma16816(sa[0][2*ntp+1], (const uint32_t*)&qh[0][kt], bl + 2);
            mma16816(sa[1][2*ntp],   (const uint32_t*)&qh[1][kt], bl);
            mma16816(sa[1][2*ntp+1], (const uint32_t*)&qh[1][kt], bl + 2);
        }
    }

    // ---- softmax (rows split over 4 lanes; 2 bfly shuffles) ----
    float rinv[2][2];
    #pragma unroll
    for (int mt = 0; mt < 2; mt++)
        #pragma unroll
        for (int rh = 0; rh < 2; rh++) {
            float mx = -1e30f;
            #pragma unroll
            for (int nt = 0; nt < 8; nt++)
                mx = fmaxf(mx, fmaxf(sa[mt][nt][rh*2], sa[mt][nt][rh*2+1]));
            mx = fmaxf(mx, __shfl_xor_sync(0xffffffffu, mx, 1));
            mx = fmaxf(mx, __shfl_xor_sync(0xffffffffu, mx, 2));
            float ls = 0.f;
            #pragma unroll
            for (int nt = 0; nt < 8; nt++) {
                float p0 = __expf(sa[mt][nt][rh*2]   - mx);
                float p1 = __expf(sa[mt][nt][rh*2+1] - mx);
                sa[mt][nt][rh*2] = p0; sa[mt][nt][rh*2+1] = p1;
                ls += p0 + p1;
            }
            ls += __shfl_xor_sync(0xffffffffu, ls, 1);
            ls += __shfl_xor_sync(0xffffffffu, ls, 2);
            rinv[mt][rh] = 1.f / ls;
        }

    asm volatile("cp.async.wait_group 0;" ::: "memory");
    __syncthreads();

    // ---- O = Ph@Vh + Pl@Vh + Ph@Vl  (P via C->A fragment identity) ----
    float oa[2][4][4];
    #pragma unroll
    for (int mt = 0; mt < 2; mt++)
        #pragma unroll
        for (int nt = 0; nt < 4; nt++)
            #pragma unroll
            for (int i = 0; i < 4; i++) oa[mt][nt][i] = 0.f;

    #pragma unroll
    for (int j = 0; j < 4; j++) {
        uint32_t Ph[2][4], Pl[2][4];
        #pragma unroll
        for (int mt = 0; mt < 2; mt++) {
            Ph[mt][0] = split2h(sa[mt][2*j][0],   sa[mt][2*j][1],   Pl[mt][0]);
            Ph[mt][1] = split2h(sa[mt][2*j][2],   sa[mt][2*j][3],   Pl[mt][1]);
            Ph[mt][2] = split2h(sa[mt][2*j+1][0], sa[mt][2*j+1][1], Pl[mt][2]);
            Ph[mt][3] = split2h(sa[mt][2*j+1][2], sa[mt][2*j+1][3], Pl[mt][3]);
        }
        #pragma unroll
        for (int ep = 0; ep < 2; ep++) {
            const int mrow = j * 16 + lrow + (grp & 1) * 8;
            const int ecol = h * 32 + ep * 16 + (grp >> 1) * 8;
            uint32_t va = sKV + 65536 + kv_off(mrow, ecol);
            uint32_t vh[4], vl[4];
            ldsm_x4_t(vh, va);
            ldsm_x4_t(vl, va + 32768);
            #pragma unroll
            for (int mt = 0; mt < 2; mt++) {
                mma16816(oa[mt][2*ep],   Ph[mt], vh);
                mma16816(oa[mt][2*ep+1], Ph[mt], vh + 2);
                mma16816(oa[mt][2*ep],   Pl[mt], vh);
                mma16816(oa[mt][2*ep+1], Pl[mt], vh + 2);
                mma16816(oa[mt][2*ep],   Ph[mt], vl);
                mma16816(oa[mt][2*ep+1], Ph[mt], vl + 2);
            }
        }
    }

    // ---- scale by 1/l, write O fp32 ----
    const int q2 = (lid & 3) * 2, r4 = lid >> 2;
    #pragma unroll
    for (int mt = 0; mt < 2; mt++)
        #pragma unroll
        for (int rh = 0; rh < 2; rh++) {
            const int n = s * 32 + mt * 16 + r4 + rh * 8;
            float* orow = g_O + (size_t)(blockIdx.x * 64 + n) * 256 + h * 32;
            const float sc = rinv[mt][rh];
            #pragma unroll
            for (int nt = 0; nt < 4; nt++)
                *(float2*)(orow + nt * 8 + q2) =
                    make_float2(oa[mt][nt][rh*2] * sc, oa[mt][nt][rh*2+1] * sc);
        }
}

// ---------------- launcher ----------------
extern "C" void kernel_launch(void* const* d_in, const int* in_sizes, int n_in,
                              void* d_out, int out_size) {
    const float* x      = (const float*)d_in[0];
    const float* emb    = (const float*)d_in[1];
    const float* rpb    = (const float*)d_in[2];
    const float* q_w    = (const float*)d_in[3];
    const float* q_b    = (const float*)d_in[4];
    const float* kv_w   = (const float*)d_in[5];
    const float* kv_b   = (const float*)d_in[6];
    const float* proj_w = (const float*)d_in[7];
    const float* proj_b = (const float*)d_in[8];
    float* out = (float*)d_out;
    (void)in_sizes; (void)n_in; (void)out_size;

    const int GSM = 1024 + 131072 + 98304;   // 230400
    const int ASM = 1024 + 131072;           // 132096

    cudaFuncSetAttribute(gemm_kernel<8, true>,
                         cudaFuncAttributeMaxDynamicSharedMemorySize, GSM);
    cudaFuncSetAttribute(gemm_kernel<4, false>,
                         cudaFuncAttributeMaxDynamicSharedMemorySize, GSM);
    cudaFuncSetAttribute(attn_kernel,
                         cudaFuncAttributeMaxDynamicSharedMemorySize, ASM);

    setup_kernel<<<480, 512>>>(emb, rpb, q_w, q_b, kv_w, proj_w);
    setup2_kernel<<<8, 512>>>();
    gemm_kernel<8, true ><<<1024, 512, GSM>>>(x, kv_b, nullptr);
    attn_kernel<<<2048, 512, ASM>>>();
    gemm_kernel<4, false><<<1024, 512, GSM>>>(nullptr, proj_b, out);
}

// round 12
// speedup vs baseline: 5.5747x; 1.2487x over previous
#include <cuda_runtime.h>
#include <cuda_fp16.h>
#include <cstdint>

typedef unsigned long long ull;

#define SCALE 0.17677669529663687f   // 32^-0.5

// ---------------- device scratch ----------------
// g_KV: per window (2048) 65536 B: K-hi 32KB | V-hi 32KB (fp16)
// each 32KB block: [64 rows m][256 dims d], blocked SW128 (atom 8x64)
__device__ __align__(128) uint8_t g_KV[2048ULL * 65536];
__device__ __align__(128) float g_q [8 * 64 * 32];       // [(h*64+n)*32+e], * SCALE
__device__ __align__(128) float g_biasF[32768];          // C-frag-ordered bias
__device__ __align__(128) uint4 g_qfrag[128 * 32];       // A-frag-ordered q (hi/lo fp16)
// Weight stages: fp16 HI ONLY. 32KB stage = 128 cols x 128 k. kv: 8 stages, proj: 4.
__device__ __align__(128) __half g_kvw_blk[131072];
__device__ __align__(128) __half g_pw_blk [65536];

// ---------------- helpers ----------------
__device__ __forceinline__ uint32_t smem_u32(const void* p) {
    uint32_t a;
    asm("{ .reg .u64 t; cvta.to.shared.u64 t, %1; cvt.u32.u64 %0, t; }" : "=r"(a) : "l"(p));
    return a;
}

// 128-row blocked SW128 (GEMM A tile + weight stages)
__device__ __forceinline__ uint32_t a_sw_off(int m, int kk) {
    uint32_t off = ((uint32_t)(kk >> 6) * 16 + (m >> 3)) * 1024 + (m & 7) * 128 + (kk & 63) * 2;
    return off ^ ((off >> 3) & 0x70);
}
// 64-row blocked SW128 (per-window K/V/O blocks)
__device__ __forceinline__ uint32_t kv_off(int m, int d) {
    uint32_t off = ((uint32_t)(d >> 6) * 8 + (m >> 3)) * 1024 + (m & 7) * 128 + (d & 63) * 2;
    return off ^ ((off >> 3) & 0x70);
}

// split fp32 pair -> fp16x2 hi (returned) + fp16x2 lo
__device__ __forceinline__ uint32_t split2h(float a, float b, uint32_t& lo) {
    __half2 h = __floats2half2_rn(a, b);
    float2 hf = __half22float2(h);
    __half2 l = __floats2half2_rn(a - hf.x, b - hf.y);
    lo = *(uint32_t*)&l;
    return *(uint32_t*)&h;
}
__device__ __forceinline__ uint32_t pack2h(float a, float b) {
    __half2 h = __floats2half2_rn(a, b);
    return *(uint32_t*)&h;
}

__device__ __forceinline__ void ldsm_x4(uint32_t* r, uint32_t addr) {
    asm volatile("ldmatrix.sync.aligned.m8n8.x4.shared.b16 {%0,%1,%2,%3}, [%4];"
        : "=r"(r[0]), "=r"(r[1]), "=r"(r[2]), "=r"(r[3]) : "r"(addr));
}
__device__ __forceinline__ void ldsm_x4_t(uint32_t* r, uint32_t addr) {
    asm volatile("ldmatrix.sync.aligned.m8n8.x4.trans.shared.b16 {%0,%1,%2,%3}, [%4];"
        : "=r"(r[0]), "=r"(r[1]), "=r"(r[2]), "=r"(r[3]) : "r"(addr));
}
__device__ __forceinline__ void mma16816(float* c, const uint32_t* a, const uint32_t* b) {
    asm volatile(
        "mma.sync.aligned.m16n8k16.row.col.f32.f16.f16.f32 "
        "{%0,%1,%2,%3}, {%4,%5,%6,%7}, {%8,%9}, {%0,%1,%2,%3};"
        : "+f"(c[0]), "+f"(c[1]), "+f"(c[2]), "+f"(c[3])
        : "r"(a[0]), "r"(a[1]), "r"(a[2]), "r"(a[3]), "r"(b[0]), "r"(b[1]));
}

// ---------------- setup 1: q, bias(frag order), weight stages (fp16 hi) ----------------
__global__ void setup_kernel(const float* __restrict__ emb,
                             const float* __restrict__ rpb,
                             const float* __restrict__ q_w,
                             const float* __restrict__ q_b,
                             const float* __restrict__ kv_w,
                             const float* __restrict__ proj_w) {
    int gid = blockIdx.x * blockDim.x + threadIdx.x;   // < 245760
    if (gid < 16384) {
        int e = gid & 31; int hn = gid >> 5;
        int h = hn >> 6, n = hn & 63;
        int d = h * 32 + e;
        const float* er = emb + n * 256;
        const float* wr = q_w + d * 256;
        float acc = q_b[d];
        #pragma unroll 4
        for (int c = 0; c < 256; c++) acc = fmaf(er[c], wr[c], acc);
        g_q[gid] = acc * SCALE;
    } else if (gid < 49152) {
        // bias in C-fragment order
        int t = gid - 16384;
        int r = t & 3, lane = (t >> 2) & 31, nt = (t >> 7) & 7;
        int mt = (t >> 10) & 1, s = (t >> 11) & 1, h = t >> 12;
        int n = s * 32 + mt * 16 + (lane >> 2) + ((r >> 1) << 3);
        int m = nt * 8 + ((lane & 3) << 1) + (r & 1);
        int r0 = (n >> 3) - (m >> 3) + 7;
        int r1 = (n & 7) - (m & 7) + 7;
        g_biasF[t] = rpb[(r0 * 15 + r1) * 8 + h];
    } else if (gid < 180224) {
        // kv_w fp16 hi: 512 rows x 256 k -> 8 stages of 32KB
        int t = gid - 49152;             // n*256 + kk, n < 512
        int n = t >> 8, kk = t & 255;
        int stage = (n >> 7) * 2 + (kk >> 7);
        uint32_t off = (uint32_t)stage * 32768 + a_sw_off(n & 127, kk & 127);
        g_kvw_blk[off >> 1] = __float2half(kv_w[n * 256 + kk]);
    } else {
        // proj_w fp16 hi: 256 rows x 256 k -> 4 stages
        int t = gid - 180224;            // n*256 + kk, n < 256
        int n = t >> 8, kk = t & 255;
        int stage = (n >> 7) * 2 + (kk >> 7);
        uint32_t off = (uint32_t)stage * 32768 + a_sw_off(n & 127, kk & 127);
        g_pw_blk[off >> 1] = __float2half(proj_w[n * 256 + kk]);
    }
}

// ---------------- setup 2: q A-fragments (128 slots: h,s,mt,kt,prec) ----------------
__global__ void setup2_kernel() {
    int t = blockIdx.x * blockDim.x + threadIdx.x;   // 4096
    int lane = t & 31, slot = t >> 5;                // slot 0..127
    int prec = slot & 1, kt = (slot >> 1) & 1, mt = (slot >> 2) & 1;
    int s = (slot >> 3) & 1, h = slot >> 4;
    uint32_t rr[4];
    #pragma unroll
    for (int r = 0; r < 4; r++) {
        int n = s * 32 + mt * 16 + (lane >> 2) + ((r & 1) << 3);
        int k = kt * 16 + ((lane & 3) << 1) + ((r >> 1) << 3);
        float q0 = g_q[(h * 64 + n) * 32 + k];
        float q1 = g_q[(h * 64 + n) * 32 + k + 1];
        uint32_t lo;
        uint32_t hi = split2h(q0, q1, lo);
        rr[r] = prec ? lo : hi;
    }
    g_qfrag[slot * 32 + lane] = make_uint4(rr[0], rr[1], rr[2], rr[3]);
}

// ---------------- kv epilogue store: fp32 pair -> fp16 hi into window blocks ----------------
__device__ __forceinline__ void store2_kv(int r, int col, float a, float b) {
    const int w = r >> 6, m = r & 63;
    const int isV = col >= 256;
    const int d = col - (isV ? 256 : 0);
    uint8_t* base = g_KV + (size_t)w * 65536 + (isV ? 32768 : 0);
    *(uint32_t*)(base + kv_off(m, d)) = pack2h(a, b);
}

// ---------------- mma.sync split-fp16 GEMM (kv): C = (Ah+Al) @ Wh^T + bias ----------------
__global__ void __launch_bounds__(512, 1)
gemm_kernel(const float* __restrict__ xsrc,
            const float* __restrict__ bias) {
    extern __shared__ char gsm[];
    const uint32_t sraw = smem_u32(gsm);
    const uint32_t sA = (sraw + 1023) & ~1023u;
    const uint32_t sB = sA + 131072;          // 3 x 32KB ring

    const int tid = threadIdx.x;
    const int wid = tid >> 5;
    const int lid = tid & 31;
    const int r0  = blockIdx.x * 128;
    const int NST = 8;

    char* Ab = gsm + (sA - sraw);

    auto issue_copy = [&](int j) {
        uint32_t dst = sB + (uint32_t)(j % 3) * 32768 + (uint32_t)tid * 64;
        const char* src = (const char*)g_kvw_blk + (size_t)j * 32768 + (size_t)tid * 64;
        #pragma unroll
        for (int q = 0; q < 4; q++)
            asm volatile("cp.async.cg.shared.global [%0], [%1], 16;"
                         :: "r"(dst + q * 16), "l"(src + q * 16));
        asm volatile("cp.async.commit_group;" ::: "memory");
    };

    issue_copy(0); issue_copy(1);

    // ---- build A tile: fp32 -> fp16 hi (k 0..255) | lo (k 256..511) ----
    #pragma unroll 4
    for (int it = 0; it < 32; it++) {
        int idx = tid + it * 512;
        int m = idx >> 7, p = idx & 127, c = p * 2;
        int r = r0 + m;
        int b = r >> 14, i = (r >> 10) & 15, j = (r >> 6) & 15, n = r & 63;
        const float* rowp = xsrc + ((size_t)b << 22) + ((size_t)i << 18)
             + ((size_t)(n >> 3) << 15) + ((size_t)j << 11) + ((size_t)(n & 7) << 8);
        float2 f = *(const float2*)(rowp + c);
        uint32_t lo;
        uint32_t hi = split2h(f.x, f.y, lo);
        *(uint32_t*)(Ab + a_sw_off(m, c))       = hi;
        *(uint32_t*)(Ab + a_sw_off(m, c + 256)) = lo;
    }

    const int m0w = (wid >> 2) * 32;
    const int n0w = (wid & 3) * 32;
    const int lrow = lid & 7;
    const int quad = lid >> 3;
    const int mA0 = m0w + lrow + (quad & 1) * 8;
    const int mA1 = mA0 + 16;
    const uint32_t aoff0 = ((uint32_t)(mA0 >> 3) << 10) + ((uint32_t)(mA0 & 7) << 7);
    const uint32_t aoff1 = ((uint32_t)(mA1 >> 3) << 10) + ((uint32_t)(mA1 & 7) << 7);
    const uint32_t xorA  = (uint32_t)(mA0 & 7) << 4;
    const int kqa = (quad >> 1) * 8;
    const int nB0 = n0w + lrow + (quad >> 1) * 8;
    const uint32_t boff0 = ((uint32_t)(nB0 >> 3) << 10) + ((uint32_t)(nB0 & 7) << 7);
    const uint32_t boff1 = boff0 + 2048;
    const uint32_t xorB  = (uint32_t)(nB0 & 7) << 4;
    const int kqb = (quad & 1) * 8;

    auto ldA = [&](int ak, uint32_t* d0, uint32_t* d1) {
        uint32_t kp = (((uint32_t)(ak >> 6)) << 14) | (((uint32_t)(ak & 63)) << 1);
        ldsm_x4(d0, sA + aoff0 + (kp ^ xorA));
        ldsm_x4(d1, sA + aoff1 + (kp ^ xorA));
    };
    auto ldB2 = [&](uint32_t slot, int kl, uint32_t* d0, uint32_t* d1) {
        uint32_t kp = (((uint32_t)(kl >> 6)) << 14) | (((uint32_t)(kl & 63)) << 1);
        ldsm_x4(d0, slot + boff0 + (kp ^ xorB));
        ldsm_x4(d1, slot + boff1 + (kp ^ xorB));
    };

    float c[2][4][4];
    #pragma unroll
    for (int mt = 0; mt < 2; mt++)
        #pragma unroll
        for (int nt = 0; nt < 4; nt++)
            #pragma unroll
            for (int i = 0; i < 4; i++) c[mt][nt][i] = 0.f;

    uint32_t fh0[2][4], fh1[2][4], fl0[2][4], fl1[2][4], fb0[2][4], fb1[2][4];

    auto mma8 = [&](uint32_t* a0, uint32_t* a1, uint32_t* b0, uint32_t* b1) {
        mma16816(c[0][0], a0, b0);
        mma16816(c[0][1], a0, b0 + 2);
        mma16816(c[0][2], a0, b1);
        mma16816(c[0][3], a0, b1 + 2);
        mma16816(c[1][0], a1, b0);
        mma16816(c[1][1], a1, b0 + 2);
        mma16816(c[1][2], a1, b1);
        mma16816(c[1][3], a1, b1 + 2);
    };

    for (int i = 0; i < NST; i++) {
        asm volatile("cp.async.wait_group 1;" ::: "memory");
        __syncthreads();
        if (i + 2 < NST) issue_copy(i + 2);

        const uint32_t slot = sB + (uint32_t)(i % 3) * 32768;
        const int kb = (i & 1) * 128;

        ldA(kb + kqa,       fh0[0], fh1[0]);
        ldA(kb + 256 + kqa, fl0[0], fl1[0]);
        ldB2(slot, kqb, fb0[0], fb1[0]);
        #pragma unroll
        for (int st = 0; st < 8; st++) {
            const int cb = st & 1, nb = cb ^ 1;
            if (st < 7) {
                ldA(kb + (st + 1) * 16 + kqa,       fh0[nb], fh1[nb]);
                ldA(kb + 256 + (st + 1) * 16 + kqa, fl0[nb], fl1[nb]);
                ldB2(slot, (st + 1) * 16 + kqb, fb0[nb], fb1[nb]);
            }
            mma8(fh0[cb], fh1[cb], fb0[cb], fb1[cb]);
            mma8(fl0[cb], fl1[cb], fb0[cb], fb1[cb]);
        }

        if (i & 1) {
            const int colb = (i >> 1) * 128 + n0w;
            #pragma unroll
            for (int nt = 0; nt < 4; nt++) {
                const int col = colb + nt * 8 + 2 * (lid & 3);
                const float2 bv = *(const float2*)(bias + col);
                #pragma unroll
                for (int mt = 0; mt < 2; mt++) {
                    const int rlo = r0 + m0w + mt * 16 + (lid >> 2);
                    store2_kv(rlo,     col, c[mt][nt][0] + bv.x, c[mt][nt][1] + bv.y);
                    store2_kv(rlo + 8, col, c[mt][nt][2] + bv.x, c[mt][nt][3] + bv.y);
                }
            }
            #pragma unroll
            for (int mt = 0; mt < 2; mt++)
                #pragma unroll
                for (int nt = 0; nt < 4; nt++)
                    #pragma unroll
                    for (int k2 = 0; k2 < 4; k2++) c[mt][nt][k2] = 0.f;
        }
    }
}

// ------- fused attention + proj: 1 CTA per window, writes final out --------
__global__ void __launch_bounds__(512, 1)
attn_kernel(const float* __restrict__ proj_b, float* __restrict__ out) {
    extern __shared__ char asmem[];
    const uint32_t sraw = smem_u32(asmem);
    const uint32_t sKV = (sraw + 1023) & ~1023u;   // 64KB: K-hi | V-hi; later O-hi | O-lo
    const uint32_t sP  = sKV + 65536;              // 128KB proj weights (4 stages)
    const int tid = threadIdx.x;
    const uint8_t* src = g_KV + (size_t)blockIdx.x * 65536;

    // group0: KV 64KB; group1+2: proj weights 128KB
    #pragma unroll
    for (int t = 0; t < 8; t++) {
        uint32_t o = (uint32_t)(tid + t * 512) * 16;
        asm volatile("cp.async.cg.shared.global [%0], [%1], 16;"
                     :: "r"(sKV + o), "l"(src + o));
    }
    asm volatile("cp.async.commit_group;" ::: "memory");
    #pragma unroll
    for (int t = 0; t < 8; t++) {
        uint32_t o = (uint32_t)(tid + t * 512) * 16;
        asm volatile("cp.async.cg.shared.global [%0], [%1], 16;"
                     :: "r"(sP + o), "l"((const char*)g_pw_blk + o));
    }
    asm volatile("cp.async.commit_group;" ::: "memory");
    #pragma unroll
    for (int t = 8; t < 16; t++) {
        uint32_t o = (uint32_t)(tid + t * 512) * 16;
        asm volatile("cp.async.cg.shared.global [%0], [%1], 16;"
                     :: "r"(sP + o), "l"((const char*)g_pw_blk + o));
    }
    asm volatile("cp.async.commit_group;" ::: "memory");

    const int wid = tid >> 5, lid = tid & 31;
    const int h = wid >> 1, s = wid & 1;
    const int lrow = lid & 7, grp = lid >> 3;

    // bias -> accumulators (C-frag order), q fragments (A-frag order)
    float sa[2][8][4];
    const float4* bf = (const float4*)g_biasF;
    #pragma unroll
    for (int mt = 0; mt < 2; mt++)
        #pragma unroll
        for (int nt = 0; nt < 8; nt++) {
            float4 b = bf[((((h * 2 + s) * 2 + mt) * 8) + nt) * 32 + lid];
            sa[mt][nt][0] = b.x; sa[mt][nt][1] = b.y;
            sa[mt][nt][2] = b.z; sa[mt][nt][3] = b.w;
        }
    uint4 qh[2][2], ql[2][2];
    #pragma unroll
    for (int mt = 0; mt < 2; mt++)
        #pragma unroll
        for (int kt = 0; kt < 2; kt++) {
            int sb = (((h * 2 + s) * 2 + mt) * 2 + kt) * 2;
            qh[mt][kt] = g_qfrag[sb * 32 + lid];
            ql[mt][kt] = g_qfrag[(sb + 1) * 32 + lid];
        }

    asm volatile("cp.async.wait_group 2;" ::: "memory");
    __syncthreads();

    // ---- S = (Qh+Ql)@Kh  (bias preloaded) ----
    #pragma unroll
    for (int kt = 0; kt < 2; kt++) {
        const int dcol = h * 32 + kt * 16 + (grp & 1) * 8;
        #pragma unroll
        for (int ntp = 0; ntp < 4; ntp++) {
            const int mrow = ntp * 16 + lrow + (grp >> 1) * 8;
            uint32_t a = sKV + kv_off(mrow, dcol);
            uint32_t bh[4];
            ldsm_x4(bh, a);
            mma16816(sa[0][2*ntp],   (const uint32_t*)&qh[0][kt], bh);
            mma16816(sa[0][2*ntp+1], (const uint32_t*)&qh[0][kt], bh + 2);
            mma16816(sa[1][2*ntp],   (const uint32_t*)&qh[1][kt], bh);
            mma16816(sa[1][2*ntp+1], (const uint32_t*)&qh[1][kt], bh + 2);
            mma16816(sa[0][2*ntp],   (const uint32_t*)&ql[0][kt], bh);
            mma16816(sa[0][2*ntp+1], (const uint32_t*)&ql[0][kt], bh + 2);
            mma16816(sa[1][2*ntp],   (const uint32_t*)&ql[1][kt], bh);
            mma16816(sa[1][2*ntp+1], (const uint32_t*)&ql[1][kt], bh + 2);
        }
    }

    // ---- softmax ----
    float rinv[2][2];
    #pragma unroll
    for (int mt = 0; mt < 2; mt++)
        #pragma unroll
        for (int rh = 0; rh < 2; rh++) {
            float mx = -1e30f;
            #pragma unroll
            for (int nt = 0; nt < 8; nt++)
                mx = fmaxf(mx, fmaxf(sa[mt][nt][rh*2], sa[mt][nt][rh*2+1]));
            mx = fmaxf(mx, __shfl_xor_sync(0xffffffffu, mx, 1));
            mx = fmaxf(mx, __shfl_xor_sync(0xffffffffu, mx, 2));
            float ls = 0.f;
            #pragma unroll
            for (int nt = 0; nt < 8; nt++) {
                float p0 = __expf(sa[mt][nt][rh*2]   - mx);
                float p1 = __expf(sa[mt][nt][rh*2+1] - mx);
                sa[mt][nt][rh*2] = p0; sa[mt][nt][rh*2+1] = p1;
                ls += p0 + p1;
            }
            ls += __shfl_xor_sync(0xffffffffu, ls, 1);
            ls += __shfl_xor_sync(0xffffffffu, ls, 2);
            rinv[mt][rh] = 1.f / ls;
        }

    // ---- O = (Ph+Pl)@Vh ----
    float oa[2][4][4];
    #pragma unroll
    for (int mt = 0; mt < 2; mt++)
        #pragma unroll
        for (int nt = 0; nt < 4; nt++)
            #pragma unroll
            for (int i = 0; i < 4; i++) oa[mt][nt][i] = 0.f;

    #pragma unroll
    for (int j = 0; j < 4; j++) {
        uint32_t Ph[2][4], Pl[2][4];
        #pragma unroll
        for (int mt = 0; mt < 2; mt++) {
            Ph[mt][0] = split2h(sa[mt][2*j][0],   sa[mt][2*j][1],   Pl[mt][0]);
            Ph[mt][1] = split2h(sa[mt][2*j][2],   sa[mt][2*j][3],   Pl[mt][1]);
            Ph[mt][2] = split2h(sa[mt][2*j+1][0], sa[mt][2*j+1][1], Pl[mt][2]);
            Ph[mt][3] = split2h(sa[mt][2*j+1][2], sa[mt][2*j+1][3], Pl[mt][3]);
        }
        #pragma unroll
        for (int ep = 0; ep < 2; ep++) {
            const int mrow = j * 16 + lrow + (grp & 1) * 8;
            const int ecol = h * 32 + ep * 16 + (grp >> 1) * 8;
            uint32_t va = sKV + 32768 + kv_off(mrow, ecol);
            uint32_t vh[4];
            ldsm_x4_t(vh, va);
            #pragma unroll
            for (int mt = 0; mt < 2; mt++) {
                mma16816(oa[mt][2*ep],   Ph[mt], vh);
                mma16816(oa[mt][2*ep+1], Ph[mt], vh + 2);
                mma16816(oa[mt][2*ep],   Pl[mt], vh);
                mma16816(oa[mt][2*ep+1], Pl[mt], vh + 2);
            }
        }
    }

    // ---- stage O (scaled) into smem as fp16 hi|lo, 64-row SW128 layout ----
    __syncthreads();    // all K/V reads done; reuse sKV region for O
    const int q2 = (lid & 3) * 2, r4 = lid >> 2;
    char* sm = asmem + (sKV - sraw);
    #pragma unroll
    for (int mt = 0; mt < 2; mt++)
        #pragma unroll
        for (int rh = 0; rh < 2; rh++) {
            const int n = s * 32 + mt * 16 + r4 + rh * 8;
            const float sc = rinv[mt][rh];
            #pragma unroll
            for (int nt = 0; nt < 4; nt++) {
                const int col = h * 32 + nt * 8 + q2;
                uint32_t lo;
                uint32_t hi = split2h(oa[mt][nt][rh*2] * sc, oa[mt][nt][rh*2+1] * sc, lo);
                uint32_t off = kv_off(n, col);
                *(uint32_t*)(sm + off)         = hi;
                *(uint32_t*)(sm + 32768 + off) = lo;
            }
        }
    asm volatile("cp.async.wait_group 0;" ::: "memory");
    __syncthreads();

    // ---- proj: C[64x256] = (Oh+Ol) @ PWh^T + proj_b ----
    const int mw = wid >> 2, nw = wid & 3;          // warp tile 16 rows x 64 cols
    const int arow = mw * 16 + lrow + (grp & 1) * 8;
    const int kqa = (grp >> 1) * 8;
    const int kqb = (grp & 1) * 8;
    int nrow[4];
    #pragma unroll
    for (int t = 0; t < 4; t++) nrow[t] = nw * 64 + t * 16 + lrow + (grp >> 1) * 8;
    const uint32_t sPw = sP + (uint32_t)(nw >> 1) * 65536;

    float pc[8][4];
    #pragma unroll
    for (int nt = 0; nt < 8; nt++)
        #pragma unroll
        for (int i = 0; i < 4; i++) pc[nt][i] = 0.f;

    #pragma unroll 4
    for (int ks = 0; ks < 16; ks++) {
        const int k = ks * 16;
        uint32_t ah[4], al[4], bb[4][4];
        uint32_t aoff = kv_off(arow, k + kqa);
        ldsm_x4(ah, sKV + aoff);
        ldsm_x4(al, sKV + 32768 + aoff);
        #pragma unroll
        for (int t = 0; t < 4; t++) {
            uint32_t ba = sPw + (uint32_t)((k + kqb) >> 7) * 32768
                        + a_sw_off(nrow[t] & 127, (k + kqb) & 127);
            ldsm_x4(bb[t], ba);
        }
        #pragma unroll
        for (int t = 0; t < 4; t++) {
            mma16816(pc[2*t],   ah, bb[t]);
            mma16816(pc[2*t+1], ah, bb[t] + 2);
            mma16816(pc[2*t],   al, bb[t]);
            mma16816(pc[2*t+1], al, bb[t] + 2);
        }
    }

    // ---- epilogue: bias + store out ----
    float* obase = out + (size_t)blockIdx.x * 64 * 256;
    #pragma unroll
    for (int nt = 0; nt < 8; nt++) {
        const int col = nw * 64 + nt * 8 + q2;
        const float2 bv = *(const float2*)(proj_b + col);
        const int rlo = mw * 16 + r4;
        *(float2*)(obase + (size_t)rlo * 256 + col) =
            make_float2(pc[nt][0] + bv.x, pc[nt][1] + bv.y);
        *(float2*)(obase + (size_t)(rlo + 8) * 256 + col) =
            make_float2(pc[nt][2] + bv.x, pc[nt][3] + bv.y);
    }
}

// ---------------- launcher ----------------
extern "C" void kernel_launch(void* const* d_in, const int* in_sizes, int n_in,
                              void* d_out, int out_size) {
    const float* x      = (const float*)d_in[0];
    const float* emb    = (const float*)d_in[1];
    const float* rpb    = (const float*)d_in[2];
    const float* q_w    = (const float*)d_in[3];
    const float* q_b    = (const float*)d_in[4];
    const float* kv_w   = (const float*)d_in[5];
    const float* kv_b   = (const float*)d_in[6];
    const float* proj_w = (const float*)d_in[7];
    const float* proj_b = (const float*)d_in[8];
    float* out = (float*)d_out;
    (void)in_sizes; (void)n_in; (void)out_size;

    const int GSM = 1024 + 131072 + 98304;   // 230400
    const int ASM = 1024 + 65536 + 131072;   // 197632

    cudaFuncSetAttribute(gemm_kernel,
                         cudaFuncAttributeMaxDynamicSharedMemorySize, GSM);
    cudaFuncSetAttribute(attn_kernel,
                         cudaFuncAttributeMaxDynamicSharedMemorySize, ASM);

    setup_kernel<<<480, 512>>>(emb, rpb, q_w, q_b, kv_w, proj_w);
    setup2_kernel<<<8, 512>>>();
    gemm_kernel<<<1024, 512, GSM>>>(x, kv_b);
    attn_kernel<<<2048, 512, ASM>>>(proj_b, out);
}

// round 13
// speedup vs baseline: 6.6630x; 1.1952x over previous
#include <cuda_runtime.h>
#include <cuda_fp16.h>
#include <cstdint>

typedef unsigned long long ull;

#define SCALE 0.17677669529663687f   // 32^-0.5

// ---------------- device scratch ----------------
// g_KV: per window (2048) 65536 B: K-hi 32KB | V-hi 32KB (fp16)
// each 32KB block: [64 rows m][256 dims d], blocked SW128 (atom 8x64)
__device__ __align__(128) uint8_t g_KV[2048ULL * 65536];
__device__ __align__(128) float g_q [8 * 64 * 32];       // [(h*64+n)*32+e], * SCALE
__device__ __align__(128) float g_biasF[32768];          // C-frag-ordered bias
__device__ __align__(128) uint4 g_qfrag[128 * 32];       // A-frag-ordered q (hi/lo fp16)
// Weight stages: fp16 HI ONLY. 32KB stage = 128 cols x 128 k. kv: 8 stages, proj: 4.
__device__ __align__(128) __half g_kvw_blk[131072];
__device__ __align__(128) __half g_pw_blk [65536];

// ---------------- helpers ----------------
__device__ __forceinline__ uint32_t smem_u32(const void* p) {
    uint32_t a;
    asm("{ .reg .u64 t; cvta.to.shared.u64 t, %1; cvt.u32.u64 %0, t; }" : "=r"(a) : "l"(p));
    return a;
}

// 128-row blocked SW128 (GEMM A tile + weight stages)
__device__ __forceinline__ uint32_t a_sw_off(int m, int kk) {
    uint32_t off = ((uint32_t)(kk >> 6) * 16 + (m >> 3)) * 1024 + (m & 7) * 128 + (kk & 63) * 2;
    return off ^ ((off >> 3) & 0x70);
}
// 64-row blocked SW128 (per-window K/V/O blocks)
__device__ __forceinline__ uint32_t kv_off(int m, int d) {
    uint32_t off = ((uint32_t)(d >> 6) * 8 + (m >> 3)) * 1024 + (m & 7) * 128 + (d & 63) * 2;
    return off ^ ((off >> 3) & 0x70);
}

// split fp32 pair -> fp16x2 hi (returned) + fp16x2 lo
__device__ __forceinline__ uint32_t split2h(float a, float b, uint32_t& lo) {
    __half2 h = __floats2half2_rn(a, b);
    float2 hf = __half22float2(h);
    __half2 l = __floats2half2_rn(a - hf.x, b - hf.y);
    lo = *(uint32_t*)&l;
    return *(uint32_t*)&h;
}
__device__ __forceinline__ uint32_t pack2h(float a, float b) {
    __half2 h = __floats2half2_rn(a, b);
    return *(uint32_t*)&h;
}

__device__ __forceinline__ void ldsm_x4(uint32_t* r, uint32_t addr) {
    asm volatile("ldmatrix.sync.aligned.m8n8.x4.shared.b16 {%0,%1,%2,%3}, [%4];"
        : "=r"(r[0]), "=r"(r[1]), "=r"(r[2]), "=r"(r[3]) : "r"(addr));
}
__device__ __forceinline__ void ldsm_x4_t(uint32_t* r, uint32_t addr) {
    asm volatile("ldmatrix.sync.aligned.m8n8.x4.trans.shared.b16 {%0,%1,%2,%3}, [%4];"
        : "=r"(r[0]), "=r"(r[1]), "=r"(r[2]), "=r"(r[3]) : "r"(addr));
}
__device__ __forceinline__ void mma16816(float* c, const uint32_t* a, const uint32_t* b) {
    asm volatile(
        "mma.sync.aligned.m16n8k16.row.col.f32.f16.f16.f32 "
        "{%0,%1,%2,%3}, {%4,%5,%6,%7}, {%8,%9}, {%0,%1,%2,%3};"
        : "+f"(c[0]), "+f"(c[1]), "+f"(c[2]), "+f"(c[3])
        : "r"(a[0]), "r"(a[1]), "r"(a[2]), "r"(a[3]), "r"(b[0]), "r"(b[1]));
}

// ---------------- setup 1: q, bias(frag order), weight stages (fp16 hi) ----------------
__global__ void setup_kernel(const float* __restrict__ emb,
                             const float* __restrict__ rpb,
                             const float* __restrict__ q_w,
                             const float* __restrict__ q_b,
                             const float* __restrict__ kv_w,
                             const float* __restrict__ proj_w) {
    int gid = blockIdx.x * blockDim.x + threadIdx.x;   // < 245760
    if (gid < 16384) {
        int e = gid & 31; int hn = gid >> 5;
        int h = hn >> 6, n = hn & 63;
        int d = h * 32 + e;
        const float* er = emb + n * 256;
        const float* wr = q_w + d * 256;
        float acc = q_b[d];
        #pragma unroll 4
        for (int c = 0; c < 256; c++) acc = fmaf(er[c], wr[c], acc);
        g_q[gid] = acc * SCALE;
    } else if (gid < 49152) {
        // bias in C-fragment order
        int t = gid - 16384;
        int r = t & 3, lane = (t >> 2) & 31, nt = (t >> 7) & 7;
        int mt = (t >> 10) & 1, s = (t >> 11) & 1, h = t >> 12;
        int n = s * 32 + mt * 16 + (lane >> 2) + ((r >> 1) << 3);
        int m = nt * 8 + ((lane & 3) << 1) + (r & 1);
        int r0 = (n >> 3) - (m >> 3) + 7;
        int r1 = (n & 7) - (m & 7) + 7;
        g_biasF[t] = rpb[(r0 * 15 + r1) * 8 + h];
    } else if (gid < 180224) {
        // kv_w fp16 hi: 512 rows x 256 k -> 8 stages of 32KB
        int t = gid - 49152;             // n*256 + kk, n < 512
        int n = t >> 8, kk = t & 255;
        int stage = (n >> 7) * 2 + (kk >> 7);
        uint32_t off = (uint32_t)stage * 32768 + a_sw_off(n & 127, kk & 127);
        g_kvw_blk[off >> 1] = __float2half(kv_w[n * 256 + kk]);
    } else {
        // proj_w fp16 hi: 256 rows x 256 k -> 4 stages
        int t = gid - 180224;            // n*256 + kk, n < 256
        int n = t >> 8, kk = t & 255;
        int stage = (n >> 7) * 2 + (kk >> 7);
        uint32_t off = (uint32_t)stage * 32768 + a_sw_off(n & 127, kk & 127);
        g_pw_blk[off >> 1] = __float2half(proj_w[n * 256 + kk]);
    }
}

// ---------------- setup 2: q A-fragments (128 slots: h,s,mt,kt,prec) ----------------
__global__ void setup2_kernel() {
    int t = blockIdx.x * blockDim.x + threadIdx.x;   // 4096
    int lane = t & 31, slot = t >> 5;                // slot 0..127
    int prec = slot & 1, kt = (slot >> 1) & 1, mt = (slot >> 2) & 1;
    int s = (slot >> 3) & 1, h = slot >> 4;
    uint32_t rr[4];
    #pragma unroll
    for (int r = 0; r < 4; r++) {
        int n = s * 32 + mt * 16 + (lane >> 2) + ((r & 1) << 3);
        int k = kt * 16 + ((lane & 3) << 1) + ((r >> 1) << 3);
        float q0 = g_q[(h * 64 + n) * 32 + k];
        float q1 = g_q[(h * 64 + n) * 32 + k + 1];
        uint32_t lo;
        uint32_t hi = split2h(q0, q1, lo);
        rr[r] = prec ? lo : hi;
    }
    g_qfrag[slot * 32 + lane] = make_uint4(rr[0], rr[1], rr[2], rr[3]);
}

// ---------------- kv epilogue store: fp32 pair -> fp16 hi into window blocks ----------------
__device__ __forceinline__ void store2_kv(int r, int col, float a, float b) {
    const int w = r >> 6, m = r & 63;
    const int isV = col >= 256;
    const int d = col - (isV ? 256 : 0);
    uint8_t* base = g_KV + (size_t)w * 65536 + (isV ? 32768 : 0);
    *(uint32_t*)(base + kv_off(m, d)) = pack2h(a, b);
}

// ---------------- mma.sync fp16 GEMM (kv): C = Ah @ Wh^T + bias (1 term) ----------------
__global__ void __launch_bounds__(512, 1)
gemm_kernel(const float* __restrict__ xsrc,
            const float* __restrict__ bias) {
    extern __shared__ char gsm[];
    const uint32_t sraw = smem_u32(gsm);
    const uint32_t sA = (sraw + 1023) & ~1023u;    // 64KB A tile (fp16 hi)
    const uint32_t sB = sA + 65536;                // 3 x 32KB ring

    const int tid = threadIdx.x;
    const int wid = tid >> 5;
    const int lid = tid & 31;
    const int r0  = blockIdx.x * 128;
    const int NST = 8;

    char* Ab = gsm + (sA - sraw);

    auto issue_copy = [&](int j) {
        uint32_t dst = sB + (uint32_t)(j % 3) * 32768 + (uint32_t)tid * 64;
        const char* src = (const char*)g_kvw_blk + (size_t)j * 32768 + (size_t)tid * 64;
        #pragma unroll
        for (int q = 0; q < 4; q++)
            asm volatile("cp.async.cg.shared.global [%0], [%1], 16;"
                         :: "r"(dst + q * 16), "l"(src + q * 16));
        asm volatile("cp.async.commit_group;" ::: "memory");
    };

    issue_copy(0); issue_copy(1);

    // ---- build A tile: fp32 -> fp16 hi only ----
    #pragma unroll 4
    for (int it = 0; it < 32; it++) {
        int idx = tid + it * 512;
        int m = idx >> 7, p = idx & 127, c = p * 2;
        int r = r0 + m;
        int b = r >> 14, i = (r >> 10) & 15, j = (r >> 6) & 15, n = r & 63;
        const float* rowp = xsrc + ((size_t)b << 22) + ((size_t)i << 18)
             + ((size_t)(n >> 3) << 15) + ((size_t)j << 11) + ((size_t)(n & 7) << 8);
        float2 f = *(const float2*)(rowp + c);
        *(uint32_t*)(Ab + a_sw_off(m, c)) = pack2h(f.x, f.y);
    }

    const int m0w = (wid >> 2) * 32;
    const int n0w = (wid & 3) * 32;
    const int lrow = lid & 7;
    const int quad = lid >> 3;
    const int mA0 = m0w + lrow + (quad & 1) * 8;
    const int mA1 = mA0 + 16;
    const uint32_t aoff0 = ((uint32_t)(mA0 >> 3) << 10) + ((uint32_t)(mA0 & 7) << 7);
    const uint32_t aoff1 = ((uint32_t)(mA1 >> 3) << 10) + ((uint32_t)(mA1 & 7) << 7);
    const uint32_t xorA  = (uint32_t)(mA0 & 7) << 4;
    const int kqa = (quad >> 1) * 8;
    const int nB0 = n0w + lrow + (quad >> 1) * 8;
    const uint32_t boff0 = ((uint32_t)(nB0 >> 3) << 10) + ((uint32_t)(nB0 & 7) << 7);
    const uint32_t boff1 = boff0 + 2048;
    const uint32_t xorB  = (uint32_t)(nB0 & 7) << 4;
    const int kqb = (quad & 1) * 8;

    auto ldA = [&](int ak, uint32_t* d0, uint32_t* d1) {
        uint32_t kp = (((uint32_t)(ak >> 6)) << 14) | (((uint32_t)(ak & 63)) << 1);
        ldsm_x4(d0, sA + aoff0 + (kp ^ xorA));
        ldsm_x4(d1, sA + aoff1 + (kp ^ xorA));
    };
    auto ldB2 = [&](uint32_t slot, int kl, uint32_t* d0, uint32_t* d1) {
        uint32_t kp = (((uint32_t)(kl >> 6)) << 14) | (((uint32_t)(kl & 63)) << 1);
        ldsm_x4(d0, slot + boff0 + (kp ^ xorB));
        ldsm_x4(d1, slot + boff1 + (kp ^ xorB));
    };

    float c[2][4][4];
    #pragma unroll
    for (int mt = 0; mt < 2; mt++)
        #pragma unroll
        for (int nt = 0; nt < 4; nt++)
            #pragma unroll
            for (int i = 0; i < 4; i++) c[mt][nt][i] = 0.f;

    uint32_t fh0[2][4], fh1[2][4], fb0[2][4], fb1[2][4];

    auto mma8 = [&](uint32_t* a0, uint32_t* a1, uint32_t* b0, uint32_t* b1) {
        mma16816(c[0][0], a0, b0);
        mma16816(c[0][1], a0, b0 + 2);
        mma16816(c[0][2], a0, b1);
        mma16816(c[0][3], a0, b1 + 2);
        mma16816(c[1][0], a1, b0);
        mma16816(c[1][1], a1, b0 + 2);
        mma16816(c[1][2], a1, b1);
        mma16816(c[1][3], a1, b1 + 2);
    };

    for (int i = 0; i < NST; i++) {
        asm volatile("cp.async.wait_group 1;" ::: "memory");
        __syncthreads();
        if (i + 2 < NST) issue_copy(i + 2);

        const uint32_t slot = sB + (uint32_t)(i % 3) * 32768;
        const int kb = (i & 1) * 128;

        ldA(kb + kqa, fh0[0], fh1[0]);
        ldB2(slot, kqb, fb0[0], fb1[0]);
        #pragma unroll
        for (int st = 0; st < 8; st++) {
            const int cb = st & 1, nb = cb ^ 1;
            if (st < 7) {
                ldA(kb + (st + 1) * 16 + kqa, fh0[nb], fh1[nb]);
                ldB2(slot, (st + 1) * 16 + kqb, fb0[nb], fb1[nb]);
            }
            mma8(fh0[cb], fh1[cb], fb0[cb], fb1[cb]);
        }

        if (i & 1) {
            const int colb = (i >> 1) * 128 + n0w;
            #pragma unroll
            for (int nt = 0; nt < 4; nt++) {
                const int col = colb + nt * 8 + 2 * (lid & 3);
                const float2 bv = *(const float2*)(bias + col);
                #pragma unroll
                for (int mt = 0; mt < 2; mt++) {
                    const int rlo = r0 + m0w + mt * 16 + (lid >> 2);
                    store2_kv(rlo,     col, c[mt][nt][0] + bv.x, c[mt][nt][1] + bv.y);
                    store2_kv(rlo + 8, col, c[mt][nt][2] + bv.x, c[mt][nt][3] + bv.y);
                }
            }
            #pragma unroll
            for (int mt = 0; mt < 2; mt++)
                #pragma unroll
                for (int nt = 0; nt < 4; nt++)
                    #pragma unroll
                    for (int k2 = 0; k2 < 4; k2++) c[mt][nt][k2] = 0.f;
        }
    }
}

// ------- fused attention + proj: 1 CTA per window, writes final out --------
__global__ void __launch_bounds__(512, 1)
attn_kernel(const float* __restrict__ proj_b, float* __restrict__ out) {
    extern __shared__ char asmem[];
    const uint32_t sraw = smem_u32(asmem);
    const uint32_t sKV = (sraw + 1023) & ~1023u;   // 64KB: K-hi | V-hi; later O-hi
    const uint32_t sP  = sKV + 65536;              // 128KB proj weights (4 stages)
    const int tid = threadIdx.x;
    const uint8_t* src = g_KV + (size_t)blockIdx.x * 65536;

    // group0: KV 64KB; group1+2: proj weights 128KB
    #pragma unroll
    for (int t = 0; t < 8; t++) {
        uint32_t o = (uint32_t)(tid + t * 512) * 16;
        asm volatile("cp.async.cg.shared.global [%0], [%1], 16;"
                     :: "r"(sKV + o), "l"(src + o));
    }
    asm volatile("cp.async.commit_group;" ::: "memory");
    #pragma unroll
    for (int t = 0; t < 8; t++) {
        uint32_t o = (uint32_t)(tid + t * 512) * 16;
        asm volatile("cp.async.cg.shared.global [%0], [%1], 16;"
                     :: "r"(sP + o), "l"((const char*)g_pw_blk + o));
    }
    asm volatile("cp.async.commit_group;" ::: "memory");
    #pragma unroll
    for (int t = 8; t < 16; t++) {
        uint32_t o = (uint32_t)(tid + t * 512) * 16;
        asm volatile("cp.async.cg.shared.global [%0], [%1], 16;"
                     :: "r"(sP + o), "l"((const char*)g_pw_blk + o));
    }
    asm volatile("cp.async.commit_group;" ::: "memory");

    const int wid = tid >> 5, lid = tid & 31;
    const int h = wid >> 1, s = wid & 1;
    const int lrow = lid & 7, grp = lid >> 3;

    // bias -> accumulators (C-frag order), q fragments (A-frag order)
    float sa[2][8][4];
    const float4* bf = (const float4*)g_biasF;
    #pragma unroll
    for (int mt = 0; mt < 2; mt++)
        #pragma unroll
        for (int nt = 0; nt < 8; nt++) {
            float4 b = bf[((((h * 2 + s) * 2 + mt) * 8) + nt) * 32 + lid];
            sa[mt][nt][0] = b.x; sa[mt][nt][1] = b.y;
            sa[mt][nt][2] = b.z; sa[mt][nt][3] = b.w;
        }
    uint4 qh[2][2], ql[2][2];
    #pragma unroll
    for (int mt = 0; mt < 2; mt++)
        #pragma unroll
        for (int kt = 0; kt < 2; kt++) {
            int sb = (((h * 2 + s) * 2 + mt) * 2 + kt) * 2;
            qh[mt][kt] = g_qfrag[sb * 32 + lid];
            ql[mt][kt] = g_qfrag[(sb + 1) * 32 + lid];
        }

    asm volatile("cp.async.wait_group 2;" ::: "memory");
    __syncthreads();

    // ---- S = (Qh+Ql)@Kh  (bias preloaded) ----
    #pragma unroll
    for (int kt = 0; kt < 2; kt++) {
        const int dcol = h * 32 + kt * 16 + (grp & 1) * 8;
        #pragma unroll
        for (int ntp = 0; ntp < 4; ntp++) {
            const int mrow = ntp * 16 + lrow + (grp >> 1) * 8;
            uint32_t a = sKV + kv_off(mrow, dcol);
            uint32_t bh[4];
            ldsm_x4(bh, a);
            mma16816(sa[0][2*ntp],   (const uint32_t*)&qh[0][kt], bh);
            mma16816(sa[0][2*ntp+1], (const uint32_t*)&qh[0][kt], bh + 2);
            mma16816(sa[1][2*ntp],   (const uint32_t*)&qh[1][kt], bh);
            mma16816(sa[1][2*ntp+1], (const uint32_t*)&qh[1][kt], bh + 2);
            mma16816(sa[0][2*ntp],   (const uint32_t*)&ql[0][kt], bh);
            mma16816(sa[0][2*ntp+1], (const uint32_t*)&ql[0][kt], bh + 2);
            mma16816(sa[1][2*ntp],   (const uint32_t*)&ql[1][kt], bh);
            mma16816(sa[1][2*ntp+1], (const uint32_t*)&ql[1][kt], bh + 2);
        }
    }

    // ---- softmax ----
    float rinv[2][2];
    #pragma unroll
    for (int mt = 0; mt < 2; mt++)
        #pragma unroll
        for (int rh = 0; rh < 2; rh++) {
            float mx = -1e30f;
            #pragma unroll
            for (int nt = 0; nt < 8; nt++)
                mx = fmaxf(mx, fmaxf(sa[mt][nt][rh*2], sa[mt][nt][rh*2+1]));
            mx = fmaxf(mx, __shfl_xor_sync(0xffffffffu, mx, 1));
            mx = fmaxf(mx, __shfl_xor_sync(0xffffffffu, mx, 2));
            float ls = 0.f;
            #pragma unroll
            for (int nt = 0; nt < 8; nt++) {
                float p0 = __expf(sa[mt][nt][rh*2]   - mx);
                float p1 = __expf(sa[mt][nt][rh*2+1] - mx);
                sa[mt][nt][rh*2] = p0; sa[mt][nt][rh*2+1] = p1;
                ls += p0 + p1;
            }
            ls += __shfl_xor_sync(0xffffffffu, ls, 1);
            ls += __shfl_xor_sync(0xffffffffu, ls, 2);
            rinv[mt][rh] = 1.f / ls;
        }

    // ---- O = (Ph+Pl)@Vh ----
    float oa[2][4][4];
    #pragma unroll
    for (int mt = 0; mt < 2; mt++)
        #pragma unroll
        for (int nt = 0; nt < 4; nt++)
            #pragma unroll
            for (int i = 0; i < 4; i++) oa[mt][nt][i] = 0.f;

    #pragma unroll
    for (int j = 0; j < 4; j++) {
        uint32_t Ph[2][4], Pl[2][4];
        #pragma unroll
        for (int mt = 0; mt < 2; mt++) {
            Ph[mt][0] = split2h(sa[mt][2*j][0],   sa[mt][2*j][1],   Pl[mt][0]);
            Ph[mt][1] = split2h(sa[mt][2*j][2],   sa[mt][2*j][3],   Pl[mt][1]);
            Ph[mt][2] = split2h(sa[mt][2*j+1][0], sa[mt][2*j+1][1], Pl[mt][2]);
            Ph[mt][3] = split2h(sa[mt][2*j+1][2], sa[mt][2*j+1][3], Pl[mt][3]);
        }
        #pragma unroll
        for (int ep = 0; ep < 2; ep++) {
            const int mrow = j * 16 + lrow + (grp & 1) * 8;
            const int ecol = h * 32 + ep * 16 + (grp >> 1) * 8;
            uint32_t va = sKV + 32768 + kv_off(mrow, ecol);
            uint32_t vh[4];
            ldsm_x4_t(vh, va);
            #pragma unroll
            for (int mt = 0; mt < 2; mt++) {
                mma16816(oa[mt][2*ep],   Ph[mt], vh);
                mma16816(oa[mt][2*ep+1], Ph[mt], vh + 2);
                mma16816(oa[mt][2*ep],   Pl[mt], vh);
                mma16816(oa[mt][2*ep+1], Pl[mt], vh + 2);
            }
        }
    }

    // ---- stage O (scaled) into smem as fp16 hi only, 64-row SW128 layout ----
    __syncthreads();    // all K/V reads done; reuse sKV region for O
    const int q2 = (lid & 3) * 2, r4 = lid >> 2;
    char* sm = asmem + (sKV - sraw);
    #pragma unroll
    for (int mt = 0; mt < 2; mt++)
        #pragma unroll
        for (int rh = 0; rh < 2; rh++) {
            const int n = s * 32 + mt * 16 + r4 + rh * 8;
            const float sc = rinv[mt][rh];
            #pragma unroll
            for (int nt = 0; nt < 4; nt++) {
                const int col = h * 32 + nt * 8 + q2;
                *(uint32_t*)(sm + kv_off(n, col)) =
                    pack2h(oa[mt][nt][rh*2] * sc, oa[mt][nt][rh*2+1] * sc);
            }
        }
    asm volatile("cp.async.wait_group 0;" ::: "memory");
    __syncthreads();

    // ---- proj: C[64x256] = Oh @ PWh^T + proj_b (1 term) ----
    const int mw = wid >> 2, nw = wid & 3;          // warp tile 16 rows x 64 cols
    const int arow = mw * 16 + lrow + (grp & 1) * 8;
    const int kqa = (grp >> 1) * 8;
    const int kqb = (grp & 1) * 8;
    int nrow[4];
    #pragma unroll
    for (int t = 0; t < 4; t++) nrow[t] = nw * 64 + t * 16 + lrow + (grp >> 1) * 8;
    const uint32_t sPw = sP + (uint32_t)(nw >> 1) * 65536;

    float pc[8][4];
    #pragma unroll
    for (int nt = 0; nt < 8; nt++)
        #pragma unroll
        for (int i = 0; i < 4; i++) pc[nt][i] = 0.f;

    #pragma unroll 4
    for (int ks = 0; ks < 16; ks++) {
        const int k = ks * 16;
        uint32_t ah[4], bb[4][4];
        ldsm_x4(ah, sKV + kv_off(arow, k + kqa));
        #pragma unroll
        for (int t = 0; t < 4; t++) {
            uint32_t ba = sPw + (uint32_t)((k + kqb) >> 7) * 32768
                        + a_sw_off(nrow[t] & 127, (k + kqb) & 127);
            ldsm_x4(bb[t], ba);
        }
        #pragma unroll
        for (int t = 0; t < 4; t++) {
            mma16816(pc[2*t],   ah, bb[t]);
            mma16816(pc[2*t+1], ah, bb[t] + 2);
        }
    }

    // ---- epilogue: bias + store out ----
    float* obase = out + (size_t)blockIdx.x * 64 * 256;
    #pragma unroll
    for (int nt = 0; nt < 8; nt++) {
        const int col = nw * 64 + nt * 8 + q2;
        const float2 bv = *(const float2*)(proj_b + col);
        const int rlo = mw * 16 + r4;
        *(float2*)(obase + (size_t)rlo * 256 + col) =
            make_float2(pc[nt][0] + bv.x, pc[nt][1] + bv.y);
        *(float2*)(obase + (size_t)(rlo + 8) * 256 + col) =
            make_float2(pc[nt][2] + bv.x, pc[nt][3] + bv.y);
    }
}

// ---------------- launcher ----------------
extern "C" void kernel_launch(void* const* d_in, const int* in_sizes, int n_in,
                              void* d_out, int out_size) {
    const float* x      = (const float*)d_in[0];
    const float* emb    = (const float*)d_in[1];
    const float* rpb    = (const float*)d_in[2];
    const float* q_w    = (const float*)d_in[3];
    const float* q_b    = (const float*)d_in[4];
    const float* kv_w   = (const float*)d_in[5];
    const float* kv_b   = (const float*)d_in[6];
    const float* proj_w = (const float*)d_in[7];
    const float* proj_b = (const float*)d_in[8];
    float* out = (float*)d_out;
    (void)in_sizes; (void)n_in; (void)out_size;

    const int GSM = 1024 + 65536 + 98304;    // 164864
    const int ASM = 1024 + 65536 + 131072;   // 197632

    cudaFuncSetAttribute(gemm_kernel,
                         cudaFuncAttributeMaxDynamicSharedMemorySize, GSM);
    cudaFuncSetAttribute(attn_kernel,
                         cudaFuncAttributeMaxDynamicSharedMemorySize, ASM);

    setup_kernel<<<480, 512>>>(emb, rpb, q_w, q_b, kv_w, proj_w);
    setup2_kernel<<<8, 512>>>();
    gemm_kernel<<<1024, 512, GSM>>>(x, kv_b);
    attn_kernel<<<2048, 512, ASM>>>(proj_b, out);
}